// round 7
// baseline (speedup 1.0000x reference)
#include <cuda_runtime.h>
#include <math.h>
#include <cstdint>

#define SEQ 2048
#define DM 1024
#define NH 16
#define HD 64
#define NB 2
#define MROWS (NB * SEQ)   // 4096

// Scratch (__device__ globals; allocation-free rule). tf32 bit patterns.
__device__ unsigned g_qt[MROWS * DM];    // tf32(q)
__device__ unsigned g_kt[MROWS * DM];    // tf32(k)
__device__ unsigned g_vt[MROWS * DM];    // tf32(v)
__device__ unsigned g_w4[4 * DM * DM];   // tf32(Wq|Wk|Wv|Wo)  [K,N]
__device__ unsigned g_qw[MROWS * DM];    // tf32(proj Q * 0.125)
__device__ unsigned g_kw[MROWS * DM];    // tf32(proj K)
__device__ unsigned g_vw[MROWS * DM];    // tf32(proj V)
__device__ unsigned g_ctx[MROWS * DM];   // tf32(attention output)

__device__ __forceinline__ unsigned f2tf(float x) {
    unsigned r;
    asm("cvt.rna.tf32.f32 %0, %1;" : "=r"(r) : "f"(x));
    return r;
}

__device__ __forceinline__ void mma_tf32(float c[4], const unsigned a[4],
                                         const unsigned b[2]) {
    asm volatile(
        "mma.sync.aligned.m16n8k8.row.col.f32.tf32.tf32.f32 "
        "{%0,%1,%2,%3}, {%4,%5,%6,%7}, {%8,%9}, {%0,%1,%2,%3};\n"
        : "+f"(c[0]), "+f"(c[1]), "+f"(c[2]), "+f"(c[3])
        : "r"(a[0]), "r"(a[1]), "r"(a[2]), "r"(a[3]), "r"(b[0]), "r"(b[1]));
}

__device__ __forceinline__ void cp_cg16(void* dst, const void* src) {
    unsigned u = (unsigned)__cvta_generic_to_shared(dst);
    asm volatile("cp.async.cg.shared.global [%0], [%1], 16;" :: "r"(u), "l"(src));
}

extern __shared__ float sm_dyn[];

// ---------------------------------------------------------------------------
// Elementwise fp32 -> tf32 bits.
// ---------------------------------------------------------------------------
__global__ __launch_bounds__(256) void to_tf32_k(
    const float4* __restrict__ in, uint4* __restrict__ out, int n4)
{
    int i = blockIdx.x * 256 + threadIdx.x;
    if (i < n4) {
        float4 x = in[i];
        uint4 y;
        y.x = f2tf(x.x); y.y = f2tf(x.y); y.z = f2tf(x.z); y.w = f2tf(x.w);
        out[i] = y;
    }
}

// ---------------------------------------------------------------------------
// tf32 GEMM on pre-converted bits, cp.async double-buffered.
// C = (A @ B + bias) * scale; out fp32 or tf32 bits.
// 128x128 block, 256 threads, 8 warps x (64x32) m16n8k8 tiles.
// ---------------------------------------------------------------------------
#define GA_S 36
#define GB_S 136
#define GEMM_STAGE_A (128 * GA_S)
#define GEMM_STAGE_B (32 * GB_S)
#define GEMM_SMEM ((2 * (GEMM_STAGE_A + GEMM_STAGE_B)) * (int)sizeof(float))

__device__ __forceinline__ void gemm_prefetch(
    unsigned* As, unsigned* Bs, const unsigned* A, const unsigned* B,
    int N, int K, int bm, int bn, int k0, int tid)
{
    const int arow = tid >> 1, ac0 = (tid & 1) * 16;
    const unsigned* ap = A + (size_t)(bm + arow) * K + k0 + ac0;
#pragma unroll
    for (int v = 0; v < 4; v++)
        cp_cg16(&As[arow * GA_S + ac0 + v * 4], ap + v * 4);
    const int brow = tid >> 3, bc0 = (tid & 7) * 4;
    const unsigned* bp = B + (size_t)(k0 + brow) * N + bn + bc0;
#pragma unroll
    for (int v = 0; v < 4; v++)
        cp_cg16(&Bs[brow * GB_S + bc0 + v * 32], bp + v * 32);
}

__global__ __launch_bounds__(256) void gemm_tf32(
    const unsigned* __restrict__ A, const unsigned* __restrict__ B,
    const float* __restrict__ bias, float* __restrict__ C,
    int M, int N, int K, float scale, int conv)
{
    unsigned* As0 = (unsigned*)sm_dyn;
    unsigned* Bs0 = As0 + 2 * GEMM_STAGE_A;

    const int tid  = threadIdx.x;
    const int lane = tid & 31;
    const int warp = tid >> 5;
    const int g = lane >> 2, t = lane & 3;
    const int wm = (warp >> 2) * 64;
    const int wn = (warp & 3) * 32;
    const int bm = blockIdx.y * 128;
    const int bn = blockIdx.x * 128;

    float acc[4][4][4];
#pragma unroll
    for (int mi = 0; mi < 4; mi++)
#pragma unroll
        for (int ni = 0; ni < 4; ni++)
#pragma unroll
            for (int e = 0; e < 4; e++) acc[mi][ni][e] = 0.0f;

    gemm_prefetch(As0, Bs0, A, B, N, K, bm, bn, 0, tid);
    asm volatile("cp.async.commit_group;" ::: "memory");

    const int NKI = K / 32;
    for (int i = 0; i < NKI; i++) {
        const int st = i & 1;
        asm volatile("cp.async.wait_group 0;" ::: "memory");
        __syncthreads();
        if (i + 1 < NKI) {
            gemm_prefetch(As0 + (st ^ 1) * GEMM_STAGE_A,
                          Bs0 + (st ^ 1) * GEMM_STAGE_B,
                          A, B, N, K, bm, bn, (i + 1) * 32, tid);
            asm volatile("cp.async.commit_group;" ::: "memory");
        }
        const unsigned* As = As0 + st * GEMM_STAGE_A;
        const unsigned* Bs = Bs0 + st * GEMM_STAGE_B;

#pragma unroll
        for (int kk = 0; kk < 32; kk += 8) {
            unsigned af[4][4], bf[4][2];
#pragma unroll
            for (int mi = 0; mi < 4; mi++) {
                int r = wm + mi * 16;
                af[mi][0] = As[(r + g)     * GA_S + kk + t];
                af[mi][1] = As[(r + g + 8) * GA_S + kk + t];
                af[mi][2] = As[(r + g)     * GA_S + kk + t + 4];
                af[mi][3] = As[(r + g + 8) * GA_S + kk + t + 4];
            }
#pragma unroll
            for (int ni = 0; ni < 4; ni++) {
                int c = wn + ni * 8;
                bf[ni][0] = Bs[(kk + t)     * GB_S + c + g];
                bf[ni][1] = Bs[(kk + t + 4) * GB_S + c + g];
            }
#pragma unroll
            for (int mi = 0; mi < 4; mi++)
#pragma unroll
                for (int ni = 0; ni < 4; ni++)
                    mma_tf32(acc[mi][ni], af[mi], bf[ni]);
        }
    }

#pragma unroll
    for (int mi = 0; mi < 4; mi++) {
        int r0 = bm + wm + mi * 16 + g;
#pragma unroll
        for (int ni = 0; ni < 4; ni++) {
            int cb = bn + wn + ni * 8 + 2 * t;
            float b0 = bias[cb], b1 = bias[cb + 1];
            float x00 = (acc[mi][ni][0] + b0) * scale;
            float x01 = (acc[mi][ni][1] + b1) * scale;
            float x10 = (acc[mi][ni][2] + b0) * scale;
            float x11 = (acc[mi][ni][3] + b1) * scale;
            float2 v0, v1;
            if (conv) {
                v0 = make_float2(__uint_as_float(f2tf(x00)),
                                 __uint_as_float(f2tf(x01)));
                v1 = make_float2(__uint_as_float(f2tf(x10)),
                                 __uint_as_float(f2tf(x11)));
            } else {
                v0 = make_float2(x00, x01);
                v1 = make_float2(x10, x11);
            }
            *(float2*)&C[(size_t)r0 * N + cb]       = v0;
            *(float2*)&C[(size_t)(r0 + 8) * N + cb] = v1;
        }
    }
}

// ---------------------------------------------------------------------------
// Flash-attention. 256 threads / 8 warps, QROWS=256 (32 rows per warp, mi=2
// B-frag sharing). 3-stage cp.async K/V pipeline (wait_group 1 keeps the
// next tile always in flight). Q tile staged once in smem (stride 68,
// (4g+t) mod 32 conflict-free). K/V natural [key][d] stride 76:
// (12g+t) and (12t+g) mod 32 both conflict-free.
// ---------------------------------------------------------------------------
#define QROWS 256
#define KTILE 64
#define NT (SEQ / KTILE)
#define NSTG 3
#define AT_S 76
#define QS_S 68
#define STAGE_FLOATS (KTILE * AT_S * 2 + 64)     // Ks + Vs + mask = 9792
#define QS_FLOATS (QROWS * QS_S)                 // 17408
#define ATTN_SMEM ((NSTG * STAGE_FLOATS + QS_FLOATS) * (int)sizeof(float))

__device__ __forceinline__ void attn_prefetch(
    float* stage, const unsigned* kb, const unsigned* vb, const int* mb, int tid)
{
    float* Ks = stage;
    float* Vs = stage + KTILE * AT_S;
    float* Mk = Vs + KTILE * AT_S;
#pragma unroll
    for (int j = 0; j < 4; j++) {
        int c = tid + j * 256;
        int r = c >> 4, col = (c & 15) << 2;
        cp_cg16(Ks + r * AT_S + col, kb + (size_t)r * DM + col);
        cp_cg16(Vs + r * AT_S + col, vb + (size_t)r * DM + col);
    }
    if (tid < 16) cp_cg16(Mk + tid * 4, mb + tid * 4);
}

__global__ __launch_bounds__(256) void attn_mma(
    const unsigned* __restrict__ qw, const unsigned* __restrict__ kw,
    const unsigned* __restrict__ vw, const int* __restrict__ vmask,
    unsigned* __restrict__ ctx)
{
    const int tid  = threadIdx.x;
    const int lane = tid & 31;
    const int warp = tid >> 5;
    const int g = lane >> 2, t = lane & 3;
    const int qrow0 = warp * 32;
    const int qt = blockIdx.x, h = blockIdx.y, b = blockIdx.z;

    float* Qs = sm_dyn + NSTG * STAGE_FLOATS;
    const unsigned* Qu = (const unsigned*)Qs;

    // Stage Q tile (256 rows x 64 dims of tf32 bits, pre-scaled 1/8)
    const unsigned* qb = qw + ((size_t)b * SEQ + qt * QROWS) * DM + h * HD;
#pragma unroll
    for (int j = 0; j < 16; j++) {
        int c = tid + j * 256;
        int r = c >> 4, col = (c & 15) << 2;
        cp_cg16(Qs + r * QS_S + col, qb + (size_t)r * DM + col);
    }

    const unsigned* kbase = kw + ((size_t)b * SEQ) * DM + h * HD;
    const unsigned* vbase = vw + ((size_t)b * SEQ) * DM + h * HD;
    const int*      mbase = vmask + b * SEQ;

    // Prologue: tiles 0 (with Q) and 1 in flight.
    attn_prefetch(sm_dyn, kbase, vbase, mbase, tid);
    asm volatile("cp.async.commit_group;" ::: "memory");
    attn_prefetch(sm_dyn + STAGE_FLOATS, kbase + (size_t)KTILE * DM,
                  vbase + (size_t)KTILE * DM, mbase + KTILE, tid);
    asm volatile("cp.async.commit_group;" ::: "memory");

    float m[2][2], l[2][2];
#pragma unroll
    for (int mi = 0; mi < 2; mi++) {
        m[mi][0] = -1e30f; m[mi][1] = -1e30f;
        l[mi][0] = 0.0f;   l[mi][1] = 0.0f;
    }
    float o[2][8][4];
#pragma unroll
    for (int mi = 0; mi < 2; mi++)
#pragma unroll
        for (int nf = 0; nf < 8; nf++)
#pragma unroll
            for (int e = 0; e < 4; e++) o[mi][nf][e] = 0.0f;

    const int srcA = (lane & ~3) | (t >> 1);
    const int srcB = srcA + 2;
    const bool odd = (t & 1);

    int st = 0;
    for (int kt = 0; kt < NT; kt++) {
        asm volatile("cp.async.wait_group 1;" ::: "memory");
        __syncthreads();   // tile kt resident; all warps done with stage being refilled
        if (kt + 2 < NT) {
            int j = st - 1; if (j < 0) j += NSTG;   // stage consumed 2 iters ago
            attn_prefetch(sm_dyn + j * STAGE_FLOATS,
                          kbase + (size_t)(kt + 2) * KTILE * DM,
                          vbase + (size_t)(kt + 2) * KTILE * DM,
                          mbase + (kt + 2) * KTILE, tid);
            asm volatile("cp.async.commit_group;" ::: "memory");
        } else {
            asm volatile("cp.async.commit_group;" ::: "memory");  // keep group count in step
        }
        const unsigned* Ks = (const unsigned*)(sm_dyn + st * STAGE_FLOATS);
        const unsigned* Vs = Ks + KTILE * AT_S;
        const int*      Mk = (const int*)(Vs + KTILE * AT_S);
        if (++st == NSTG) st = 0;

        // ---- S = Qs . K^T : B-frag shared across mi ----
        float s[2][8][4];
#pragma unroll
        for (int mi = 0; mi < 2; mi++)
#pragma unroll
            for (int nf = 0; nf < 8; nf++)
#pragma unroll
                for (int e = 0; e < 4; e++) s[mi][nf][e] = 0.0f;

#pragma unroll
        for (int kf = 0; kf < 8; kf++) {
            unsigned a0[4], a1[4];
            a0[0] = Qu[(qrow0 + g)      * QS_S + kf * 8 + t];
            a0[1] = Qu[(qrow0 + g + 8)  * QS_S + kf * 8 + t];
            a0[2] = Qu[(qrow0 + g)      * QS_S + kf * 8 + t + 4];
            a0[3] = Qu[(qrow0 + g + 8)  * QS_S + kf * 8 + t + 4];
            a1[0] = Qu[(qrow0 + g + 16) * QS_S + kf * 8 + t];
            a1[1] = Qu[(qrow0 + g + 24) * QS_S + kf * 8 + t];
            a1[2] = Qu[(qrow0 + g + 16) * QS_S + kf * 8 + t + 4];
            a1[3] = Qu[(qrow0 + g + 24) * QS_S + kf * 8 + t + 4];
#pragma unroll
            for (int nf = 0; nf < 8; nf++) {
                unsigned bfr[2];
                bfr[0] = Ks[(nf * 8 + g) * AT_S + kf * 8 + t];
                bfr[1] = Ks[(nf * 8 + g) * AT_S + kf * 8 + t + 4];
                mma_tf32(s[0][nf], a0, bfr);
                mma_tf32(s[1][nf], a1, bfr);
            }
        }

        // ---- mask + online softmax (per mi independent) ----
#pragma unroll
        for (int mi = 0; mi < 2; mi++) {
            float mx0 = -1e30f, mx1 = -1e30f;
#pragma unroll
            for (int nf = 0; nf < 8; nf++) {
                float pen0 = Mk[nf * 8 + 2 * t]     ? 0.0f : 1e12f;
                float pen1 = Mk[nf * 8 + 2 * t + 1] ? 0.0f : 1e12f;
                s[mi][nf][0] -= pen0; s[mi][nf][1] -= pen1;
                s[mi][nf][2] -= pen0; s[mi][nf][3] -= pen1;
                mx0 = fmaxf(mx0, fmaxf(s[mi][nf][0], s[mi][nf][1]));
                mx1 = fmaxf(mx1, fmaxf(s[mi][nf][2], s[mi][nf][3]));
            }
            mx0 = fmaxf(mx0, __shfl_xor_sync(0xffffffffu, mx0, 1));
            mx0 = fmaxf(mx0, __shfl_xor_sync(0xffffffffu, mx0, 2));
            mx1 = fmaxf(mx1, __shfl_xor_sync(0xffffffffu, mx1, 1));
            mx1 = fmaxf(mx1, __shfl_xor_sync(0xffffffffu, mx1, 2));
            float mn0 = fmaxf(m[mi][0], mx0), mn1 = fmaxf(m[mi][1], mx1);
            float al0 = __expf(m[mi][0] - mn0), al1 = __expf(m[mi][1] - mn1);
            m[mi][0] = mn0; m[mi][1] = mn1;
            float sum0 = 0.0f, sum1 = 0.0f;
#pragma unroll
            for (int nf = 0; nf < 8; nf++) {
                s[mi][nf][0] = __expf(s[mi][nf][0] - mn0);
                s[mi][nf][1] = __expf(s[mi][nf][1] - mn0);
                s[mi][nf][2] = __expf(s[mi][nf][2] - mn1);
                s[mi][nf][3] = __expf(s[mi][nf][3] - mn1);
                sum0 += s[mi][nf][0] + s[mi][nf][1];
                sum1 += s[mi][nf][2] + s[mi][nf][3];
            }
            sum0 += __shfl_xor_sync(0xffffffffu, sum0, 1);
            sum0 += __shfl_xor_sync(0xffffffffu, sum0, 2);
            sum1 += __shfl_xor_sync(0xffffffffu, sum1, 1);
            sum1 += __shfl_xor_sync(0xffffffffu, sum1, 2);
            l[mi][0] = l[mi][0] * al0 + sum0;
            l[mi][1] = l[mi][1] * al1 + sum1;
#pragma unroll
            for (int nf = 0; nf < 8; nf++) {
                o[mi][nf][0] *= al0; o[mi][nf][1] *= al0;
                o[mi][nf][2] *= al1; o[mi][nf][3] *= al1;
            }
        }

        // ---- O += P . V : V B-frag shared across mi ----
#pragma unroll
        for (int kf = 0; kf < 8; kf++) {
            unsigned af[2][4];
#pragma unroll
            for (int mi = 0; mi < 2; mi++) {
                float x0 = __shfl_sync(0xffffffffu, s[mi][kf][0], srcA);
                float x1 = __shfl_sync(0xffffffffu, s[mi][kf][1], srcA);
                float x2 = __shfl_sync(0xffffffffu, s[mi][kf][2], srcA);
                float x3 = __shfl_sync(0xffffffffu, s[mi][kf][3], srcA);
                float y0 = __shfl_sync(0xffffffffu, s[mi][kf][0], srcB);
                float y1 = __shfl_sync(0xffffffffu, s[mi][kf][1], srcB);
                float y2 = __shfl_sync(0xffffffffu, s[mi][kf][2], srcB);
                float y3 = __shfl_sync(0xffffffffu, s[mi][kf][3], srcB);
                af[mi][0] = f2tf(odd ? x1 : x0);
                af[mi][1] = f2tf(odd ? x3 : x2);
                af[mi][2] = f2tf(odd ? y1 : y0);
                af[mi][3] = f2tf(odd ? y3 : y2);
            }
#pragma unroll
            for (int nf = 0; nf < 8; nf++) {
                unsigned bfr[2];
                bfr[0] = Vs[(kf * 8 + t)     * AT_S + nf * 8 + g];
                bfr[1] = Vs[(kf * 8 + t + 4) * AT_S + nf * 8 + g];
                mma_tf32(o[0][nf], af[0], bfr);
                mma_tf32(o[1][nf], af[1], bfr);
            }
        }
    }

    // ---- normalize; write ctx as tf32 bits ----
    unsigned* obase = ctx + ((size_t)b * SEQ + qt * QROWS + qrow0) * DM + h * HD;
#pragma unroll
    for (int mi = 0; mi < 2; mi++) {
        float inv0 = 1.0f / l[mi][0], inv1 = 1.0f / l[mi][1];
        unsigned* ob = obase + (size_t)(mi * 16) * DM;
#pragma unroll
        for (int nf = 0; nf < 8; nf++) {
            int col = nf * 8 + 2 * t;
            uint2 v0, v1;
            v0.x = f2tf(o[mi][nf][0] * inv0);
            v0.y = f2tf(o[mi][nf][1] * inv0);
            v1.x = f2tf(o[mi][nf][2] * inv1);
            v1.y = f2tf(o[mi][nf][3] * inv1);
            *(uint2*)&ob[(size_t)g * DM + col]       = v0;
            *(uint2*)&ob[(size_t)(g + 8) * DM + col] = v1;
        }
    }
}

// ---------------------------------------------------------------------------
extern "C" void kernel_launch(void* const* d_in, const int* in_sizes, int n_in,
                              void* d_out, int out_size)
{
    const float* q    = (const float*)d_in[0];
    const float* k    = (const float*)d_in[1];
    const float* v    = (const float*)d_in[2];
    const int*   mask = (const int*)  d_in[3];
    const float* Wq   = (const float*)d_in[4];
    const float* bq   = (const float*)d_in[5];
    const float* Wk   = (const float*)d_in[6];
    const float* bk   = (const float*)d_in[7];
    const float* Wv   = (const float*)d_in[8];
    const float* bv   = (const float*)d_in[9];
    const float* Wo   = (const float*)d_in[10];
    const float* bo   = (const float*)d_in[11];
    float* out = (float*)d_out;

    void *pqt, *pkt, *pvt, *pw4, *pqw, *pkw, *pvw, *pctx;
    cudaGetSymbolAddress(&pqt, g_qt);
    cudaGetSymbolAddress(&pkt, g_kt);
    cudaGetSymbolAddress(&pvt, g_vt);
    cudaGetSymbolAddress(&pw4, g_w4);
    cudaGetSymbolAddress(&pqw, g_qw);
    cudaGetSymbolAddress(&pkw, g_kw);
    cudaGetSymbolAddress(&pvw, g_vw);
    cudaGetSymbolAddress(&pctx, g_ctx);

    unsigned* qt  = (unsigned*)pqt;
    unsigned* kt  = (unsigned*)pkt;
    unsigned* vt  = (unsigned*)pvt;
    unsigned* w4  = (unsigned*)pw4;
    unsigned* qwp = (unsigned*)pqw;
    unsigned* kwp = (unsigned*)pkw;
    unsigned* vwp = (unsigned*)pvw;
    unsigned* ctx = (unsigned*)pctx;

    cudaFuncSetAttribute(gemm_tf32,
                         cudaFuncAttributeMaxDynamicSharedMemorySize, GEMM_SMEM);
    cudaFuncSetAttribute(attn_mma,
                         cudaFuncAttributeMaxDynamicSharedMemorySize, ATTN_SMEM);

    // 1) one-shot tf32 conversions
    const int nBig = MROWS * DM / 4, nW = DM * DM / 4;
    to_tf32_k<<<nBig / 256, 256>>>((const float4*)q, (uint4*)qt, nBig);
    to_tf32_k<<<nBig / 256, 256>>>((const float4*)k, (uint4*)kt, nBig);
    to_tf32_k<<<nBig / 256, 256>>>((const float4*)v, (uint4*)vt, nBig);
    to_tf32_k<<<nW / 256, 256>>>((const float4*)Wq, (uint4*)(w4 + 0 * DM * DM), nW);
    to_tf32_k<<<nW / 256, 256>>>((const float4*)Wk, (uint4*)(w4 + 1 * DM * DM), nW);
    to_tf32_k<<<nW / 256, 256>>>((const float4*)Wv, (uint4*)(w4 + 2 * DM * DM), nW);
    to_tf32_k<<<nW / 256, 256>>>((const float4*)Wo, (uint4*)(w4 + 3 * DM * DM), nW);

    dim3 ggrid(DM / 128, MROWS / 128);   // (8, 32)

    // 2) projections -> tf32 bits (Q pre-scaled by 1/sqrt(64))
    gemm_tf32<<<ggrid, 256, GEMM_SMEM>>>(qt, w4 + 0 * DM * DM, bq,
                                         (float*)qwp, MROWS, DM, DM, 0.125f, 1);
    gemm_tf32<<<ggrid, 256, GEMM_SMEM>>>(kt, w4 + 1 * DM * DM, bk,
                                         (float*)kwp, MROWS, DM, DM, 1.0f, 1);
    gemm_tf32<<<ggrid, 256, GEMM_SMEM>>>(vt, w4 + 2 * DM * DM, bv,
                                         (float*)vwp, MROWS, DM, DM, 1.0f, 1);

    // 3) fused attention -> ctx (tf32 bits)
    attn_mma<<<dim3(SEQ / QROWS, NH, NB), 256, ATTN_SMEM>>>(
        qwp, kwp, vwp, mask, ctx);

    // 4) output projection (fp32 out)
    gemm_tf32<<<ggrid, 256, GEMM_SMEM>>>(ctx, w4 + 3 * DM * DM, bo,
                                         out, MROWS, DM, DM, 1.0f, 0);
}

// round 8
// speedup vs baseline: 1.8155x; 1.8155x over previous
#include <cuda_runtime.h>
#include <cuda_fp16.h>
#include <math.h>
#include <cstdint>

#define SEQ 2048
#define DM 1024
#define NH 16
#define HD 64
#define NB 2
#define MROWS (NB * SEQ)   // 4096

// Scratch (__device__ globals; allocation-free rule). fp16 payloads.
__device__ __half g_qh[MROWS * DM];     // fp16(q)
__device__ __half g_kh[MROWS * DM];     // fp16(k)
__device__ __half g_vh[MROWS * DM];     // fp16(v)
__device__ __half g_wT[4 * DM * DM];    // fp16(Wq^T|Wk^T|Wv^T|Wo^T) [N][K]
__device__ __half g_qw[MROWS * DM];     // fp16(proj Q * 0.125)  [token][c]
__device__ __half g_kw[MROWS * DM];     // fp16(proj K)          [token][c]
__device__ __half g_vw[MROWS * DM];     // fp16(proj V)          [token][c]
__device__ __half g_vwT[NB * DM * SEQ]; // fp16(proj V)^T  [b][c][token]
__device__ __half g_ctx[MROWS * DM];    // fp16(attn out)        [token][c]

__device__ __forceinline__ void mma_f16(float c[4], const unsigned a[4],
                                        const unsigned b[2]) {
    asm volatile(
        "mma.sync.aligned.m16n8k16.row.col.f32.f16.f16.f32 "
        "{%0,%1,%2,%3}, {%4,%5,%6,%7}, {%8,%9}, {%0,%1,%2,%3};\n"
        : "+f"(c[0]), "+f"(c[1]), "+f"(c[2]), "+f"(c[3])
        : "r"(a[0]), "r"(a[1]), "r"(a[2]), "r"(a[3]), "r"(b[0]), "r"(b[1]));
}

__device__ __forceinline__ unsigned packh2(float lo, float hi) {
    __half2 h = __floats2half2_rn(lo, hi);   // lo -> .x (low 16 bits)
    return *(unsigned*)&h;
}

__device__ __forceinline__ void cp_cg16(void* dst, const void* src) {
    unsigned u = (unsigned)__cvta_generic_to_shared(dst);
    asm volatile("cp.async.cg.shared.global [%0], [%1], 16;" :: "r"(u), "l"(src));
}

extern __shared__ float sm_dyn[];

// ---------------------------------------------------------------------------
// fp32 -> fp16 elementwise.
// ---------------------------------------------------------------------------
__global__ __launch_bounds__(256) void to_f16_k(
    const float4* __restrict__ in, __half2* __restrict__ out, int n4)
{
    int i = blockIdx.x * 256 + threadIdx.x;
    if (i < n4) {
        float4 x = in[i];
        out[2 * i]     = __floats2half2_rn(x.x, x.y);
        out[2 * i + 1] = __floats2half2_rn(x.z, x.w);
    }
}

// Transpose + fp16: out[n*DM + k] = h(in[k*DM + n]).
__global__ __launch_bounds__(256) void transp_w(
    const float* __restrict__ in, __half* __restrict__ out)
{
    __shared__ float t[32][33];
    int tx = threadIdx.x, ty = threadIdx.y;           // 32 x 8
    int bx = blockIdx.x * 32, by = blockIdx.y * 32;
#pragma unroll
    for (int j = 0; j < 4; j++)
        t[ty + j * 8][tx] = in[(size_t)(by + ty + j * 8) * DM + bx + tx];
    __syncthreads();
#pragma unroll
    for (int j = 0; j < 4; j++)
        out[(size_t)(bx + ty + j * 8) * DM + by + tx] =
            __float2half_rn(t[tx][ty + j * 8]);
}

// Per-batch fp16 transpose: out[b][c][tok] = in[b][tok][c].  64x64 tiles.
__global__ __launch_bounds__(256) void transp_vw(
    const __half* __restrict__ in, __half* __restrict__ out)
{
    __shared__ __half t[64][72];
    const int tid = threadIdx.x;
    const int tok0 = blockIdx.x * 64, c0 = blockIdx.y * 64, b = blockIdx.z;
    for (int i = tid; i < 64 * 64; i += 256) {
        int r = i >> 6, c = i & 63;
        t[r][c] = in[((size_t)b * SEQ + tok0 + r) * DM + c0 + c];
    }
    __syncthreads();
    for (int i = tid; i < 64 * 64; i += 256) {
        int r = i >> 6, c = i & 63;
        out[((size_t)b * DM + c0 + r) * SEQ + tok0 + c] = t[c][r];
    }
}

// ---------------------------------------------------------------------------
// fp16 GEMM: C = (A @ W + bias) * scale.  A [M,K] fp16; WT [N,K] fp16.
// 128x128 block, 256 threads, 8 warps x (64x32), m16n8k16, k-chunk 64 halves.
// Smem pitch 36 words (72 halves): frag addr 4g+t mod 32 -> conflict-free.
// ---------------------------------------------------------------------------
#define GW 36
#define GEMM_STAGE (128 * GW)          // words per operand stage
#define GEMM_SMEM ((4 * GEMM_STAGE) * (int)sizeof(float))   // 2 stages x (A+B)

__device__ __forceinline__ void gemm_prefetch(
    unsigned* As, unsigned* Bs, const __half* A, const __half* WT,
    int K, int bm, int bn, int k0, int tid)
{
#pragma unroll
    for (int j = 0; j < 4; j++) {
        int idx = tid + j * 256;          // 0..1023
        int row = idx >> 3;               // 0..127
        int c16 = idx & 7;                // 0..7 (16B chunks)
        cp_cg16(&As[row * GW + c16 * 4],
                A + (size_t)(bm + row) * K + k0 + c16 * 8);
        cp_cg16(&Bs[row * GW + c16 * 4],
                WT + (size_t)(bn + row) * K + k0 + c16 * 8);
    }
}

__global__ __launch_bounds__(256) void gemm_f16(
    const __half* __restrict__ A, const __half* __restrict__ WT,
    const float* __restrict__ bias, float* __restrict__ C,
    int M, int N, int K, float scale, int conv)
{
    unsigned* As0 = (unsigned*)sm_dyn;
    unsigned* Bs0 = As0 + 2 * GEMM_STAGE;

    const int tid  = threadIdx.x;
    const int lane = tid & 31;
    const int warp = tid >> 5;
    const int g = lane >> 2, t = lane & 3;
    const int wm = (warp >> 2) * 64;
    const int wn = (warp & 3) * 32;
    const int bm = blockIdx.y * 128;
    const int bn = blockIdx.x * 128;

    float acc[4][4][4];
#pragma unroll
    for (int mi = 0; mi < 4; mi++)
#pragma unroll
        for (int ni = 0; ni < 4; ni++)
#pragma unroll
            for (int e = 0; e < 4; e++) acc[mi][ni][e] = 0.0f;

    gemm_prefetch(As0, Bs0, A, WT, K, bm, bn, 0, tid);
    asm volatile("cp.async.commit_group;" ::: "memory");

    const int NKI = K / 64;   // 16
    for (int i = 0; i < NKI; i++) {
        const int st = i & 1;
        asm volatile("cp.async.wait_group 0;" ::: "memory");
        __syncthreads();
        if (i + 1 < NKI) {
            gemm_prefetch(As0 + (st ^ 1) * GEMM_STAGE,
                          Bs0 + (st ^ 1) * GEMM_STAGE,
                          A, WT, K, bm, bn, (i + 1) * 64, tid);
            asm volatile("cp.async.commit_group;" ::: "memory");
        }
        const unsigned* As = As0 + st * GEMM_STAGE;
        const unsigned* Bs = Bs0 + st * GEMM_STAGE;

#pragma unroll
        for (int kf = 0; kf < 4; kf++) {
            unsigned af[4][4], bf[4][2];
#pragma unroll
            for (int mi = 0; mi < 4; mi++) {
                int r = wm + mi * 16;
                af[mi][0] = As[(r + g)     * GW + kf * 8 + t];
                af[mi][1] = As[(r + g + 8) * GW + kf * 8 + t];
                af[mi][2] = As[(r + g)     * GW + kf * 8 + t + 4];
                af[mi][3] = As[(r + g + 8) * GW + kf * 8 + t + 4];
            }
#pragma unroll
            for (int ni = 0; ni < 4; ni++) {
                int c = wn + ni * 8;
                bf[ni][0] = Bs[(c + g) * GW + kf * 8 + t];
                bf[ni][1] = Bs[(c + g) * GW + kf * 8 + t + 4];
            }
#pragma unroll
            for (int mi = 0; mi < 4; mi++)
#pragma unroll
                for (int ni = 0; ni < 4; ni++)
                    mma_f16(acc[mi][ni], af[mi], bf[ni]);
        }
    }

#pragma unroll
    for (int mi = 0; mi < 4; mi++) {
        int r0 = bm + wm + mi * 16 + g;
#pragma unroll
        for (int ni = 0; ni < 4; ni++) {
            int cb = bn + wn + ni * 8 + 2 * t;
            float b0 = bias[cb], b1 = bias[cb + 1];
            float x00 = (acc[mi][ni][0] + b0) * scale;
            float x01 = (acc[mi][ni][1] + b1) * scale;
            float x10 = (acc[mi][ni][2] + b0) * scale;
            float x11 = (acc[mi][ni][3] + b1) * scale;
            if (conv) {
                __half* Ch = (__half*)C;
                *(__half2*)&Ch[(size_t)r0 * N + cb] = __floats2half2_rn(x00, x01);
                *(__half2*)&Ch[(size_t)(r0 + 8) * N + cb] = __floats2half2_rn(x10, x11);
            } else {
                *(float2*)&C[(size_t)r0 * N + cb]       = make_float2(x00, x01);
                *(float2*)&C[(size_t)(r0 + 8) * N + cb] = make_float2(x10, x11);
            }
        }
    }
}

// ---------------------------------------------------------------------------
// Flash-attention, fp16 mma. 256 threads / 8 warps, QROWS=256 (32 rows/warp).
// K tile [key][d] halves; V tile TRANSPOSED [d][key] halves (from g_vwT) so
// both S and PV B-frag k-pairs are adjacent halves. Pitch 36 words ->
// conflict-free (4g+t). P C-layout -> A-layout is the IDENTITY in fp16
// (half2 packs of own c-regs) — no shuffles. 3-stage cp.async pipeline.
// ---------------------------------------------------------------------------
#define QROWS 256
#define KTILE 64
#define NT (SEQ / KTILE)
#define NSTG 3
#define AT_W 36
#define STAGE_W (KTILE * AT_W * 2 + 64)   // Ks + VTs + mask = 4672 words
#define QS_W (QROWS * AT_W)               // 9216 words
#define ATTN_SMEM ((NSTG * STAGE_W + QS_W) * (int)sizeof(float))  // 92928

__device__ __forceinline__ void attn_prefetch(
    unsigned* stage, const __half* kb, const __half* vtb, const int* mb,
    int kt, int tid)
{
    unsigned* Ks  = stage;
    unsigned* VTs = stage + KTILE * AT_W;
    unsigned* Mk  = VTs + KTILE * AT_W;
#pragma unroll
    for (int j = 0; j < 2; j++) {
        int idx = tid + j * 256;          // 0..511
        int row = idx >> 3;               // 0..63
        int c16 = idx & 7;
        cp_cg16(&Ks[row * AT_W + c16 * 4],
                kb + (size_t)(kt * KTILE + row) * DM + c16 * 8);
        cp_cg16(&VTs[row * AT_W + c16 * 4],
                vtb + (size_t)row * SEQ + kt * KTILE + c16 * 8);
    }
    if (tid < 16) cp_cg16(&Mk[tid * 4], mb + kt * KTILE + tid * 4);
}

__global__ __launch_bounds__(256) void attn_mma(
    const __half* __restrict__ qw, const __half* __restrict__ kw,
    const __half* __restrict__ vwT, const int* __restrict__ vmask,
    __half* __restrict__ ctx)
{
    const int tid  = threadIdx.x;
    const int lane = tid & 31;
    const int warp = tid >> 5;
    const int g = lane >> 2, t = lane & 3;
    const int qrow0 = warp * 32;
    const int qt = blockIdx.x, h = blockIdx.y, b = blockIdx.z;

    unsigned* Qs = (unsigned*)(sm_dyn + NSTG * STAGE_W);

    // Stage Q tile (256 rows x 64 halves, pre-scaled 1/8)
    const __half* qb = qw + ((size_t)b * SEQ + qt * QROWS) * DM + h * HD;
#pragma unroll
    for (int j = 0; j < 8; j++) {
        int idx = tid + j * 256;          // 0..2047
        int row = idx >> 3, c16 = idx & 7;
        cp_cg16(&Qs[row * AT_W + c16 * 4], qb + (size_t)row * DM + c16 * 8);
    }

    const __half* kbase  = kw + ((size_t)b * SEQ) * DM + h * HD;
    const __half* vtbase = vwT + ((size_t)b * DM + h * HD) * SEQ;
    const int*    mbase  = vmask + b * SEQ;

    attn_prefetch((unsigned*)sm_dyn, kbase, vtbase, mbase, 0, tid);
    asm volatile("cp.async.commit_group;" ::: "memory");
    attn_prefetch((unsigned*)sm_dyn + STAGE_W, kbase, vtbase, mbase, 1, tid);
    asm volatile("cp.async.commit_group;" ::: "memory");

    float m[2][2], l[2][2];
#pragma unroll
    for (int mi = 0; mi < 2; mi++) {
        m[mi][0] = -1e30f; m[mi][1] = -1e30f;
        l[mi][0] = 0.0f;   l[mi][1] = 0.0f;
    }
    float o[2][8][4];
#pragma unroll
    for (int mi = 0; mi < 2; mi++)
#pragma unroll
        for (int nf = 0; nf < 8; nf++)
#pragma unroll
            for (int e = 0; e < 4; e++) o[mi][nf][e] = 0.0f;

    int st = 0;
    for (int kt = 0; kt < NT; kt++) {
        asm volatile("cp.async.wait_group 1;" ::: "memory");
        __syncthreads();
        if (kt + 2 < NT) {
            int j = st - 1; if (j < 0) j += NSTG;
            attn_prefetch((unsigned*)sm_dyn + j * STAGE_W,
                          kbase, vtbase, mbase, kt + 2, tid);
            asm volatile("cp.async.commit_group;" ::: "memory");
        } else {
            asm volatile("cp.async.commit_group;" ::: "memory");
        }
        const unsigned* Ks  = (const unsigned*)sm_dyn + st * STAGE_W;
        const unsigned* VTs = Ks + KTILE * AT_W;
        const int*      Mk  = (const int*)(VTs + KTILE * AT_W);
        if (++st == NSTG) st = 0;

        // ---- S = Q . K^T ----
        float s[2][8][4];
#pragma unroll
        for (int mi = 0; mi < 2; mi++)
#pragma unroll
            for (int nf = 0; nf < 8; nf++)
#pragma unroll
                for (int e = 0; e < 4; e++) s[mi][nf][e] = 0.0f;

#pragma unroll
        for (int kf = 0; kf < 4; kf++) {
            unsigned a0[4], a1[4];
            a0[0] = Qs[(qrow0 + g)      * AT_W + kf * 8 + t];
            a0[1] = Qs[(qrow0 + g + 8)  * AT_W + kf * 8 + t];
            a0[2] = Qs[(qrow0 + g)      * AT_W + kf * 8 + t + 4];
            a0[3] = Qs[(qrow0 + g + 8)  * AT_W + kf * 8 + t + 4];
            a1[0] = Qs[(qrow0 + g + 16) * AT_W + kf * 8 + t];
            a1[1] = Qs[(qrow0 + g + 24) * AT_W + kf * 8 + t];
            a1[2] = Qs[(qrow0 + g + 16) * AT_W + kf * 8 + t + 4];
            a1[3] = Qs[(qrow0 + g + 24) * AT_W + kf * 8 + t + 4];
#pragma unroll
            for (int nf = 0; nf < 8; nf++) {
                unsigned bfr[2];
                bfr[0] = Ks[(nf * 8 + g) * AT_W + kf * 8 + t];
                bfr[1] = Ks[(nf * 8 + g) * AT_W + kf * 8 + t + 4];
                mma_f16(s[0][nf], a0, bfr);
                mma_f16(s[1][nf], a1, bfr);
            }
        }

        // ---- mask + online softmax ----
#pragma unroll
        for (int mi = 0; mi < 2; mi++) {
            float mx0 = -1e30f, mx1 = -1e30f;
#pragma unroll
            for (int nf = 0; nf < 8; nf++) {
                float pen0 = Mk[nf * 8 + 2 * t]     ? 0.0f : 1e12f;
                float pen1 = Mk[nf * 8 + 2 * t + 1] ? 0.0f : 1e12f;
                s[mi][nf][0] -= pen0; s[mi][nf][1] -= pen1;
                s[mi][nf][2] -= pen0; s[mi][nf][3] -= pen1;
                mx0 = fmaxf(mx0, fmaxf(s[mi][nf][0], s[mi][nf][1]));
                mx1 = fmaxf(mx1, fmaxf(s[mi][nf][2], s[mi][nf][3]));
            }
            mx0 = fmaxf(mx0, __shfl_xor_sync(0xffffffffu, mx0, 1));
            mx0 = fmaxf(mx0, __shfl_xor_sync(0xffffffffu, mx0, 2));
            mx1 = fmaxf(mx1, __shfl_xor_sync(0xffffffffu, mx1, 1));
            mx1 = fmaxf(mx1, __shfl_xor_sync(0xffffffffu, mx1, 2));
            float mn0 = fmaxf(m[mi][0], mx0), mn1 = fmaxf(m[mi][1], mx1);
            float al0 = __expf(m[mi][0] - mn0), al1 = __expf(m[mi][1] - mn1);
            m[mi][0] = mn0; m[mi][1] = mn1;
            float sum0 = 0.0f, sum1 = 0.0f;
#pragma unroll
            for (int nf = 0; nf < 8; nf++) {
                s[mi][nf][0] = __expf(s[mi][nf][0] - mn0);
                s[mi][nf][1] = __expf(s[mi][nf][1] - mn0);
                s[mi][nf][2] = __expf(s[mi][nf][2] - mn1);
                s[mi][nf][3] = __expf(s[mi][nf][3] - mn1);
                sum0 += s[mi][nf][0] + s[mi][nf][1];
                sum1 += s[mi][nf][2] + s[mi][nf][3];
            }
            sum0 += __shfl_xor_sync(0xffffffffu, sum0, 1);
            sum0 += __shfl_xor_sync(0xffffffffu, sum0, 2);
            sum1 += __shfl_xor_sync(0xffffffffu, sum1, 1);
            sum1 += __shfl_xor_sync(0xffffffffu, sum1, 2);
            l[mi][0] = l[mi][0] * al0 + sum0;
            l[mi][1] = l[mi][1] * al1 + sum1;
#pragma unroll
            for (int nf = 0; nf < 8; nf++) {
                o[mi][nf][0] *= al0; o[mi][nf][1] *= al0;
                o[mi][nf][2] *= al1; o[mi][nf][3] *= al1;
            }
        }

        // ---- O += P . V : A-frag = identity pack of own c-regs ----
#pragma unroll
        for (int kf = 0; kf < 4; kf++) {
            unsigned af[2][4];
#pragma unroll
            for (int mi = 0; mi < 2; mi++) {
                af[mi][0] = packh2(s[mi][2 * kf][0],     s[mi][2 * kf][1]);
                af[mi][1] = packh2(s[mi][2 * kf][2],     s[mi][2 * kf][3]);
                af[mi][2] = packh2(s[mi][2 * kf + 1][0], s[mi][2 * kf + 1][1]);
                af[mi][3] = packh2(s[mi][2 * kf + 1][2], s[mi][2 * kf + 1][3]);
            }
#pragma unroll
            for (int nf = 0; nf < 8; nf++) {
                unsigned bfr[2];
                bfr[0] = VTs[(nf * 8 + g) * AT_W + kf * 8 + t];
                bfr[1] = VTs[(nf * 8 + g) * AT_W + kf * 8 + t + 4];
                mma_f16(o[0][nf], af[0], bfr);
                mma_f16(o[1][nf], af[1], bfr);
            }
        }
    }

    // ---- normalize; write ctx fp16 [token][c] ----
    __half* obase = ctx + ((size_t)b * SEQ + qt * QROWS + qrow0) * DM + h * HD;
#pragma unroll
    for (int mi = 0; mi < 2; mi++) {
        float inv0 = 1.0f / l[mi][0], inv1 = 1.0f / l[mi][1];
        __half* ob = obase + (size_t)(mi * 16) * DM;
#pragma unroll
        for (int nf = 0; nf < 8; nf++) {
            int col = nf * 8 + 2 * t;
            *(__half2*)&ob[(size_t)g * DM + col] =
                __floats2half2_rn(o[mi][nf][0] * inv0, o[mi][nf][1] * inv0);
            *(__half2*)&ob[(size_t)(g + 8) * DM + col] =
                __floats2half2_rn(o[mi][nf][2] * inv1, o[mi][nf][3] * inv1);
        }
    }
}

// ---------------------------------------------------------------------------
extern "C" void kernel_launch(void* const* d_in, const int* in_sizes, int n_in,
                              void* d_out, int out_size)
{
    const float* q    = (const float*)d_in[0];
    const float* k    = (const float*)d_in[1];
    const float* v    = (const float*)d_in[2];
    const int*   mask = (const int*)  d_in[3];
    const float* Wq   = (const float*)d_in[4];
    const float* bq   = (const float*)d_in[5];
    const float* Wk   = (const float*)d_in[6];
    const float* bk   = (const float*)d_in[7];
    const float* Wv   = (const float*)d_in[8];
    const float* bv   = (const float*)d_in[9];
    const float* Wo   = (const float*)d_in[10];
    const float* bo   = (const float*)d_in[11];
    float* out = (float*)d_out;

    void *pqh, *pkh, *pvh, *pwT, *pqw, *pkw, *pvw, *pvwT, *pctx;
    cudaGetSymbolAddress(&pqh, g_qh);
    cudaGetSymbolAddress(&pkh, g_kh);
    cudaGetSymbolAddress(&pvh, g_vh);
    cudaGetSymbolAddress(&pwT, g_wT);
    cudaGetSymbolAddress(&pqw, g_qw);
    cudaGetSymbolAddress(&pkw, g_kw);
    cudaGetSymbolAddress(&pvw, g_vw);
    cudaGetSymbolAddress(&pvwT, g_vwT);
    cudaGetSymbolAddress(&pctx, g_ctx);

    __half* qh   = (__half*)pqh;
    __half* kh   = (__half*)pkh;
    __half* vh   = (__half*)pvh;
    __half* wT   = (__half*)pwT;
    __half* qwp  = (__half*)pqw;
    __half* kwp  = (__half*)pkw;
    __half* vwp  = (__half*)pvw;
    __half* vwT  = (__half*)pvwT;
    __half* ctx  = (__half*)pctx;

    cudaFuncSetAttribute(gemm_f16,
                         cudaFuncAttributeMaxDynamicSharedMemorySize, GEMM_SMEM);
    cudaFuncSetAttribute(attn_mma,
                         cudaFuncAttributeMaxDynamicSharedMemorySize, ATTN_SMEM);

    // 1) fp16 converts + weight transposes
    const int nBig = MROWS * DM / 4;
    to_f16_k<<<nBig / 256, 256>>>((const float4*)q, (__half2*)qh, nBig);
    to_f16_k<<<nBig / 256, 256>>>((const float4*)k, (__half2*)kh, nBig);
    to_f16_k<<<nBig / 256, 256>>>((const float4*)v, (__half2*)vh, nBig);
    dim3 tgrid(DM / 32, DM / 32), tblk(32, 8);
    transp_w<<<tgrid, tblk>>>(Wq, wT + 0 * (size_t)DM * DM);
    transp_w<<<tgrid, tblk>>>(Wk, wT + 1 * (size_t)DM * DM);
    transp_w<<<tgrid, tblk>>>(Wv, wT + 2 * (size_t)DM * DM);
    transp_w<<<tgrid, tblk>>>(Wo, wT + 3 * (size_t)DM * DM);

    dim3 ggrid(DM / 128, MROWS / 128);   // (8, 32)

    // 2) projections (fp16 out; Q pre-scaled by 1/sqrt(64))
    gemm_f16<<<ggrid, 256, GEMM_SMEM>>>(qh, wT + 0 * (size_t)DM * DM, bq,
                                        (float*)qwp, MROWS, DM, DM, 0.125f, 1);
    gemm_f16<<<ggrid, 256, GEMM_SMEM>>>(kh, wT + 1 * (size_t)DM * DM, bk,
                                        (float*)kwp, MROWS, DM, DM, 1.0f, 1);
    gemm_f16<<<ggrid, 256, GEMM_SMEM>>>(vh, wT + 2 * (size_t)DM * DM, bv,
                                        (float*)vwp, MROWS, DM, DM, 1.0f, 1);

    // 2b) V^T per batch for PV B-operand adjacency
    transp_vw<<<dim3(SEQ / 64, DM / 64, NB), 256>>>(vwp, vwT);

    // 3) fused attention -> ctx (fp16)
    attn_mma<<<dim3(SEQ / QROWS, NH, NB), 256, ATTN_SMEM>>>(
        qwp, kwp, vwT, mask, ctx);

    // 4) output projection (fp32 out)
    gemm_f16<<<ggrid, 256, GEMM_SMEM>>>(ctx, wT + 3 * (size_t)DM * DM, bo,
                                        out, MROWS, DM, DM, 1.0f, 0);
}

// round 10
// speedup vs baseline: 2.0063x; 1.1051x over previous
#include <cuda_runtime.h>
#include <cuda_fp16.h>
#include <math.h>
#include <cstdint>

#define SEQ 2048
#define DM 1024
#define NH 16
#define HD 64
#define NB 2
#define MROWS (NB * SEQ)   // 4096
#define N3 (3 * DM)        // 3072 (qkv buffer width)

// Scratch (__device__ globals; allocation-free rule). fp16 payloads.
__device__ __half g_inh[3 * MROWS * DM];  // fp16(q|k|v) inputs, tensor-major
__device__ __half g_wT[4 * DM * DM];      // fp16(Wq^T|Wk^T|Wv^T|Wo^T) [N][K]
__device__ __half g_qkv[MROWS * N3];      // fp16 proj: [token][Q|K|V], Q*0.125
__device__ __half g_vwT[NB * DM * SEQ];   // fp16(proj V)^T  [b][c][token]
__device__ __half g_ctx[MROWS * DM];      // fp16(attn out)  [token][c]

__device__ __forceinline__ void mma_f16(float c[4], const unsigned a[4],
                                        const unsigned b[2]) {
    asm volatile(
        "mma.sync.aligned.m16n8k16.row.col.f32.f16.f16.f32 "
        "{%0,%1,%2,%3}, {%4,%5,%6,%7}, {%8,%9}, {%0,%1,%2,%3};\n"
        : "+f"(c[0]), "+f"(c[1]), "+f"(c[2]), "+f"(c[3])
        : "r"(a[0]), "r"(a[1]), "r"(a[2]), "r"(a[3]), "r"(b[0]), "r"(b[1]));
}

__device__ __forceinline__ unsigned packh2(float lo, float hi) {
    __half2 h = __floats2half2_rn(lo, hi);
    return *(unsigned*)&h;
}

__device__ __forceinline__ void cp_cg16(void* dst, const void* src) {
    unsigned u = (unsigned)__cvta_generic_to_shared(dst);
    asm volatile("cp.async.cg.shared.global [%0], [%1], 16;" :: "r"(u), "l"(src));
}

extern __shared__ float sm_dyn[];

// ---------------------------------------------------------------------------
// Fused prepass kernels.
// ---------------------------------------------------------------------------
__global__ __launch_bounds__(256) void to_f16_3(
    const float4* __restrict__ q, const float4* __restrict__ k,
    const float4* __restrict__ v, __half2* __restrict__ out, int n4)
{
    int i = blockIdx.x * 256 + threadIdx.x;
    const float4* in = (blockIdx.z == 0) ? q : (blockIdx.z == 1) ? k : v;
    __half2* o = out + (size_t)blockIdx.z * (2 * (size_t)n4);
    if (i < n4) {
        float4 x = in[i];
        o[2 * i]     = __floats2half2_rn(x.x, x.y);
        o[2 * i + 1] = __floats2half2_rn(x.z, x.w);
    }
}

__global__ __launch_bounds__(256) void transp_w4(
    const float* __restrict__ w0, const float* __restrict__ w1,
    const float* __restrict__ w2, const float* __restrict__ w3,
    __half* __restrict__ out)
{
    __shared__ float t[32][33];
    const float* in = (blockIdx.z == 0) ? w0 : (blockIdx.z == 1) ? w1
                    : (blockIdx.z == 2) ? w2 : w3;
    __half* o = out + (size_t)blockIdx.z * DM * DM;
    int tx = threadIdx.x, ty = threadIdx.y;           // 32 x 8
    int bx = blockIdx.x * 32, by = blockIdx.y * 32;
#pragma unroll
    for (int j = 0; j < 4; j++)
        t[ty + j * 8][tx] = in[(size_t)(by + ty + j * 8) * DM + bx + tx];
    __syncthreads();
#pragma unroll
    for (int j = 0; j < 4; j++)
        o[(size_t)(bx + ty + j * 8) * DM + by + tx] =
            __float2half_rn(t[tx][ty + j * 8]);
}

// Per-batch fp16 transpose of V segment: out[b][c][tok] = qkv[b][tok][2048+c]
__global__ __launch_bounds__(256) void transp_vw(
    const __half* __restrict__ qkv, __half* __restrict__ out)
{
    __shared__ __half t[64][72];
    const int tid = threadIdx.x;
    const int tok0 = blockIdx.x * 64, c0 = blockIdx.y * 64, b = blockIdx.z;
    for (int i = tid; i < 64 * 64; i += 256) {
        int r = i >> 6, c = i & 63;
        t[r][c] = qkv[((size_t)b * SEQ + tok0 + r) * N3 + 2 * DM + c0 + c];
    }
    __syncthreads();
    for (int i = tid; i < 64 * 64; i += 256) {
        int r = i >> 6, c = i & 63;
        out[((size_t)b * DM + c0 + r) * SEQ + tok0 + c] = t[c][r];
    }
}

// ---------------------------------------------------------------------------
// GEMM tiles: 128x128 block, 256 threads, 8 warps x (64x32), m16n8k16,
// k-chunk 64 halves, smem pitch 36 words (conflict-free 4g+t).
// ---------------------------------------------------------------------------
#define GW 36
#define GEMM_STAGE (128 * GW)
#define GEMM_SMEM ((4 * GEMM_STAGE) * (int)sizeof(float))

__device__ __forceinline__ void gemm_prefetch(
    unsigned* As, unsigned* Bs, const __half* A, const __half* WT,
    int K, int bm, int bn, int k0, int tid)
{
#pragma unroll
    for (int j = 0; j < 4; j++) {
        int idx = tid + j * 256;
        int row = idx >> 3;
        int c16 = idx & 7;
        cp_cg16(&As[row * GW + c16 * 4],
                A + (size_t)(bm + row) * K + k0 + c16 * 8);
        cp_cg16(&Bs[row * GW + c16 * 4],
                WT + (size_t)(bn + row) * K + k0 + c16 * 8);
    }
}

// Shared mainloop: accumulates the 128x128 tile into acc.
__device__ __forceinline__ void gemm_mainloop(
    float acc[4][4][4], const __half* A, const __half* WT,
    int K, int bm, int bn, int tid, int wm, int wn, int g, int t)
{
    unsigned* As0 = (unsigned*)sm_dyn;
    unsigned* Bs0 = As0 + 2 * GEMM_STAGE;

    gemm_prefetch(As0, Bs0, A, WT, K, bm, bn, 0, tid);
    asm volatile("cp.async.commit_group;" ::: "memory");

    const int NKI = K / 64;
    for (int i = 0; i < NKI; i++) {
        const int st = i & 1;
        asm volatile("cp.async.wait_group 0;" ::: "memory");
        __syncthreads();
        if (i + 1 < NKI) {
            gemm_prefetch(As0 + (st ^ 1) * GEMM_STAGE,
                          Bs0 + (st ^ 1) * GEMM_STAGE,
                          A, WT, K, bm, bn, (i + 1) * 64, tid);
            asm volatile("cp.async.commit_group;" ::: "memory");
        }
        const unsigned* As = As0 + st * GEMM_STAGE;
        const unsigned* Bs = Bs0 + st * GEMM_STAGE;

#pragma unroll
        for (int kf = 0; kf < 4; kf++) {
            unsigned af[4][4], bf[4][2];
#pragma unroll
            for (int mi = 0; mi < 4; mi++) {
                int r = wm + mi * 16;
                af[mi][0] = As[(r + g)     * GW + kf * 8 + t];
                af[mi][1] = As[(r + g + 8) * GW + kf * 8 + t];
                af[mi][2] = As[(r + g)     * GW + kf * 8 + t + 4];
                af[mi][3] = As[(r + g + 8) * GW + kf * 8 + t + 4];
            }
#pragma unroll
            for (int ni = 0; ni < 4; ni++) {
                int c = wn + ni * 8;
                bf[ni][0] = Bs[(c + g) * GW + kf * 8 + t];
                bf[ni][1] = Bs[(c + g) * GW + kf * 8 + t + 4];
            }
#pragma unroll
            for (int mi = 0; mi < 4; mi++)
#pragma unroll
                for (int ni = 0; ni < 4; ni++)
                    mma_f16(acc[mi][ni], af[mi], bf[ni]);
        }
    }
}

// Grouped QKV projection: grid.z selects (input_z, Wz^T, bias_z, scale_z);
// output segment z*DM of the [token][N3] fp16 qkv buffer.
__global__ __launch_bounds__(256, 2) void gemm_qkv(
    const __half* __restrict__ inh, const __half* __restrict__ wT,
    const float* __restrict__ bq, const float* __restrict__ bk,
    const float* __restrict__ bv, __half* __restrict__ qkv)
{
    const int tid  = threadIdx.x;
    const int lane = tid & 31;
    const int warp = tid >> 5;
    const int g = lane >> 2, t = lane & 3;
    const int wm = (warp >> 2) * 64;
    const int wn = (warp & 3) * 32;
    const int bm = blockIdx.y * 128;
    const int bn = blockIdx.x * 128;
    const int z  = blockIdx.z;

    const __half* A  = inh + (size_t)z * MROWS * DM;
    const __half* WT = wT  + (size_t)z * DM * DM;
    const float* bias = (z == 0) ? bq : (z == 1) ? bk : bv;
    const float sc = (z == 0) ? 0.125f : 1.0f;

    float acc[4][4][4];
#pragma unroll
    for (int mi = 0; mi < 4; mi++)
#pragma unroll
        for (int ni = 0; ni < 4; ni++)
#pragma unroll
            for (int e = 0; e < 4; e++) acc[mi][ni][e] = 0.0f;

    gemm_mainloop(acc, A, WT, DM, bm, bn, tid, wm, wn, g, t);

#pragma unroll
    for (int mi = 0; mi < 4; mi++) {
        int r0 = bm + wm + mi * 16 + g;
#pragma unroll
        for (int ni = 0; ni < 4; ni++) {
            int cb = bn + wn + ni * 8 + 2 * t;
            float b0 = bias[cb], b1 = bias[cb + 1];
            float x00 = (acc[mi][ni][0] + b0) * sc;
            float x01 = (acc[mi][ni][1] + b1) * sc;
            float x10 = (acc[mi][ni][2] + b0) * sc;
            float x11 = (acc[mi][ni][3] + b1) * sc;
            __half* c0p = qkv + (size_t)r0 * N3 + z * DM + cb;
            *(__half2*)c0p = __floats2half2_rn(x00, x01);
            *(__half2*)(c0p + (size_t)8 * N3) = __floats2half2_rn(x10, x11);
        }
    }
}

// Output projection: C(fp32) = ctx(fp16) @ Wo + bo.
__global__ __launch_bounds__(256, 2) void gemm_out(
    const __half* __restrict__ A, const __half* __restrict__ WT,
    const float* __restrict__ bias, float* __restrict__ C)
{
    const int tid  = threadIdx.x;
    const int lane = tid & 31;
    const int warp = tid >> 5;
    const int g = lane >> 2, t = lane & 3;
    const int wm = (warp >> 2) * 64;
    const int wn = (warp & 3) * 32;
    const int bm = blockIdx.y * 128;
    const int bn = blockIdx.x * 128;

    float acc[4][4][4];
#pragma unroll
    for (int mi = 0; mi < 4; mi++)
#pragma unroll
        for (int ni = 0; ni < 4; ni++)
#pragma unroll
            for (int e = 0; e < 4; e++) acc[mi][ni][e] = 0.0f;

    gemm_mainloop(acc, A, WT, DM, bm, bn, tid, wm, wn, g, t);

#pragma unroll
    for (int mi = 0; mi < 4; mi++) {
        int r0 = bm + wm + mi * 16 + g;
#pragma unroll
        for (int ni = 0; ni < 4; ni++) {
            int cb = bn + wn + ni * 8 + 2 * t;
            float b0 = bias[cb], b1 = bias[cb + 1];
            *(float2*)&C[(size_t)r0 * DM + cb] =
                make_float2(acc[mi][ni][0] + b0, acc[mi][ni][1] + b1);
            *(float2*)&C[(size_t)(r0 + 8) * DM + cb] =
                make_float2(acc[mi][ni][2] + b0, acc[mi][ni][3] + b1);
        }
    }
}

// ---------------------------------------------------------------------------
// Flash-attention, fp16 mma. 256 threads / 8 warps, QROWS=256 (32 rows/warp).
// Q/K from qkv buffer (row stride N3; K at col offset DM). V transposed
// [d][key] (g_vwT). P C->A layout is identity in fp16. 3-stage cp.async.
// ---------------------------------------------------------------------------
#define QROWS 256
#define KTILE 64
#define NT (SEQ / KTILE)
#define NSTG 3
#define AT_W 36
#define STAGE_W (KTILE * AT_W * 2 + 64)
#define QS_W (QROWS * AT_W)
#define ATTN_SMEM ((NSTG * STAGE_W + QS_W) * (int)sizeof(float))

__device__ __forceinline__ void attn_prefetch(
    unsigned* stage, const __half* kb, const __half* vtb, const int* mb,
    int kt, int tid)
{
    unsigned* Ks  = stage;
    unsigned* VTs = stage + KTILE * AT_W;
    unsigned* Mk  = VTs + KTILE * AT_W;
#pragma unroll
    for (int j = 0; j < 2; j++) {
        int idx = tid + j * 256;
        int row = idx >> 3;
        int c16 = idx & 7;
        cp_cg16(&Ks[row * AT_W + c16 * 4],
                kb + (size_t)(kt * KTILE + row) * N3 + c16 * 8);
        cp_cg16(&VTs[row * AT_W + c16 * 4],
                vtb + (size_t)row * SEQ + kt * KTILE + c16 * 8);
    }
    if (tid < 16) cp_cg16(&Mk[tid * 4], mb + kt * KTILE + tid * 4);
}

__global__ __launch_bounds__(256) void attn_mma(
    const __half* __restrict__ qkv, const __half* __restrict__ vwT,
    const int* __restrict__ vmask, __half* __restrict__ ctx)
{
    const int tid  = threadIdx.x;
    const int lane = tid & 31;
    const int warp = tid >> 5;
    const int g = lane >> 2, t = lane & 3;
    const int qrow0 = warp * 32;
    const int qt = blockIdx.x, h = blockIdx.y, b = blockIdx.z;

    unsigned* Qs = (unsigned*)(sm_dyn + NSTG * STAGE_W);

    const __half* qb = qkv + ((size_t)b * SEQ + qt * QROWS) * N3 + h * HD;
#pragma unroll
    for (int j = 0; j < 8; j++) {
        int idx = tid + j * 256;
        int row = idx >> 3, c16 = idx & 7;
        cp_cg16(&Qs[row * AT_W + c16 * 4], qb + (size_t)row * N3 + c16 * 8);
    }

    const __half* kbase  = qkv + ((size_t)b * SEQ) * N3 + DM + h * HD;
    const __half* vtbase = vwT + ((size_t)b * DM + h * HD) * SEQ;
    const int*    mbase  = vmask + b * SEQ;

    attn_prefetch((unsigned*)sm_dyn, kbase, vtbase, mbase, 0, tid);
    asm volatile("cp.async.commit_group;" ::: "memory");
    attn_prefetch((unsigned*)sm_dyn + STAGE_W, kbase, vtbase, mbase, 1, tid);
    asm volatile("cp.async.commit_group;" ::: "memory");

    float m[2][2], l[2][2];
#pragma unroll
    for (int mi = 0; mi < 2; mi++) {
        m[mi][0] = -1e30f; m[mi][1] = -1e30f;
        l[mi][0] = 0.0f;   l[mi][1] = 0.0f;
    }
    float o[2][8][4];
#pragma unroll
    for (int mi = 0; mi < 2; mi++)
#pragma unroll
        for (int nf = 0; nf < 8; nf++)
#pragma unroll
            for (int e = 0; e < 4; e++) o[mi][nf][e] = 0.0f;

    int st = 0;
    for (int kt = 0; kt < NT; kt++) {
        asm volatile("cp.async.wait_group 1;" ::: "memory");
        __syncthreads();
        if (kt + 2 < NT) {
            int j = st - 1; if (j < 0) j += NSTG;
            attn_prefetch((unsigned*)sm_dyn + j * STAGE_W,
                          kbase, vtbase, mbase, kt + 2, tid);
            asm volatile("cp.async.commit_group;" ::: "memory");
        } else {
            asm volatile("cp.async.commit_group;" ::: "memory");
        }
        const unsigned* Ks  = (const unsigned*)sm_dyn + st * STAGE_W;
        const unsigned* VTs = Ks + KTILE * AT_W;
        const int*      Mk  = (const int*)(VTs + KTILE * AT_W);
        if (++st == NSTG) st = 0;

        // ---- S = Q . K^T ----
        float s[2][8][4];
#pragma unroll
        for (int mi = 0; mi < 2; mi++)
#pragma unroll
            for (int nf = 0; nf < 8; nf++)
#pragma unroll
                for (int e = 0; e < 4; e++) s[mi][nf][e] = 0.0f;

#pragma unroll
        for (int kf = 0; kf < 4; kf++) {
            unsigned a0[4], a1[4];
            a0[0] = Qs[(qrow0 + g)      * AT_W + kf * 8 + t];
            a0[1] = Qs[(qrow0 + g + 8)  * AT_W + kf * 8 + t];
            a0[2] = Qs[(qrow0 + g)      * AT_W + kf * 8 + t + 4];
            a0[3] = Qs[(qrow0 + g + 8)  * AT_W + kf * 8 + t + 4];
            a1[0] = Qs[(qrow0 + g + 16) * AT_W + kf * 8 + t];
            a1[1] = Qs[(qrow0 + g + 24) * AT_W + kf * 8 + t];
            a1[2] = Qs[(qrow0 + g + 16) * AT_W + kf * 8 + t + 4];
            a1[3] = Qs[(qrow0 + g + 24) * AT_W + kf * 8 + t + 4];
#pragma unroll
            for (int nf = 0; nf < 8; nf++) {
                unsigned bfr[2];
                bfr[0] = Ks[(nf * 8 + g) * AT_W + kf * 8 + t];
                bfr[1] = Ks[(nf * 8 + g) * AT_W + kf * 8 + t + 4];
                mma_f16(s[0][nf], a0, bfr);
                mma_f16(s[1][nf], a1, bfr);
            }
        }

        // ---- mask + online softmax ----
#pragma unroll
        for (int mi = 0; mi < 2; mi++) {
            float mx0 = -1e30f, mx1 = -1e30f;
#pragma unroll
            for (int nf = 0; nf < 8; nf++) {
                float pen0 = Mk[nf * 8 + 2 * t]     ? 0.0f : 1e12f;
                float pen1 = Mk[nf * 8 + 2 * t + 1] ? 0.0f : 1e12f;
                s[mi][nf][0] -= pen0; s[mi][nf][1] -= pen1;
                s[mi][nf][2] -= pen0; s[mi][nf][3] -= pen1;
                mx0 = fmaxf(mx0, fmaxf(s[mi][nf][0], s[mi][nf][1]));
                mx1 = fmaxf(mx1, fmaxf(s[mi][nf][2], s[mi][nf][3]));
            }
            mx0 = fmaxf(mx0, __shfl_xor_sync(0xffffffffu, mx0, 1));
            mx0 = fmaxf(mx0, __shfl_xor_sync(0xffffffffu, mx0, 2));
            mx1 = fmaxf(mx1, __shfl_xor_sync(0xffffffffu, mx1, 1));
            mx1 = fmaxf(mx1, __shfl_xor_sync(0xffffffffu, mx1, 2));
            float mn0 = fmaxf(m[mi][0], mx0), mn1 = fmaxf(m[mi][1], mx1);
            float al0 = __expf(m[mi][0] - mn0), al1 = __expf(m[mi][1] - mn1);
            m[mi][0] = mn0; m[mi][1] = mn1;
            float sum0 = 0.0f, sum1 = 0.0f;
#pragma unroll
            for (int nf = 0; nf < 8; nf++) {
                s[mi][nf][0] = __expf(s[mi][nf][0] - mn0);
                s[mi][nf][1] = __expf(s[mi][nf][1] - mn0);
                s[mi][nf][2] = __expf(s[mi][nf][2] - mn1);
                s[mi][nf][3] = __expf(s[mi][nf][3] - mn1);
                sum0 += s[mi][nf][0] + s[mi][nf][1];
                sum1 += s[mi][nf][2] + s[mi][nf][3];
            }
            sum0 += __shfl_xor_sync(0xffffffffu, sum0, 1);
            sum0 += __shfl_xor_sync(0xffffffffu, sum0, 2);
            sum1 += __shfl_xor_sync(0xffffffffu, sum1, 1);
            sum1 += __shfl_xor_sync(0xffffffffu, sum1, 2);
            l[mi][0] = l[mi][0] * al0 + sum0;
            l[mi][1] = l[mi][1] * al1 + sum1;
#pragma unroll
            for (int nf = 0; nf < 8; nf++) {
                o[mi][nf][0] *= al0; o[mi][nf][1] *= al0;
                o[mi][nf][2] *= al1; o[mi][nf][3] *= al1;
            }
        }

        // ---- O += P . V : A-frag = identity pack of own c-regs ----
#pragma unroll
        for (int kf = 0; kf < 4; kf++) {
            unsigned af[2][4];
#pragma unroll
            for (int mi = 0; mi < 2; mi++) {
                af[mi][0] = packh2(s[mi][2 * kf][0],     s[mi][2 * kf][1]);
                af[mi][1] = packh2(s[mi][2 * kf][2],     s[mi][2 * kf][3]);
                af[mi][2] = packh2(s[mi][2 * kf + 1][0], s[mi][2 * kf + 1][1]);
                af[mi][3] = packh2(s[mi][2 * kf + 1][2], s[mi][2 * kf + 1][3]);
            }
#pragma unroll
            for (int nf = 0; nf < 8; nf++) {
                unsigned bfr[2];
                bfr[0] = VTs[(nf * 8 + g) * AT_W + kf * 8 + t];
                bfr[1] = VTs[(nf * 8 + g) * AT_W + kf * 8 + t + 4];
                mma_f16(o[0][nf], af[0], bfr);
                mma_f16(o[1][nf], af[1], bfr);
            }
        }
    }

    // ---- normalize; write ctx fp16 [token][c] ----
    __half* obase = ctx + ((size_t)b * SEQ + qt * QROWS + qrow0) * DM + h * HD;
#pragma unroll
    for (int mi = 0; mi < 2; mi++) {
        float inv0 = 1.0f / l[mi][0], inv1 = 1.0f / l[mi][1];
        __half* ob = obase + (size_t)(mi * 16) * DM;
#pragma unroll
        for (int nf = 0; nf < 8; nf++) {
            int col = nf * 8 + 2 * t;
            *(__half2*)&ob[(size_t)g * DM + col] =
                __floats2half2_rn(o[mi][nf][0] * inv0, o[mi][nf][1] * inv0);
            *(__half2*)&ob[(size_t)(g + 8) * DM + col] =
                __floats2half2_rn(o[mi][nf][2] * inv1, o[mi][nf][3] * inv1);
        }
    }
}

// ---------------------------------------------------------------------------
extern "C" void kernel_launch(void* const* d_in, const int* in_sizes, int n_in,
                              void* d_out, int out_size)
{
    const float* q    = (const float*)d_in[0];
    const float* k    = (const float*)d_in[1];
    const float* v    = (const float*)d_in[2];
    const int*   mask = (const int*)  d_in[3];
    const float* Wq   = (const float*)d_in[4];
    const float* bq   = (const float*)d_in[5];
    const float* Wk   = (const float*)d_in[6];
    const float* bk   = (const float*)d_in[7];
    const float* Wv   = (const float*)d_in[8];
    const float* bv   = (const float*)d_in[9];
    const float* Wo   = (const float*)d_in[10];
    const float* bo   = (const float*)d_in[11];
    float* out = (float*)d_out;

    void *pin, *pwT, *pqkv, *pvwT, *pctx;
    cudaGetSymbolAddress(&pin,  g_inh);
    cudaGetSymbolAddress(&pwT,  g_wT);
    cudaGetSymbolAddress(&pqkv, g_qkv);
    cudaGetSymbolAddress(&pvwT, g_vwT);
    cudaGetSymbolAddress(&pctx, g_ctx);

    __half* inh = (__half*)pin;
    __half* wT  = (__half*)pwT;
    __half* qkv = (__half*)pqkv;
    __half* vwT = (__half*)pvwT;
    __half* ctx = (__half*)pctx;

    cudaFuncSetAttribute(gemm_qkv,
                         cudaFuncAttributeMaxDynamicSharedMemorySize, GEMM_SMEM);
    cudaFuncSetAttribute(gemm_out,
                         cudaFuncAttributeMaxDynamicSharedMemorySize, GEMM_SMEM);
    cudaFuncSetAttribute(attn_mma,
                         cudaFuncAttributeMaxDynamicSharedMemorySize, ATTN_SMEM);

    // 1) fused prepass: fp16 converts (z=3) + weight transposes (z=4)
    const int nBig = MROWS * DM / 4;
    to_f16_3<<<dim3(nBig / 256, 1, 3), 256>>>(
        (const float4*)q, (const float4*)k, (const float4*)v,
        (__half2*)inh, nBig);
    transp_w4<<<dim3(DM / 32, DM / 32, 4), dim3(32, 8)>>>(Wq, Wk, Wv, Wo, wT);

    // 2) grouped QKV projection: z selects (input_z, Wz, bias_z, scale_z)
    gemm_qkv<<<dim3(DM / 128, MROWS / 128, 3), 256, GEMM_SMEM>>>(
        inh, wT, bq, bk, bv, qkv);

    // 2b) V^T per batch for PV B-operand adjacency
    transp_vw<<<dim3(SEQ / 64, DM / 64, NB), 256>>>(qkv, vwT);

    // 3) fused attention -> ctx (fp16)
    attn_mma<<<dim3(SEQ / QROWS, NH, NB), 256, ATTN_SMEM>>>(
        qkv, vwT, mask, ctx);

    // 4) output projection (fp32 out)
    gemm_out<<<dim3(DM / 128, MROWS / 128), 256, GEMM_SMEM>>>(
        ctx, wT + 3 * (size_t)DM * DM, bo, out);
}

// round 11
// speedup vs baseline: 2.0574x; 1.0255x over previous
#include <cuda_runtime.h>
#include <cuda_fp16.h>
#include <math.h>
#include <cstdint>

#define SEQ 2048
#define DM 1024
#define NH 16
#define HD 64
#define NB 2
#define MROWS (NB * SEQ)   // 4096
#define N3 (3 * DM)        // 3072 (qkv buffer width)

// log2(e): Q projection is pre-scaled by 0.125*LOG2E so softmax runs in the
// exp2 domain (exactly equivalent to exp-e softmax).
#define QSCALE 0.18033688011112042f   // 0.125 * log2(e)

// Scratch (__device__ globals; allocation-free rule). fp16 payloads.
__device__ __half g_inh[3 * MROWS * DM];  // fp16(q|k|v) inputs, tensor-major
__device__ __half g_wT[4 * DM * DM];      // fp16(Wq^T|Wk^T|Wv^T|Wo^T) [N][K]
__device__ __half g_qkv[MROWS * N3];      // fp16 proj: [token][Q|K|V]
__device__ __half g_vwT[NB * DM * SEQ];   // fp16(proj V)^T  [b][c][token]
__device__ __half g_ctx[MROWS * DM];      // fp16(attn out)  [token][c]

__device__ __forceinline__ void mma_f16(float c[4], const unsigned a[4],
                                        const unsigned b[2]) {
    asm volatile(
        "mma.sync.aligned.m16n8k16.row.col.f32.f16.f16.f32 "
        "{%0,%1,%2,%3}, {%4,%5,%6,%7}, {%8,%9}, {%0,%1,%2,%3};\n"
        : "+f"(c[0]), "+f"(c[1]), "+f"(c[2]), "+f"(c[3])
        : "r"(a[0]), "r"(a[1]), "r"(a[2]), "r"(a[3]), "r"(b[0]), "r"(b[1]));
}

__device__ __forceinline__ unsigned h2ex2(float lo, float hi) {
    __half2 d = __floats2half2_rn(lo, hi);
    unsigned x = *(unsigned*)&d, r;
    asm("ex2.approx.f16x2 %0, %1;" : "=r"(r) : "r"(x));
    return r;
}
__device__ __forceinline__ float ex2f(float x) {
    float r;
    asm("ex2.approx.f32 %0, %1;" : "=f"(r) : "f"(x));
    return r;
}
__device__ __forceinline__ float2 h2_to_f2(unsigned u) {
    __half2 h = *(__half2*)&u;
    return __half22float2(h);
}

__device__ __forceinline__ void cp_cg16(void* dst, const void* src) {
    unsigned u = (unsigned)__cvta_generic_to_shared(dst);
    asm volatile("cp.async.cg.shared.global [%0], [%1], 16;" :: "r"(u), "l"(src));
}

extern __shared__ float sm_dyn[];

// ---------------------------------------------------------------------------
// Fused prepass kernels.
// ---------------------------------------------------------------------------
__global__ __launch_bounds__(256) void to_f16_3(
    const float4* __restrict__ q, const float4* __restrict__ k,
    const float4* __restrict__ v, __half2* __restrict__ out, int n4)
{
    int i = blockIdx.x * 256 + threadIdx.x;
    const float4* in = (blockIdx.z == 0) ? q : (blockIdx.z == 1) ? k : v;
    __half2* o = out + (size_t)blockIdx.z * (2 * (size_t)n4);
    if (i < n4) {
        float4 x = in[i];
        o[2 * i]     = __floats2half2_rn(x.x, x.y);
        o[2 * i + 1] = __floats2half2_rn(x.z, x.w);
    }
}

__global__ __launch_bounds__(256) void transp_w4(
    const float* __restrict__ w0, const float* __restrict__ w1,
    const float* __restrict__ w2, const float* __restrict__ w3,
    __half* __restrict__ out)
{
    __shared__ float t[32][33];
    const float* in = (blockIdx.z == 0) ? w0 : (blockIdx.z == 1) ? w1
                    : (blockIdx.z == 2) ? w2 : w3;
    __half* o = out + (size_t)blockIdx.z * DM * DM;
    int tx = threadIdx.x, ty = threadIdx.y;           // 32 x 8
    int bx = blockIdx.x * 32, by = blockIdx.y * 32;
#pragma unroll
    for (int j = 0; j < 4; j++)
        t[ty + j * 8][tx] = in[(size_t)(by + ty + j * 8) * DM + bx + tx];
    __syncthreads();
#pragma unroll
    for (int j = 0; j < 4; j++)
        o[(size_t)(bx + ty + j * 8) * DM + by + tx] =
            __float2half_rn(t[tx][ty + j * 8]);
}

// Vectorized per-batch fp16 transpose of V segment:
// out[b][c][tok] = qkv[b][tok][2048+c].  64x64 tiles, uint4 global accesses,
// XOR-swizzled smem (B' = B ^ ((c>>3)&7)) for conflict-free STS.16/LDS.128.
__global__ __launch_bounds__(256) void transp_vw(
    const __half* __restrict__ qkv, __half* __restrict__ out)
{
    __shared__ __half t[64 * 72];
    const int tid = threadIdx.x;
    const int tok0 = blockIdx.x * 64, c0 = blockIdx.y * 64, b = blockIdx.z;

#pragma unroll
    for (int pass = 0; pass < 2; pass++) {
        int tok = pass * 32 + (tid >> 3);
        int cc  = (tid & 7) * 8;
        uint4 x = *(const uint4*)&qkv[((size_t)b * SEQ + tok0 + tok) * N3
                                      + 2 * DM + c0 + cc];
        const __half* hp = (const __half*)&x;
        int B = tok >> 3, r = tok & 7;
#pragma unroll
        for (int j = 0; j < 8; j++) {
            int c  = cc + j;
            int Bs = B ^ ((c >> 3) & 7);
            t[c * 72 + Bs * 8 + r] = hp[j];
        }
    }
    __syncthreads();
#pragma unroll
    for (int pass = 0; pass < 2; pass++) {
        int c  = pass * 32 + (tid >> 3);
        int B  = tid & 7;
        int Bs = B ^ ((c >> 3) & 7);
        uint4 y = *(const uint4*)&t[c * 72 + Bs * 8];
        *(uint4*)&out[((size_t)b * DM + c0 + c) * SEQ + tok0 + B * 8] = y;
    }
}

// ---------------------------------------------------------------------------
// GEMM tiles: 128x128 block, 256 threads, 8 warps x (64x32), m16n8k16,
// k-chunk 64 halves, smem pitch 36 words (conflict-free 4g+t).
// ---------------------------------------------------------------------------
#define GW 36
#define GEMM_STAGE (128 * GW)
#define GEMM_SMEM ((4 * GEMM_STAGE) * (int)sizeof(float))

__device__ __forceinline__ void gemm_prefetch(
    unsigned* As, unsigned* Bs, const __half* A, const __half* WT,
    int K, int bm, int bn, int k0, int tid)
{
#pragma unroll
    for (int j = 0; j < 4; j++) {
        int idx = tid + j * 256;
        int row = idx >> 3;
        int c16 = idx & 7;
        cp_cg16(&As[row * GW + c16 * 4],
                A + (size_t)(bm + row) * K + k0 + c16 * 8);
        cp_cg16(&Bs[row * GW + c16 * 4],
                WT + (size_t)(bn + row) * K + k0 + c16 * 8);
    }
}

__device__ __forceinline__ void gemm_mainloop(
    float acc[4][4][4], const __half* A, const __half* WT,
    int K, int bm, int bn, int tid, int wm, int wn, int g, int t)
{
    unsigned* As0 = (unsigned*)sm_dyn;
    unsigned* Bs0 = As0 + 2 * GEMM_STAGE;

    gemm_prefetch(As0, Bs0, A, WT, K, bm, bn, 0, tid);
    asm volatile("cp.async.commit_group;" ::: "memory");

    const int NKI = K / 64;
    for (int i = 0; i < NKI; i++) {
        const int st = i & 1;
        asm volatile("cp.async.wait_group 0;" ::: "memory");
        __syncthreads();
        if (i + 1 < NKI) {
            gemm_prefetch(As0 + (st ^ 1) * GEMM_STAGE,
                          Bs0 + (st ^ 1) * GEMM_STAGE,
                          A, WT, K, bm, bn, (i + 1) * 64, tid);
            asm volatile("cp.async.commit_group;" ::: "memory");
        }
        const unsigned* As = As0 + st * GEMM_STAGE;
        const unsigned* Bs = Bs0 + st * GEMM_STAGE;

#pragma unroll
        for (int kf = 0; kf < 4; kf++) {
            unsigned af[4][4], bf[4][2];
#pragma unroll
            for (int mi = 0; mi < 4; mi++) {
                int r = wm + mi * 16;
                af[mi][0] = As[(r + g)     * GW + kf * 8 + t];
                af[mi][1] = As[(r + g + 8) * GW + kf * 8 + t];
                af[mi][2] = As[(r + g)     * GW + kf * 8 + t + 4];
                af[mi][3] = As[(r + g + 8) * GW + kf * 8 + t + 4];
            }
#pragma unroll
            for (int ni = 0; ni < 4; ni++) {
                int c = wn + ni * 8;
                bf[ni][0] = Bs[(c + g) * GW + kf * 8 + t];
                bf[ni][1] = Bs[(c + g) * GW + kf * 8 + t + 4];
            }
#pragma unroll
            for (int mi = 0; mi < 4; mi++)
#pragma unroll
                for (int ni = 0; ni < 4; ni++)
                    mma_f16(acc[mi][ni], af[mi], bf[ni]);
        }
    }
}

// Grouped QKV projection: grid.z selects (input_z, Wz^T, bias_z, scale_z).
__global__ __launch_bounds__(256, 2) void gemm_qkv(
    const __half* __restrict__ inh, const __half* __restrict__ wT,
    const float* __restrict__ bq, const float* __restrict__ bk,
    const float* __restrict__ bv, __half* __restrict__ qkv)
{
    const int tid  = threadIdx.x;
    const int lane = tid & 31;
    const int warp = tid >> 5;
    const int g = lane >> 2, t = lane & 3;
    const int wm = (warp >> 2) * 64;
    const int wn = (warp & 3) * 32;
    const int bm = blockIdx.y * 128;
    const int bn = blockIdx.x * 128;
    const int z  = blockIdx.z;

    const __half* A  = inh + (size_t)z * MROWS * DM;
    const __half* WT = wT  + (size_t)z * DM * DM;
    const float* bias = (z == 0) ? bq : (z == 1) ? bk : bv;
    const float sc = (z == 0) ? QSCALE : 1.0f;

    float acc[4][4][4];
#pragma unroll
    for (int mi = 0; mi < 4; mi++)
#pragma unroll
        for (int ni = 0; ni < 4; ni++)
#pragma unroll
            for (int e = 0; e < 4; e++) acc[mi][ni][e] = 0.0f;

    gemm_mainloop(acc, A, WT, DM, bm, bn, tid, wm, wn, g, t);

#pragma unroll
    for (int mi = 0; mi < 4; mi++) {
        int r0 = bm + wm + mi * 16 + g;
#pragma unroll
        for (int ni = 0; ni < 4; ni++) {
            int cb = bn + wn + ni * 8 + 2 * t;
            float b0 = bias[cb], b1 = bias[cb + 1];
            float x00 = (acc[mi][ni][0] + b0) * sc;
            float x01 = (acc[mi][ni][1] + b1) * sc;
            float x10 = (acc[mi][ni][2] + b0) * sc;
            float x11 = (acc[mi][ni][3] + b1) * sc;
            __half* c0p = qkv + (size_t)r0 * N3 + z * DM + cb;
            *(__half2*)c0p = __floats2half2_rn(x00, x01);
            *(__half2*)(c0p + (size_t)8 * N3) = __floats2half2_rn(x10, x11);
        }
    }
}

// Output projection: C(fp32) = ctx(fp16) @ Wo + bo.
__global__ __launch_bounds__(256, 2) void gemm_out(
    const __half* __restrict__ A, const __half* __restrict__ WT,
    const float* __restrict__ bias, float* __restrict__ C)
{
    const int tid  = threadIdx.x;
    const int lane = tid & 31;
    const int warp = tid >> 5;
    const int g = lane >> 2, t = lane & 3;
    const int wm = (warp >> 2) * 64;
    const int wn = (warp & 3) * 32;
    const int bm = blockIdx.y * 128;
    const int bn = blockIdx.x * 128;

    float acc[4][4][4];
#pragma unroll
    for (int mi = 0; mi < 4; mi++)
#pragma unroll
        for (int ni = 0; ni < 4; ni++)
#pragma unroll
            for (int e = 0; e < 4; e++) acc[mi][ni][e] = 0.0f;

    gemm_mainloop(acc, A, WT, DM, bm, bn, tid, wm, wn, g, t);

#pragma unroll
    for (int mi = 0; mi < 4; mi++) {
        int r0 = bm + wm + mi * 16 + g;
#pragma unroll
        for (int ni = 0; ni < 4; ni++) {
            int cb = bn + wn + ni * 8 + 2 * t;
            float b0 = bias[cb], b1 = bias[cb + 1];
            *(float2*)&C[(size_t)r0 * DM + cb] =
                make_float2(acc[mi][ni][0] + b0, acc[mi][ni][1] + b1);
            *(float2*)&C[(size_t)(r0 + 8) * DM + cb] =
                make_float2(acc[mi][ni][2] + b0, acc[mi][ni][3] + b1);
        }
    }
}

// ---------------------------------------------------------------------------
// Flash-attention, fp16 mma, exp2-domain softmax with ex2.approx.f16x2
// (2 P-elements per MUFU op; output is directly the fp16 mma A-operand).
// 256 threads / 8 warps, QROWS=256, KTILE=64, 3-stage cp.async.
// ---------------------------------------------------------------------------
#define QROWS 256
#define KTILE 64
#define NT (SEQ / KTILE)
#define NSTG 3
#define AT_W 36
#define STAGE_W (KTILE * AT_W * 2 + 64)
#define QS_W (QROWS * AT_W)
#define ATTN_SMEM ((NSTG * STAGE_W + QS_W) * (int)sizeof(float))

__device__ __forceinline__ void attn_prefetch(
    unsigned* stage, const __half* kb, const __half* vtb, const int* mb,
    int kt, int tid)
{
    unsigned* Ks  = stage;
    unsigned* VTs = stage + KTILE * AT_W;
    unsigned* Mk  = VTs + KTILE * AT_W;
#pragma unroll
    for (int j = 0; j < 2; j++) {
        int idx = tid + j * 256;
        int row = idx >> 3;
        int c16 = idx & 7;
        cp_cg16(&Ks[row * AT_W + c16 * 4],
                kb + (size_t)(kt * KTILE + row) * N3 + c16 * 8);
        cp_cg16(&VTs[row * AT_W + c16 * 4],
                vtb + (size_t)row * SEQ + kt * KTILE + c16 * 8);
    }
    if (tid < 16) cp_cg16(&Mk[tid * 4], mb + kt * KTILE + tid * 4);
}

__global__ __launch_bounds__(256) void attn_mma(
    const __half* __restrict__ qkv, const __half* __restrict__ vwT,
    const int* __restrict__ vmask, __half* __restrict__ ctx)
{
    const int tid  = threadIdx.x;
    const int lane = tid & 31;
    const int warp = tid >> 5;
    const int g = lane >> 2, t = lane & 3;
    const int qrow0 = warp * 32;
    const int qt = blockIdx.x, h = blockIdx.y, b = blockIdx.z;

    unsigned* Qs = (unsigned*)(sm_dyn + NSTG * STAGE_W);

    const __half* qb = qkv + ((size_t)b * SEQ + qt * QROWS) * N3 + h * HD;
#pragma unroll
    for (int j = 0; j < 8; j++) {
        int idx = tid + j * 256;
        int row = idx >> 3, c16 = idx & 7;
        cp_cg16(&Qs[row * AT_W + c16 * 4], qb + (size_t)row * N3 + c16 * 8);
    }

    const __half* kbase  = qkv + ((size_t)b * SEQ) * N3 + DM + h * HD;
    const __half* vtbase = vwT + ((size_t)b * DM + h * HD) * SEQ;
    const int*    mbase  = vmask + b * SEQ;

    attn_prefetch((unsigned*)sm_dyn, kbase, vtbase, mbase, 0, tid);
    asm volatile("cp.async.commit_group;" ::: "memory");
    attn_prefetch((unsigned*)sm_dyn + STAGE_W, kbase, vtbase, mbase, 1, tid);
    asm volatile("cp.async.commit_group;" ::: "memory");

    float m[2][2], l[2][2];
#pragma unroll
    for (int mi = 0; mi < 2; mi++) {
        m[mi][0] = -1e30f; m[mi][1] = -1e30f;
        l[mi][0] = 0.0f;   l[mi][1] = 0.0f;
    }
    float o[2][8][4];
#pragma unroll
    for (int mi = 0; mi < 2; mi++)
#pragma unroll
        for (int nf = 0; nf < 8; nf++)
#pragma unroll
            for (int e = 0; e < 4; e++) o[mi][nf][e] = 0.0f;

    int st = 0;
    for (int kt = 0; kt < NT; kt++) {
        asm volatile("cp.async.wait_group 1;" ::: "memory");
        __syncthreads();
        if (kt + 2 < NT) {
            int j = st - 1; if (j < 0) j += NSTG;
            attn_prefetch((unsigned*)sm_dyn + j * STAGE_W,
                          kbase, vtbase, mbase, kt + 2, tid);
            asm volatile("cp.async.commit_group;" ::: "memory");
        } else {
            asm volatile("cp.async.commit_group;" ::: "memory");
        }
        const unsigned* Ks  = (const unsigned*)sm_dyn + st * STAGE_W;
        const unsigned* VTs = Ks + KTILE * AT_W;
        const int*      Mk  = (const int*)(VTs + KTILE * AT_W);
        if (++st == NSTG) st = 0;

        // ---- S = Q . K^T  (exp2-domain scores) ----
        float s[2][8][4];
#pragma unroll
        for (int mi = 0; mi < 2; mi++)
#pragma unroll
            for (int nf = 0; nf < 8; nf++)
#pragma unroll
                for (int e = 0; e < 4; e++) s[mi][nf][e] = 0.0f;

#pragma unroll
        for (int kf = 0; kf < 4; kf++) {
            unsigned a0[4], a1[4];
            a0[0] = Qs[(qrow0 + g)      * AT_W + kf * 8 + t];
            a0[1] = Qs[(qrow0 + g + 8)  * AT_W + kf * 8 + t];
            a0[2] = Qs[(qrow0 + g)      * AT_W + kf * 8 + t + 4];
            a0[3] = Qs[(qrow0 + g + 8)  * AT_W + kf * 8 + t + 4];
            a1[0] = Qs[(qrow0 + g + 16) * AT_W + kf * 8 + t];
            a1[1] = Qs[(qrow0 + g + 24) * AT_W + kf * 8 + t];
            a1[2] = Qs[(qrow0 + g + 16) * AT_W + kf * 8 + t + 4];
            a1[3] = Qs[(qrow0 + g + 24) * AT_W + kf * 8 + t + 4];
#pragma unroll
            for (int nf = 0; nf < 8; nf++) {
                unsigned bfr[2];
                bfr[0] = Ks[(nf * 8 + g) * AT_W + kf * 8 + t];
                bfr[1] = Ks[(nf * 8 + g) * AT_W + kf * 8 + t + 4];
                mma_f16(s[0][nf], a0, bfr);
                mma_f16(s[1][nf], a1, bfr);
            }
        }

        // ---- mask + online softmax (exp2 domain, f16x2 exp) ----
        unsigned p01[2][8], p23[2][8];
#pragma unroll
        for (int mi = 0; mi < 2; mi++) {
            float mx0 = -1e30f, mx1 = -1e30f;
#pragma unroll
            for (int nf = 0; nf < 8; nf++) {
                float pen0 = Mk[nf * 8 + 2 * t]     ? 0.0f : 1e12f;
                float pen1 = Mk[nf * 8 + 2 * t + 1] ? 0.0f : 1e12f;
                s[mi][nf][0] -= pen0; s[mi][nf][1] -= pen1;
                s[mi][nf][2] -= pen0; s[mi][nf][3] -= pen1;
                mx0 = fmaxf(mx0, fmaxf(s[mi][nf][0], s[mi][nf][1]));
                mx1 = fmaxf(mx1, fmaxf(s[mi][nf][2], s[mi][nf][3]));
            }
            mx0 = fmaxf(mx0, __shfl_xor_sync(0xffffffffu, mx0, 1));
            mx0 = fmaxf(mx0, __shfl_xor_sync(0xffffffffu, mx0, 2));
            mx1 = fmaxf(mx1, __shfl_xor_sync(0xffffffffu, mx1, 1));
            mx1 = fmaxf(mx1, __shfl_xor_sync(0xffffffffu, mx1, 2));
            float mn0 = fmaxf(m[mi][0], mx0), mn1 = fmaxf(m[mi][1], mx1);
            float al0 = ex2f(m[mi][0] - mn0), al1 = ex2f(m[mi][1] - mn1);
            m[mi][0] = mn0; m[mi][1] = mn1;
            float sum0 = 0.0f, sum1 = 0.0f;
#pragma unroll
            for (int nf = 0; nf < 8; nf++) {
                unsigned u01 = h2ex2(s[mi][nf][0] - mn0, s[mi][nf][1] - mn0);
                unsigned u23 = h2ex2(s[mi][nf][2] - mn1, s[mi][nf][3] - mn1);
                p01[mi][nf] = u01;
                p23[mi][nf] = u23;
                float2 f0 = h2_to_f2(u01);
                float2 f1 = h2_to_f2(u23);
                sum0 += f0.x + f0.y;
                sum1 += f1.x + f1.y;
            }
            sum0 += __shfl_xor_sync(0xffffffffu, sum0, 1);
            sum0 += __shfl_xor_sync(0xffffffffu, sum0, 2);
            sum1 += __shfl_xor_sync(0xffffffffu, sum1, 1);
            sum1 += __shfl_xor_sync(0xffffffffu, sum1, 2);
            l[mi][0] = l[mi][0] * al0 + sum0;
            l[mi][1] = l[mi][1] * al1 + sum1;
#pragma unroll
            for (int nf = 0; nf < 8; nf++) {
                o[mi][nf][0] *= al0; o[mi][nf][1] *= al0;
                o[mi][nf][2] *= al1; o[mi][nf][3] *= al1;
            }
        }

        // ---- O += P . V : A-frag is directly the fp16 exp output ----
#pragma unroll
        for (int kf = 0; kf < 4; kf++) {
            unsigned af[2][4];
#pragma unroll
            for (int mi = 0; mi < 2; mi++) {
                af[mi][0] = p01[mi][2 * kf];
                af[mi][1] = p23[mi][2 * kf];
                af[mi][2] = p01[mi][2 * kf + 1];
                af[mi][3] = p23[mi][2 * kf + 1];
            }
#pragma unroll
            for (int nf = 0; nf < 8; nf++) {
                unsigned bfr[2];
                bfr[0] = VTs[(nf * 8 + g) * AT_W + kf * 8 + t];
                bfr[1] = VTs[(nf * 8 + g) * AT_W + kf * 8 + t + 4];
                mma_f16(o[0][nf], af[0], bfr);
                mma_f16(o[1][nf], af[1], bfr);
            }
        }
    }

    // ---- normalize; write ctx fp16 [token][c] ----
    __half* obase = ctx + ((size_t)b * SEQ + qt * QROWS + qrow0) * DM + h * HD;
#pragma unroll
    for (int mi = 0; mi < 2; mi++) {
        float inv0 = 1.0f / l[mi][0], inv1 = 1.0f / l[mi][1];
        __half* ob = obase + (size_t)(mi * 16) * DM;
#pragma unroll
        for (int nf = 0; nf < 8; nf++) {
            int col = nf * 8 + 2 * t;
            *(__half2*)&ob[(size_t)g * DM + col] =
                __floats2half2_rn(o[mi][nf][0] * inv0, o[mi][nf][1] * inv0);
            *(__half2*)&ob[(size_t)(g + 8) * DM + col] =
                __floats2half2_rn(o[mi][nf][2] * inv1, o[mi][nf][3] * inv1);
        }
    }
}

// ---------------------------------------------------------------------------
extern "C" void kernel_launch(void* const* d_in, const int* in_sizes, int n_in,
                              void* d_out, int out_size)
{
    const float* q    = (const float*)d_in[0];
    const float* k    = (const float*)d_in[1];
    const float* v    = (const float*)d_in[2];
    const int*   mask = (const int*)  d_in[3];
    const float* Wq   = (const float*)d_in[4];
    const float* bq   = (const float*)d_in[5];
    const float* Wk   = (const float*)d_in[6];
    const float* bk   = (const float*)d_in[7];
    const float* Wv   = (const float*)d_in[8];
    const float* bv   = (const float*)d_in[9];
    const float* Wo   = (const float*)d_in[10];
    const float* bo   = (const float*)d_in[11];
    float* out = (float*)d_out;

    void *pin, *pwT, *pqkv, *pvwT, *pctx;
    cudaGetSymbolAddress(&pin,  g_inh);
    cudaGetSymbolAddress(&pwT,  g_wT);
    cudaGetSymbolAddress(&pqkv, g_qkv);
    cudaGetSymbolAddress(&pvwT, g_vwT);
    cudaGetSymbolAddress(&pctx, g_ctx);

    __half* inh = (__half*)pin;
    __half* wT  = (__half*)pwT;
    __half* qkv = (__half*)pqkv;
    __half* vwT = (__half*)pvwT;
    __half* ctx = (__half*)pctx;

    cudaFuncSetAttribute(gemm_qkv,
                         cudaFuncAttributeMaxDynamicSharedMemorySize, GEMM_SMEM);
    cudaFuncSetAttribute(gemm_out,
                         cudaFuncAttributeMaxDynamicSharedMemorySize, GEMM_SMEM);
    cudaFuncSetAttribute(attn_mma,
                         cudaFuncAttributeMaxDynamicSharedMemorySize, ATTN_SMEM);

    // 1) fused prepass: fp16 converts (z=3) + weight transposes (z=4)
    const int nBig = MROWS * DM / 4;
    to_f16_3<<<dim3(nBig / 256, 1, 3), 256>>>(
        (const float4*)q, (const float4*)k, (const float4*)v,
        (__half2*)inh, nBig);
    transp_w4<<<dim3(DM / 32, DM / 32, 4), dim3(32, 8)>>>(Wq, Wk, Wv, Wo, wT);

    // 2) grouped QKV projection (Q scaled by 0.125*log2e for exp2 softmax)
    gemm_qkv<<<dim3(DM / 128, MROWS / 128, 3), 256, GEMM_SMEM>>>(
        inh, wT, bq, bk, bv, qkv);

    // 2b) V^T per batch for PV B-operand adjacency
    transp_vw<<<dim3(SEQ / 64, DM / 64, NB), 256>>>(qkv, vwT);

    // 3) fused attention -> ctx (fp16)
    attn_mma<<<dim3(SEQ / QROWS, NH, NB), 256, ATTN_SMEM>>>(
        qkv, vwT, mask, ctx);

    // 4) output projection (fp32 out)
    gemm_out<<<dim3(DM / 128, MROWS / 128), 256, GEMM_SMEM>>>(
        ctx, wT + 3 * (size_t)DM * DM, bo, out);
}

// round 12
// speedup vs baseline: 2.0706x; 1.0064x over previous
#include <cuda_runtime.h>
#include <cuda_fp16.h>
#include <math.h>
#include <cstdint>

#define SEQ 2048
#define DM 1024
#define NH 16
#define HD 64
#define NB 2
#define MROWS (NB * SEQ)   // 4096
#define N3 (3 * DM)        // 3072 (qkv buffer width)

// Q projection pre-scaled by 0.125*log2(e): softmax runs in exp2 domain.
#define QSCALE 0.18033688011112042f

// Scratch (__device__ globals; allocation-free rule). fp16 payloads.
__device__ __half g_inh[3 * MROWS * DM];  // fp16(q|k|v) inputs, tensor-major
__device__ __half g_wT[4 * DM * DM];      // fp16(Wq^T|Wk^T|Wv^T|Wo^T) [N][K]
__device__ __half g_qkv[MROWS * N3];      // fp16 proj: [token][Q|K|.] (V seg unused)
__device__ __half g_vwT[NB * DM * SEQ];   // fp16(proj V)^T  [b][c][token]
__device__ __half g_ctx[MROWS * DM];      // fp16(attn out)  [token][c]

__device__ __forceinline__ void mma_f16(float c[4], const unsigned a[4],
                                        const unsigned b[2]) {
    asm volatile(
        "mma.sync.aligned.m16n8k16.row.col.f32.f16.f16.f32 "
        "{%0,%1,%2,%3}, {%4,%5,%6,%7}, {%8,%9}, {%0,%1,%2,%3};\n"
        : "+f"(c[0]), "+f"(c[1]), "+f"(c[2]), "+f"(c[3])
        : "r"(a[0]), "r"(a[1]), "r"(a[2]), "r"(a[3]), "r"(b[0]), "r"(b[1]));
}

__device__ __forceinline__ unsigned h2ex2(float lo, float hi) {
    __half2 d = __floats2half2_rn(lo, hi);
    unsigned x = *(unsigned*)&d, r;
    asm("ex2.approx.f16x2 %0, %1;" : "=r"(r) : "r"(x));
    return r;
}
__device__ __forceinline__ float ex2f(float x) {
    float r;
    asm("ex2.approx.f32 %0, %1;" : "=f"(r) : "f"(x));
    return r;
}
__device__ __forceinline__ float2 h2_to_f2(unsigned u) {
    __half2 h = *(__half2*)&u;
    return __half22float2(h);
}

__device__ __forceinline__ void cp_cg16(void* dst, const void* src) {
    unsigned u = (unsigned)__cvta_generic_to_shared(dst);
    asm volatile("cp.async.cg.shared.global [%0], [%1], 16;" :: "r"(u), "l"(src));
}

extern __shared__ float sm_dyn[];

// ---------------------------------------------------------------------------
// Fused prepass kernels.
// ---------------------------------------------------------------------------
__global__ __launch_bounds__(256) void to_f16_3(
    const float4* __restrict__ q, const float4* __restrict__ k,
    const float4* __restrict__ v, __half2* __restrict__ out, int n4)
{
    int i = blockIdx.x * 256 + threadIdx.x;
    const float4* in = (blockIdx.z == 0) ? q : (blockIdx.z == 1) ? k : v;
    __half2* o = out + (size_t)blockIdx.z * (2 * (size_t)n4);
    if (i < n4) {
        float4 x = in[i];
        o[2 * i]     = __floats2half2_rn(x.x, x.y);
        o[2 * i + 1] = __floats2half2_rn(x.z, x.w);
    }
}

__global__ __launch_bounds__(256) void transp_w4(
    const float* __restrict__ w0, const float* __restrict__ w1,
    const float* __restrict__ w2, const float* __restrict__ w3,
    __half* __restrict__ out)
{
    __shared__ float t[32][33];
    const float* in = (blockIdx.z == 0) ? w0 : (blockIdx.z == 1) ? w1
                    : (blockIdx.z == 2) ? w2 : w3;
    __half* o = out + (size_t)blockIdx.z * DM * DM;
    int tx = threadIdx.x, ty = threadIdx.y;           // 32 x 8
    int bx = blockIdx.x * 32, by = blockIdx.y * 32;
#pragma unroll
    for (int j = 0; j < 4; j++)
        t[ty + j * 8][tx] = in[(size_t)(by + ty + j * 8) * DM + bx + tx];
    __syncthreads();
#pragma unroll
    for (int j = 0; j < 4; j++)
        o[(size_t)(bx + ty + j * 8) * DM + by + tx] =
            __float2half_rn(t[tx][ty + j * 8]);
}

// ---------------------------------------------------------------------------
// GEMM tiles: 128x128 block, 256 threads, 8 warps x (64x32), m16n8k16,
// k-chunk 64 halves, 3-stage cp.async (wait_group 1), pitch 36 words.
// ---------------------------------------------------------------------------
#define GW 36
#define GEMM_STAGE (128 * GW)
#define GEMM_NSTG 3
#define GEMM_SMEM ((2 * GEMM_NSTG * GEMM_STAGE) * (int)sizeof(float))  // 110592

__device__ __forceinline__ void gemm_prefetch(
    unsigned* As, unsigned* Bs, const __half* A, const __half* WT,
    int K, int bm, int bn, int k0, int tid)
{
#pragma unroll
    for (int j = 0; j < 4; j++) {
        int idx = tid + j * 256;
        int row = idx >> 3;
        int c16 = idx & 7;
        cp_cg16(&As[row * GW + c16 * 4],
                A + (size_t)(bm + row) * K + k0 + c16 * 8);
        cp_cg16(&Bs[row * GW + c16 * 4],
                WT + (size_t)(bn + row) * K + k0 + c16 * 8);
    }
}

__device__ __forceinline__ void gemm_mainloop(
    float acc[4][4][4], const __half* A, const __half* WT,
    int K, int bm, int bn, int tid, int wm, int wn, int g, int t)
{
    unsigned* As0 = (unsigned*)sm_dyn;
    unsigned* Bs0 = As0 + GEMM_NSTG * GEMM_STAGE;

    gemm_prefetch(As0, Bs0, A, WT, K, bm, bn, 0, tid);
    asm volatile("cp.async.commit_group;" ::: "memory");
    gemm_prefetch(As0 + GEMM_STAGE, Bs0 + GEMM_STAGE, A, WT, K, bm, bn, 64, tid);
    asm volatile("cp.async.commit_group;" ::: "memory");

    const int NKI = K / 64;
    for (int i = 0; i < NKI; i++) {
        asm volatile("cp.async.wait_group 1;" ::: "memory");
        __syncthreads();
        int pf = i + 2;
        if (pf < NKI) {
            int j = pf % GEMM_NSTG;
            gemm_prefetch(As0 + j * GEMM_STAGE, Bs0 + j * GEMM_STAGE,
                          A, WT, K, bm, bn, pf * 64, tid);
        }
        asm volatile("cp.async.commit_group;" ::: "memory");
        const int st = i % GEMM_NSTG;
        const unsigned* As = As0 + st * GEMM_STAGE;
        const unsigned* Bs = Bs0 + st * GEMM_STAGE;

#pragma unroll
        for (int kf = 0; kf < 4; kf++) {
            unsigned af[4][4], bf[4][2];
#pragma unroll
            for (int mi = 0; mi < 4; mi++) {
                int r = wm + mi * 16;
                af[mi][0] = As[(r + g)     * GW + kf * 8 + t];
                af[mi][1] = As[(r + g + 8) * GW + kf * 8 + t];
                af[mi][2] = As[(r + g)     * GW + kf * 8 + t + 4];
                af[mi][3] = As[(r + g + 8) * GW + kf * 8 + t + 4];
            }
#pragma unroll
            for (int ni = 0; ni < 4; ni++) {
                int c = wn + ni * 8;
                bf[ni][0] = Bs[(c + g) * GW + kf * 8 + t];
                bf[ni][1] = Bs[(c + g) * GW + kf * 8 + t + 4];
            }
#pragma unroll
            for (int mi = 0; mi < 4; mi++)
#pragma unroll
                for (int ni = 0; ni < 4; ni++)
                    mma_f16(acc[mi][ni], af[mi], bf[ni]);
        }
    }
}

// Grouped QKV projection. z=0: Q (scaled) -> qkv seg 0; z=1: K -> qkv seg 1;
// z=2: V -> written TRANSPOSED directly to vwT[b][c][tok] via smem restage.
__global__ __launch_bounds__(256, 2) void gemm_qkv(
    const __half* __restrict__ inh, const __half* __restrict__ wT,
    const float* __restrict__ bq, const float* __restrict__ bk,
    const float* __restrict__ bv, __half* __restrict__ qkv,
    __half* __restrict__ vwT)
{
    const int tid  = threadIdx.x;
    const int lane = tid & 31;
    const int warp = tid >> 5;
    const int g = lane >> 2, t = lane & 3;
    const int wm = (warp >> 2) * 64;
    const int wn = (warp & 3) * 32;
    const int bm = blockIdx.y * 128;
    const int bn = blockIdx.x * 128;
    const int z  = blockIdx.z;

    const __half* A  = inh + (size_t)z * MROWS * DM;
    const __half* WT = wT  + (size_t)z * DM * DM;
    const float* bias = (z == 0) ? bq : (z == 1) ? bk : bv;
    const float sc = (z == 0) ? QSCALE : 1.0f;

    float acc[4][4][4];
#pragma unroll
    for (int mi = 0; mi < 4; mi++)
#pragma unroll
        for (int ni = 0; ni < 4; ni++)
#pragma unroll
            for (int e = 0; e < 4; e++) acc[mi][ni][e] = 0.0f;

    gemm_mainloop(acc, A, WT, DM, bm, bn, tid, wm, wn, g, t);

    if (z < 2) {
#pragma unroll
        for (int mi = 0; mi < 4; mi++) {
            int r0 = bm + wm + mi * 16 + g;
#pragma unroll
            for (int ni = 0; ni < 4; ni++) {
                int cb = bn + wn + ni * 8 + 2 * t;
                float b0 = bias[cb], b1 = bias[cb + 1];
                float x00 = (acc[mi][ni][0] + b0) * sc;
                float x01 = (acc[mi][ni][1] + b1) * sc;
                float x10 = (acc[mi][ni][2] + b0) * sc;
                float x11 = (acc[mi][ni][3] + b1) * sc;
                __half* c0p = qkv + (size_t)r0 * N3 + z * DM + cb;
                *(__half2*)c0p = __floats2half2_rn(x00, x01);
                *(__half2*)(c0p + (size_t)8 * N3) = __floats2half2_rn(x10, x11);
            }
        }
    } else {
        // V: restage transposed through smem, write vwT[b][c][tok].
        __syncthreads();           // all warps done reading mainloop smem
        __half* ts = (__half*)sm_dyn;   // [128 c][136 tok-pitch] halves
#pragma unroll
        for (int mi = 0; mi < 4; mi++) {
            int tokl = wm + mi * 16 + g;
#pragma unroll
            for (int ni = 0; ni < 4; ni++) {
                int cl = wn + ni * 8 + 2 * t;
                float b0 = bias[bn + cl], b1 = bias[bn + cl + 1];
                ts[cl * 136 + tokl]           = __float2half_rn(acc[mi][ni][0] + b0);
                ts[(cl + 1) * 136 + tokl]     = __float2half_rn(acc[mi][ni][1] + b1);
                ts[cl * 136 + tokl + 8]       = __float2half_rn(acc[mi][ni][2] + b0);
                ts[(cl + 1) * 136 + tokl + 8] = __float2half_rn(acc[mi][ni][3] + b1);
            }
        }
        __syncthreads();
        const int b = bm >> 11;
        const int tok0 = bm & 2047;
#pragma unroll
        for (int it = 0; it < 8; it++) {
            int idx = tid + it * 256;
            int cl = idx >> 4;
            int tk = (idx & 15) * 8;
            uint4 y = *(const uint4*)&ts[cl * 136 + tk];
            *(uint4*)&vwT[((size_t)b * DM + bn + cl) * SEQ + tok0 + tk] = y;
        }
    }
}

// Output projection: C(fp32) = ctx(fp16) @ Wo + bo.
__global__ __launch_bounds__(256, 2) void gemm_out(
    const __half* __restrict__ A, const __half* __restrict__ WT,
    const float* __restrict__ bias, float* __restrict__ C)
{
    const int tid  = threadIdx.x;
    const int lane = tid & 31;
    const int warp = tid >> 5;
    const int g = lane >> 2, t = lane & 3;
    const int wm = (warp >> 2) * 64;
    const int wn = (warp & 3) * 32;
    const int bm = blockIdx.y * 128;
    const int bn = blockIdx.x * 128;

    float acc[4][4][4];
#pragma unroll
    for (int mi = 0; mi < 4; mi++)
#pragma unroll
        for (int ni = 0; ni < 4; ni++)
#pragma unroll
            for (int e = 0; e < 4; e++) acc[mi][ni][e] = 0.0f;

    gemm_mainloop(acc, A, WT, DM, bm, bn, tid, wm, wn, g, t);

#pragma unroll
    for (int mi = 0; mi < 4; mi++) {
        int r0 = bm + wm + mi * 16 + g;
#pragma unroll
        for (int ni = 0; ni < 4; ni++) {
            int cb = bn + wn + ni * 8 + 2 * t;
            float b0 = bias[cb], b1 = bias[cb + 1];
            *(float2*)&C[(size_t)r0 * DM + cb] =
                make_float2(acc[mi][ni][0] + b0, acc[mi][ni][1] + b1);
            *(float2*)&C[(size_t)(r0 + 8) * DM + cb] =
                make_float2(acc[mi][ni][2] + b0, acc[mi][ni][3] + b1);
        }
    }
}

// ---------------------------------------------------------------------------
// Flash-attention, fp16 mma, exp2-domain softmax with ex2.approx.f16x2.
// 256 threads / 8 warps, QROWS=256, KTILE=64, 3-stage cp.async.
// ---------------------------------------------------------------------------
#define QROWS 256
#define KTILE 64
#define NT (SEQ / KTILE)
#define NSTG 3
#define AT_W 36
#define STAGE_W (KTILE * AT_W * 2 + 64)
#define QS_W (QROWS * AT_W)
#define ATTN_SMEM ((NSTG * STAGE_W + QS_W) * (int)sizeof(float))

__device__ __forceinline__ void attn_prefetch(
    unsigned* stage, const __half* kb, const __half* vtb, const int* mb,
    int kt, int tid)
{
    unsigned* Ks  = stage;
    unsigned* VTs = stage + KTILE * AT_W;
    unsigned* Mk  = VTs + KTILE * AT_W;
#pragma unroll
    for (int j = 0; j < 2; j++) {
        int idx = tid + j * 256;
        int row = idx >> 3;
        int c16 = idx & 7;
        cp_cg16(&Ks[row * AT_W + c16 * 4],
                kb + (size_t)(kt * KTILE + row) * N3 + c16 * 8);
        cp_cg16(&VTs[row * AT_W + c16 * 4],
                vtb + (size_t)row * SEQ + kt * KTILE + c16 * 8);
    }
    if (tid < 16) cp_cg16(&Mk[tid * 4], mb + kt * KTILE + tid * 4);
}

__global__ __launch_bounds__(256) void attn_mma(
    const __half* __restrict__ qkv, const __half* __restrict__ vwT,
    const int* __restrict__ vmask, __half* __restrict__ ctx)
{
    const int tid  = threadIdx.x;
    const int lane = tid & 31;
    const int warp = tid >> 5;
    const int g = lane >> 2, t = lane & 3;
    const int qrow0 = warp * 32;
    const int qt = blockIdx.x, h = blockIdx.y, b = blockIdx.z;

    unsigned* Qs = (unsigned*)(sm_dyn + NSTG * STAGE_W);

    const __half* qb = qkv + ((size_t)b * SEQ + qt * QROWS) * N3 + h * HD;
#pragma unroll
    for (int j = 0; j < 8; j++) {
        int idx = tid + j * 256;
        int row = idx >> 3, c16 = idx & 7;
        cp_cg16(&Qs[row * AT_W + c16 * 4], qb + (size_t)row * N3 + c16 * 8);
    }

    const __half* kbase  = qkv + ((size_t)b * SEQ) * N3 + DM + h * HD;
    const __half* vtbase = vwT + ((size_t)b * DM + h * HD) * SEQ;
    const int*    mbase  = vmask + b * SEQ;

    attn_prefetch((unsigned*)sm_dyn, kbase, vtbase, mbase, 0, tid);
    asm volatile("cp.async.commit_group;" ::: "memory");
    attn_prefetch((unsigned*)sm_dyn + STAGE_W, kbase, vtbase, mbase, 1, tid);
    asm volatile("cp.async.commit_group;" ::: "memory");

    float m[2][2], l[2][2];
#pragma unroll
    for (int mi = 0; mi < 2; mi++) {
        m[mi][0] = -1e30f; m[mi][1] = -1e30f;
        l[mi][0] = 0.0f;   l[mi][1] = 0.0f;
    }
    float o[2][8][4];
#pragma unroll
    for (int mi = 0; mi < 2; mi++)
#pragma unroll
        for (int nf = 0; nf < 8; nf++)
#pragma unroll
            for (int e = 0; e < 4; e++) o[mi][nf][e] = 0.0f;

    int st = 0;
    for (int kt = 0; kt < NT; kt++) {
        asm volatile("cp.async.wait_group 1;" ::: "memory");
        __syncthreads();
        if (kt + 2 < NT) {
            int j = st - 1; if (j < 0) j += NSTG;
            attn_prefetch((unsigned*)sm_dyn + j * STAGE_W,
                          kbase, vtbase, mbase, kt + 2, tid);
            asm volatile("cp.async.commit_group;" ::: "memory");
        } else {
            asm volatile("cp.async.commit_group;" ::: "memory");
        }
        const unsigned* Ks  = (const unsigned*)sm_dyn + st * STAGE_W;
        const unsigned* VTs = Ks + KTILE * AT_W;
        const int*      Mk  = (const int*)(VTs + KTILE * AT_W);
        if (++st == NSTG) st = 0;

        // ---- S = Q . K^T  (exp2-domain scores) ----
        float s[2][8][4];
#pragma unroll
        for (int mi = 0; mi < 2; mi++)
#pragma unroll
            for (int nf = 0; nf < 8; nf++)
#pragma unroll
                for (int e = 0; e < 4; e++) s[mi][nf][e] = 0.0f;

#pragma unroll
        for (int kf = 0; kf < 4; kf++) {
            unsigned a0[4], a1[4];
            a0[0] = Qs[(qrow0 + g)      * AT_W + kf * 8 + t];
            a0[1] = Qs[(qrow0 + g + 8)  * AT_W + kf * 8 + t];
            a0[2] = Qs[(qrow0 + g)      * AT_W + kf * 8 + t + 4];
            a0[3] = Qs[(qrow0 + g + 8)  * AT_W + kf * 8 + t + 4];
            a1[0] = Qs[(qrow0 + g + 16) * AT_W + kf * 8 + t];
            a1[1] = Qs[(qrow0 + g + 24) * AT_W + kf * 8 + t];
            a1[2] = Qs[(qrow0 + g + 16) * AT_W + kf * 8 + t + 4];
            a1[3] = Qs[(qrow0 + g + 24) * AT_W + kf * 8 + t + 4];
#pragma unroll
            for (int nf = 0; nf < 8; nf++) {
                unsigned bfr[2];
                bfr[0] = Ks[(nf * 8 + g) * AT_W + kf * 8 + t];
                bfr[1] = Ks[(nf * 8 + g) * AT_W + kf * 8 + t + 4];
                mma_f16(s[0][nf], a0, bfr);
                mma_f16(s[1][nf], a1, bfr);
            }
        }

        // ---- mask + online softmax (exp2 domain, f16x2 exp) ----
        unsigned p01[2][8], p23[2][8];
#pragma unroll
        for (int mi = 0; mi < 2; mi++) {
            float mx0 = -1e30f, mx1 = -1e30f;
#pragma unroll
            for (int nf = 0; nf < 8; nf++) {
                float pen0 = Mk[nf * 8 + 2 * t]     ? 0.0f : 1e12f;
                float pen1 = Mk[nf * 8 + 2 * t + 1] ? 0.0f : 1e12f;
                s[mi][nf][0] -= pen0; s[mi][nf][1] -= pen1;
                s[mi][nf][2] -= pen0; s[mi][nf][3] -= pen1;
                mx0 = fmaxf(mx0, fmaxf(s[mi][nf][0], s[mi][nf][1]));
                mx1 = fmaxf(mx1, fmaxf(s[mi][nf][2], s[mi][nf][3]));
            }
            mx0 = fmaxf(mx0, __shfl_xor_sync(0xffffffffu, mx0, 1));
            mx0 = fmaxf(mx0, __shfl_xor_sync(0xffffffffu, mx0, 2));
            mx1 = fmaxf(mx1, __shfl_xor_sync(0xffffffffu, mx1, 1));
            mx1 = fmaxf(mx1, __shfl_xor_sync(0xffffffffu, mx1, 2));
            float mn0 = fmaxf(m[mi][0], mx0), mn1 = fmaxf(m[mi][1], mx1);
            float al0 = ex2f(m[mi][0] - mn0), al1 = ex2f(m[mi][1] - mn1);
            m[mi][0] = mn0; m[mi][1] = mn1;
            float sum0 = 0.0f, sum1 = 0.0f;
#pragma unroll
            for (int nf = 0; nf < 8; nf++) {
                unsigned u01 = h2ex2(s[mi][nf][0] - mn0, s[mi][nf][1] - mn0);
                unsigned u23 = h2ex2(s[mi][nf][2] - mn1, s[mi][nf][3] - mn1);
                p01[mi][nf] = u01;
                p23[mi][nf] = u23;
                float2 f0 = h2_to_f2(u01);
                float2 f1 = h2_to_f2(u23);
                sum0 += f0.x + f0.y;
                sum1 += f1.x + f1.y;
            }
            sum0 += __shfl_xor_sync(0xffffffffu, sum0, 1);
            sum0 += __shfl_xor_sync(0xffffffffu, sum0, 2);
            sum1 += __shfl_xor_sync(0xffffffffu, sum1, 1);
            sum1 += __shfl_xor_sync(0xffffffffu, sum1, 2);
            l[mi][0] = l[mi][0] * al0 + sum0;
            l[mi][1] = l[mi][1] * al1 + sum1;
#pragma unroll
            for (int nf = 0; nf < 8; nf++) {
                o[mi][nf][0] *= al0; o[mi][nf][1] *= al0;
                o[mi][nf][2] *= al1; o[mi][nf][3] *= al1;
            }
        }

        // ---- O += P . V : A-frag is directly the fp16 exp output ----
#pragma unroll
        for (int kf = 0; kf < 4; kf++) {
            unsigned af[2][4];
#pragma unroll
            for (int mi = 0; mi < 2; mi++) {
                af[mi][0] = p01[mi][2 * kf];
                af[mi][1] = p23[mi][2 * kf];
                af[mi][2] = p01[mi][2 * kf + 1];
                af[mi][3] = p23[mi][2 * kf + 1];
            }
#pragma unroll
            for (int nf = 0; nf < 8; nf++) {
                unsigned bfr[2];
                bfr[0] = VTs[(nf * 8 + g) * AT_W + kf * 8 + t];
                bfr[1] = VTs[(nf * 8 + g) * AT_W + kf * 8 + t + 4];
                mma_f16(o[0][nf], af[0], bfr);
                mma_f16(o[1][nf], af[1], bfr);
            }
        }
    }

    // ---- normalize; write ctx fp16 [token][c] ----
    __half* obase = ctx + ((size_t)b * SEQ + qt * QROWS + qrow0) * DM + h * HD;
#pragma unroll
    for (int mi = 0; mi < 2; mi++) {
        float inv0 = 1.0f / l[mi][0], inv1 = 1.0f / l[mi][1];
        __half* ob = obase + (size_t)(mi * 16) * DM;
#pragma unroll
        for (int nf = 0; nf < 8; nf++) {
            int col = nf * 8 + 2 * t;
            *(__half2*)&ob[(size_t)g * DM + col] =
                __floats2half2_rn(o[mi][nf][0] * inv0, o[mi][nf][1] * inv0);
            *(__half2*)&ob[(size_t)(g + 8) * DM + col] =
                __floats2half2_rn(o[mi][nf][2] * inv1, o[mi][nf][3] * inv1);
        }
    }
}

// ---------------------------------------------------------------------------
extern "C" void kernel_launch(void* const* d_in, const int* in_sizes, int n_in,
                              void* d_out, int out_size)
{
    const float* q    = (const float*)d_in[0];
    const float* k    = (const float*)d_in[1];
    const float* v    = (const float*)d_in[2];
    const int*   mask = (const int*)  d_in[3];
    const float* Wq   = (const float*)d_in[4];
    const float* bq   = (const float*)d_in[5];
    const float* Wk   = (const float*)d_in[6];
    const float* bk   = (const float*)d_in[7];
    const float* Wv   = (const float*)d_in[8];
    const float* bv   = (const float*)d_in[9];
    const float* Wo   = (const float*)d_in[10];
    const float* bo   = (const float*)d_in[11];
    float* out = (float*)d_out;

    void *pin, *pwT, *pqkv, *pvwT, *pctx;
    cudaGetSymbolAddress(&pin,  g_inh);
    cudaGetSymbolAddress(&pwT,  g_wT);
    cudaGetSymbolAddress(&pqkv, g_qkv);
    cudaGetSymbolAddress(&pvwT, g_vwT);
    cudaGetSymbolAddress(&pctx, g_ctx);

    __half* inh = (__half*)pin;
    __half* wT  = (__half*)pwT;
    __half* qkv = (__half*)pqkv;
    __half* vwT = (__half*)pvwT;
    __half* ctx = (__half*)pctx;

    cudaFuncSetAttribute(gemm_qkv,
                         cudaFuncAttributeMaxDynamicSharedMemorySize, GEMM_SMEM);
    cudaFuncSetAttribute(gemm_out,
                         cudaFuncAttributeMaxDynamicSharedMemorySize, GEMM_SMEM);
    cudaFuncSetAttribute(attn_mma,
                         cudaFuncAttributeMaxDynamicSharedMemorySize, ATTN_SMEM);

    // 1) fused prepass: fp16 converts (z=3) + weight transposes (z=4)
    const int nBig = MROWS * DM / 4;
    to_f16_3<<<dim3(nBig / 256, 1, 3), 256>>>(
        (const float4*)q, (const float4*)k, (const float4*)v,
        (__half2*)inh, nBig);
    transp_w4<<<dim3(DM / 32, DM / 32, 4), dim3(32, 8)>>>(Wq, Wk, Wv, Wo, wT);

    // 2) grouped QKV projection; z==2 writes V transposed straight to vwT
    gemm_qkv<<<dim3(DM / 128, MROWS / 128, 3), 256, GEMM_SMEM>>>(
        inh, wT, bq, bk, bv, qkv, vwT);

    // 3) fused attention -> ctx (fp16)
    attn_mma<<<dim3(SEQ / QROWS, NH, NB), 256, ATTN_SMEM>>>(
        qkv, vwT, mask, ctx);

    // 4) output projection (fp32 out)
    gemm_out<<<dim3(DM / 128, MROWS / 128), 256, GEMM_SMEM>>>(
        ctx, wT + 3 * (size_t)DM * DM, bo, out);
}

// round 13
// speedup vs baseline: 2.1392x; 1.0331x over previous
#include <cuda_runtime.h>
#include <cuda_fp16.h>
#include <math.h>
#include <cstdint>

#define SEQ 2048
#define DM 1024
#define NH 16
#define HD 64
#define NB 2
#define MROWS (NB * SEQ)   // 4096
#define N3 (3 * DM)        // 3072 (qkv buffer width)

// Q projection pre-scaled by 0.125*log2(e): softmax runs in exp2 domain.
#define QSCALE 0.18033688011112042f

// Scratch (__device__ globals; allocation-free rule). fp16 payloads.
__device__ __half g_inh[3 * MROWS * DM];  // fp16(q|k|v) inputs, tensor-major
__device__ __half g_wT[4 * DM * DM];      // fp16(Wq^T|Wk^T|Wv^T|Wo^T) [N][K]
__device__ __half g_qkv[MROWS * N3];      // fp16 proj: [token][Q|K|.] (V seg unused)
__device__ __half g_vwT[NB * DM * SEQ];   // fp16(proj V)^T  [b][c][token]
__device__ __half g_ctx[MROWS * DM];      // fp16(attn out)  [token][c]

__device__ __forceinline__ void mma_f16(float c[4], const unsigned a[4],
                                        const unsigned b[2]) {
    asm volatile(
        "mma.sync.aligned.m16n8k16.row.col.f32.f16.f16.f32 "
        "{%0,%1,%2,%3}, {%4,%5,%6,%7}, {%8,%9}, {%0,%1,%2,%3};\n"
        : "+f"(c[0]), "+f"(c[1]), "+f"(c[2]), "+f"(c[3])
        : "r"(a[0]), "r"(a[1]), "r"(a[2]), "r"(a[3]), "r"(b[0]), "r"(b[1]));
}

__device__ __forceinline__ unsigned h2ex2(float lo, float hi) {
    __half2 d = __floats2half2_rn(lo, hi);
    unsigned x = *(unsigned*)&d, r;
    asm("ex2.approx.f16x2 %0, %1;" : "=r"(r) : "r"(x));
    return r;
}
__device__ __forceinline__ float ex2f(float x) {
    float r;
    asm("ex2.approx.f32 %0, %1;" : "=f"(r) : "f"(x));
    return r;
}
__device__ __forceinline__ float2 h2_to_f2(unsigned u) {
    __half2 h = *(__half2*)&u;
    return __half22float2(h);
}

__device__ __forceinline__ void cp_cg16(void* dst, const void* src) {
    unsigned u = (unsigned)__cvta_generic_to_shared(dst);
    asm volatile("cp.async.cg.shared.global [%0], [%1], 16;" :: "r"(u), "l"(src));
}

extern __shared__ float sm_dyn[];

// ---------------------------------------------------------------------------
// Fused prepass kernels.
// ---------------------------------------------------------------------------
__global__ __launch_bounds__(256) void to_f16_3(
    const float4* __restrict__ q, const float4* __restrict__ k,
    const float4* __restrict__ v, __half2* __restrict__ out, int n4)
{
    int i = blockIdx.x * 256 + threadIdx.x;
    const float4* in = (blockIdx.z == 0) ? q : (blockIdx.z == 1) ? k : v;
    __half2* o = out + (size_t)blockIdx.z * (2 * (size_t)n4);
    if (i < n4) {
        float4 x = in[i];
        o[2 * i]     = __floats2half2_rn(x.x, x.y);
        o[2 * i + 1] = __floats2half2_rn(x.z, x.w);
    }
}

__global__ __launch_bounds__(256) void transp_w4(
    const float* __restrict__ w0, const float* __restrict__ w1,
    const float* __restrict__ w2, const float* __restrict__ w3,
    __half* __restrict__ out)
{
    __shared__ float t[32][33];
    const float* in = (blockIdx.z == 0) ? w0 : (blockIdx.z == 1) ? w1
                    : (blockIdx.z == 2) ? w2 : w3;
    __half* o = out + (size_t)blockIdx.z * DM * DM;
    int tx = threadIdx.x, ty = threadIdx.y;           // 32 x 8
    int bx = blockIdx.x * 32, by = blockIdx.y * 32;
#pragma unroll
    for (int j = 0; j < 4; j++)
        t[ty + j * 8][tx] = in[(size_t)(by + ty + j * 8) * DM + bx + tx];
    __syncthreads();
#pragma unroll
    for (int j = 0; j < 4; j++)
        o[(size_t)(bx + ty + j * 8) * DM + by + tx] =
            __float2half_rn(t[tx][ty + j * 8]);
}

// ---------------------------------------------------------------------------
// GEMM tiles: 128x128 block, 256 threads, 8 warps x (64x32), m16n8k16,
// k-chunk 64 halves, 3-stage cp.async (wait_group 1), pitch 36 words.
// ---------------------------------------------------------------------------
#define GW 36
#define GEMM_STAGE (128 * GW)
#define GEMM_NSTG 3
#define GEMM_SMEM ((2 * GEMM_NSTG * GEMM_STAGE) * (int)sizeof(float))  // 110592

__device__ __forceinline__ void gemm_prefetch(
    unsigned* As, unsigned* Bs, const __half* A, const __half* WT,
    int K, int bm, int bn, int k0, int tid)
{
#pragma unroll
    for (int j = 0; j < 4; j++) {
        int idx = tid + j * 256;
        int row = idx >> 3;
        int c16 = idx & 7;
        cp_cg16(&As[row * GW + c16 * 4],
                A + (size_t)(bm + row) * K + k0 + c16 * 8);
        cp_cg16(&Bs[row * GW + c16 * 4],
                WT + (size_t)(bn + row) * K + k0 + c16 * 8);
    }
}

__device__ __forceinline__ void gemm_mainloop(
    float acc[4][4][4], const __half* A, const __half* WT,
    int K, int bm, int bn, int tid, int wm, int wn, int g, int t)
{
    unsigned* As0 = (unsigned*)sm_dyn;
    unsigned* Bs0 = As0 + GEMM_NSTG * GEMM_STAGE;

    gemm_prefetch(As0, Bs0, A, WT, K, bm, bn, 0, tid);
    asm volatile("cp.async.commit_group;" ::: "memory");
    gemm_prefetch(As0 + GEMM_STAGE, Bs0 + GEMM_STAGE, A, WT, K, bm, bn, 64, tid);
    asm volatile("cp.async.commit_group;" ::: "memory");

    const int NKI = K / 64;
    for (int i = 0; i < NKI; i++) {
        asm volatile("cp.async.wait_group 1;" ::: "memory");
        __syncthreads();
        int pf = i + 2;
        if (pf < NKI) {
            int j = pf % GEMM_NSTG;
            gemm_prefetch(As0 + j * GEMM_STAGE, Bs0 + j * GEMM_STAGE,
                          A, WT, K, bm, bn, pf * 64, tid);
        }
        asm volatile("cp.async.commit_group;" ::: "memory");
        const int st = i % GEMM_NSTG;
        const unsigned* As = As0 + st * GEMM_STAGE;
        const unsigned* Bs = Bs0 + st * GEMM_STAGE;

#pragma unroll
        for (int kf = 0; kf < 4; kf++) {
            unsigned af[4][4], bf[4][2];
#pragma unroll
            for (int mi = 0; mi < 4; mi++) {
                int r = wm + mi * 16;
                af[mi][0] = As[(r + g)     * GW + kf * 8 + t];
                af[mi][1] = As[(r + g + 8) * GW + kf * 8 + t];
                af[mi][2] = As[(r + g)     * GW + kf * 8 + t + 4];
                af[mi][3] = As[(r + g + 8) * GW + kf * 8 + t + 4];
            }
#pragma unroll
            for (int ni = 0; ni < 4; ni++) {
                int c = wn + ni * 8;
                bf[ni][0] = Bs[(c + g) * GW + kf * 8 + t];
                bf[ni][1] = Bs[(c + g) * GW + kf * 8 + t + 4];
            }
#pragma unroll
            for (int mi = 0; mi < 4; mi++)
#pragma unroll
                for (int ni = 0; ni < 4; ni++)
                    mma_f16(acc[mi][ni], af[mi], bf[ni]);
        }
    }
}

// Grouped QKV projection. z=0: Q (scaled) -> qkv seg 0; z=1: K -> qkv seg 1;
// z=2: V -> written TRANSPOSED directly to vwT[b][c][tok] via smem restage.
__global__ __launch_bounds__(256, 2) void gemm_qkv(
    const __half* __restrict__ inh, const __half* __restrict__ wT,
    const float* __restrict__ bq, const float* __restrict__ bk,
    const float* __restrict__ bv, __half* __restrict__ qkv,
    __half* __restrict__ vwT)
{
    const int tid  = threadIdx.x;
    const int lane = tid & 31;
    const int warp = tid >> 5;
    const int g = lane >> 2, t = lane & 3;
    const int wm = (warp >> 2) * 64;
    const int wn = (warp & 3) * 32;
    const int bm = blockIdx.y * 128;
    const int bn = blockIdx.x * 128;
    const int z  = blockIdx.z;

    const __half* A  = inh + (size_t)z * MROWS * DM;
    const __half* WT = wT  + (size_t)z * DM * DM;
    const float* bias = (z == 0) ? bq : (z == 1) ? bk : bv;
    const float sc = (z == 0) ? QSCALE : 1.0f;

    float acc[4][4][4];
#pragma unroll
    for (int mi = 0; mi < 4; mi++)
#pragma unroll
        for (int ni = 0; ni < 4; ni++)
#pragma unroll
            for (int e = 0; e < 4; e++) acc[mi][ni][e] = 0.0f;

    gemm_mainloop(acc, A, WT, DM, bm, bn, tid, wm, wn, g, t);

    if (z < 2) {
#pragma unroll
        for (int mi = 0; mi < 4; mi++) {
            int r0 = bm + wm + mi * 16 + g;
#pragma unroll
            for (int ni = 0; ni < 4; ni++) {
                int cb = bn + wn + ni * 8 + 2 * t;
                float b0 = bias[cb], b1 = bias[cb + 1];
                float x00 = (acc[mi][ni][0] + b0) * sc;
                float x01 = (acc[mi][ni][1] + b1) * sc;
                float x10 = (acc[mi][ni][2] + b0) * sc;
                float x11 = (acc[mi][ni][3] + b1) * sc;
                __half* c0p = qkv + (size_t)r0 * N3 + z * DM + cb;
                *(__half2*)c0p = __floats2half2_rn(x00, x01);
                *(__half2*)(c0p + (size_t)8 * N3) = __floats2half2_rn(x10, x11);
            }
        }
    } else {
        // V: restage transposed through smem, write vwT[b][c][tok].
        __syncthreads();           // all warps done reading mainloop smem
        __half* ts = (__half*)sm_dyn;   // [128 c][136 tok-pitch] halves
#pragma unroll
        for (int mi = 0; mi < 4; mi++) {
            int tokl = wm + mi * 16 + g;
#pragma unroll
            for (int ni = 0; ni < 4; ni++) {
                int cl = wn + ni * 8 + 2 * t;
                float b0 = bias[bn + cl], b1 = bias[bn + cl + 1];
                ts[cl * 136 + tokl]           = __float2half_rn(acc[mi][ni][0] + b0);
                ts[(cl + 1) * 136 + tokl]     = __float2half_rn(acc[mi][ni][1] + b1);
                ts[cl * 136 + tokl + 8]       = __float2half_rn(acc[mi][ni][2] + b0);
                ts[(cl + 1) * 136 + tokl + 8] = __float2half_rn(acc[mi][ni][3] + b1);
            }
        }
        __syncthreads();
        const int b = bm >> 11;
        const int tok0 = bm & 2047;
#pragma unroll
        for (int it = 0; it < 8; it++) {
            int idx = tid + it * 256;
            int cl = idx >> 4;
            int tk = (idx & 15) * 8;
            uint4 y = *(const uint4*)&ts[cl * 136 + tk];
            *(uint4*)&vwT[((size_t)b * DM + bn + cl) * SEQ + tok0 + tk] = y;
        }
    }
}

// Output projection: C(fp32) = ctx(fp16) @ Wo + bo.
__global__ __launch_bounds__(256, 2) void gemm_out(
    const __half* __restrict__ A, const __half* __restrict__ WT,
    const float* __restrict__ bias, float* __restrict__ C)
{
    const int tid  = threadIdx.x;
    const int lane = tid & 31;
    const int warp = tid >> 5;
    const int g = lane >> 2, t = lane & 3;
    const int wm = (warp >> 2) * 64;
    const int wn = (warp & 3) * 32;
    const int bm = blockIdx.y * 128;
    const int bn = blockIdx.x * 128;

    float acc[4][4][4];
#pragma unroll
    for (int mi = 0; mi < 4; mi++)
#pragma unroll
        for (int ni = 0; ni < 4; ni++)
#pragma unroll
            for (int e = 0; e < 4; e++) acc[mi][ni][e] = 0.0f;

    gemm_mainloop(acc, A, WT, DM, bm, bn, tid, wm, wn, g, t);

#pragma unroll
    for (int mi = 0; mi < 4; mi++) {
        int r0 = bm + wm + mi * 16 + g;
#pragma unroll
        for (int ni = 0; ni < 4; ni++) {
            int cb = bn + wn + ni * 8 + 2 * t;
            float b0 = bias[cb], b1 = bias[cb + 1];
            *(float2*)&C[(size_t)r0 * DM + cb] =
                make_float2(acc[mi][ni][0] + b0, acc[mi][ni][1] + b1);
            *(float2*)&C[(size_t)(r0 + 8) * DM + cb] =
                make_float2(acc[mi][ni][2] + b0, acc[mi][ni][3] + b1);
        }
    }
}

// ---------------------------------------------------------------------------
// Flash-attention, fp16 mma, exp2-domain softmax with ex2.approx.f16x2.
// 128 threads / 4 warps, QROWS=128 (32 rows/warp, mi=2 B-frag sharing).
// 3 CTAs/SM (launch_bounds(128,3); smem 74.5KB x3 = 223.5KB) -> 12 warps/SM.
// ---------------------------------------------------------------------------
#define QROWS 128
#define KTILE 64
#define NT (SEQ / KTILE)
#define NSTG 3
#define AT_W 36
#define STAGE_W (KTILE * AT_W * 2 + 64)
#define QS_W (QROWS * AT_W)
#define ATTN_SMEM ((NSTG * STAGE_W + QS_W) * (int)sizeof(float))  // 74496

__device__ __forceinline__ void attn_prefetch(
    unsigned* stage, const __half* kb, const __half* vtb, const int* mb,
    int kt, int tid)
{
    unsigned* Ks  = stage;
    unsigned* VTs = stage + KTILE * AT_W;
    unsigned* Mk  = VTs + KTILE * AT_W;
#pragma unroll
    for (int j = 0; j < 4; j++) {
        int idx = tid + j * 128;
        int row = idx >> 3;
        int c16 = idx & 7;
        cp_cg16(&Ks[row * AT_W + c16 * 4],
                kb + (size_t)(kt * KTILE + row) * N3 + c16 * 8);
        cp_cg16(&VTs[row * AT_W + c16 * 4],
                vtb + (size_t)row * SEQ + kt * KTILE + c16 * 8);
    }
    if (tid < 16) cp_cg16(&Mk[tid * 4], mb + kt * KTILE + tid * 4);
}

__global__ __launch_bounds__(128, 3) void attn_mma(
    const __half* __restrict__ qkv, const __half* __restrict__ vwT,
    const int* __restrict__ vmask, __half* __restrict__ ctx)
{
    const int tid  = threadIdx.x;
    const int lane = tid & 31;
    const int warp = tid >> 5;
    const int g = lane >> 2, t = lane & 3;
    const int qrow0 = warp * 32;
    const int qt = blockIdx.x, h = blockIdx.y, b = blockIdx.z;

    unsigned* Qs = (unsigned*)(sm_dyn + NSTG * STAGE_W);

    const __half* qb = qkv + ((size_t)b * SEQ + qt * QROWS) * N3 + h * HD;
#pragma unroll
    for (int j = 0; j < 8; j++) {
        int idx = tid + j * 128;
        int row = idx >> 3, c16 = idx & 7;
        cp_cg16(&Qs[row * AT_W + c16 * 4], qb + (size_t)row * N3 + c16 * 8);
    }

    const __half* kbase  = qkv + ((size_t)b * SEQ) * N3 + DM + h * HD;
    const __half* vtbase = vwT + ((size_t)b * DM + h * HD) * SEQ;
    const int*    mbase  = vmask + b * SEQ;

    attn_prefetch((unsigned*)sm_dyn, kbase, vtbase, mbase, 0, tid);
    asm volatile("cp.async.commit_group;" ::: "memory");
    attn_prefetch((unsigned*)sm_dyn + STAGE_W, kbase, vtbase, mbase, 1, tid);
    asm volatile("cp.async.commit_group;" ::: "memory");

    float m[2][2], l[2][2];
#pragma unroll
    for (int mi = 0; mi < 2; mi++) {
        m[mi][0] = -1e30f; m[mi][1] = -1e30f;
        l[mi][0] = 0.0f;   l[mi][1] = 0.0f;
    }
    float o[2][8][4];
#pragma unroll
    for (int mi = 0; mi < 2; mi++)
#pragma unroll
        for (int nf = 0; nf < 8; nf++)
#pragma unroll
            for (int e = 0; e < 4; e++) o[mi][nf][e] = 0.0f;

    int st = 0;
    for (int kt = 0; kt < NT; kt++) {
        asm volatile("cp.async.wait_group 1;" ::: "memory");
        __syncthreads();
        if (kt + 2 < NT) {
            int j = st - 1; if (j < 0) j += NSTG;
            attn_prefetch((unsigned*)sm_dyn + j * STAGE_W,
                          kbase, vtbase, mbase, kt + 2, tid);
            asm volatile("cp.async.commit_group;" ::: "memory");
        } else {
            asm volatile("cp.async.commit_group;" ::: "memory");
        }
        const unsigned* Ks  = (const unsigned*)sm_dyn + st * STAGE_W;
        const unsigned* VTs = Ks + KTILE * AT_W;
        const int*      Mk  = (const int*)(VTs + KTILE * AT_W);
        if (++st == NSTG) st = 0;

        // ---- S = Q . K^T  (exp2-domain scores) ----
        float s[2][8][4];
#pragma unroll
        for (int mi = 0; mi < 2; mi++)
#pragma unroll
            for (int nf = 0; nf < 8; nf++)
#pragma unroll
                for (int e = 0; e < 4; e++) s[mi][nf][e] = 0.0f;

#pragma unroll
        for (int kf = 0; kf < 4; kf++) {
            unsigned a0[4], a1[4];
            a0[0] = Qs[(qrow0 + g)      * AT_W + kf * 8 + t];
            a0[1] = Qs[(qrow0 + g + 8)  * AT_W + kf * 8 + t];
            a0[2] = Qs[(qrow0 + g)      * AT_W + kf * 8 + t + 4];
            a0[3] = Qs[(qrow0 + g + 8)  * AT_W + kf * 8 + t + 4];
            a1[0] = Qs[(qrow0 + g + 16) * AT_W + kf * 8 + t];
            a1[1] = Qs[(qrow0 + g + 24) * AT_W + kf * 8 + t];
            a1[2] = Qs[(qrow0 + g + 16) * AT_W + kf * 8 + t + 4];
            a1[3] = Qs[(qrow0 + g + 24) * AT_W + kf * 8 + t + 4];
#pragma unroll
            for (int nf = 0; nf < 8; nf++) {
                unsigned bfr[2];
                bfr[0] = Ks[(nf * 8 + g) * AT_W + kf * 8 + t];
                bfr[1] = Ks[(nf * 8 + g) * AT_W + kf * 8 + t + 4];
                mma_f16(s[0][nf], a0, bfr);
                mma_f16(s[1][nf], a1, bfr);
            }
        }

        // ---- mask + online softmax (exp2 domain, f16x2 exp) ----
        unsigned p01[2][8], p23[2][8];
#pragma unroll
        for (int mi = 0; mi < 2; mi++) {
            float mx0 = -1e30f, mx1 = -1e30f;
#pragma unroll
            for (int nf = 0; nf < 8; nf++) {
                float pen0 = Mk[nf * 8 + 2 * t]     ? 0.0f : 1e12f;
                float pen1 = Mk[nf * 8 + 2 * t + 1] ? 0.0f : 1e12f;
                s[mi][nf][0] -= pen0; s[mi][nf][1] -= pen1;
                s[mi][nf][2] -= pen0; s[mi][nf][3] -= pen1;
                mx0 = fmaxf(mx0, fmaxf(s[mi][nf][0], s[mi][nf][1]));
                mx1 = fmaxf(mx1, fmaxf(s[mi][nf][2], s[mi][nf][3]));
            }
            mx0 = fmaxf(mx0, __shfl_xor_sync(0xffffffffu, mx0, 1));
            mx0 = fmaxf(mx0, __shfl_xor_sync(0xffffffffu, mx0, 2));
            mx1 = fmaxf(mx1, __shfl_xor_sync(0xffffffffu, mx1, 1));
            mx1 = fmaxf(mx1, __shfl_xor_sync(0xffffffffu, mx1, 2));
            float mn0 = fmaxf(m[mi][0], mx0), mn1 = fmaxf(m[mi][1], mx1);
            float al0 = ex2f(m[mi][0] - mn0), al1 = ex2f(m[mi][1] - mn1);
            m[mi][0] = mn0; m[mi][1] = mn1;
            float sum0 = 0.0f, sum1 = 0.0f;
#pragma unroll
            for (int nf = 0; nf < 8; nf++) {
                unsigned u01 = h2ex2(s[mi][nf][0] - mn0, s[mi][nf][1] - mn0);
                unsigned u23 = h2ex2(s[mi][nf][2] - mn1, s[mi][nf][3] - mn1);
                p01[mi][nf] = u01;
                p23[mi][nf] = u23;
                float2 f0 = h2_to_f2(u01);
                float2 f1 = h2_to_f2(u23);
                sum0 += f0.x + f0.y;
                sum1 += f1.x + f1.y;
            }
            sum0 += __shfl_xor_sync(0xffffffffu, sum0, 1);
            sum0 += __shfl_xor_sync(0xffffffffu, sum0, 2);
            sum1 += __shfl_xor_sync(0xffffffffu, sum1, 1);
            sum1 += __shfl_xor_sync(0xffffffffu, sum1, 2);
            l[mi][0] = l[mi][0] * al0 + sum0;
            l[mi][1] = l[mi][1] * al1 + sum1;
#pragma unroll
            for (int nf = 0; nf < 8; nf++) {
                o[mi][nf][0] *= al0; o[mi][nf][1] *= al0;
                o[mi][nf][2] *= al1; o[mi][nf][3] *= al1;
            }
        }

        // ---- O += P . V : A-frag is directly the fp16 exp output ----
#pragma unroll
        for (int kf = 0; kf < 4; kf++) {
            unsigned af[2][4];
#pragma unroll
            for (int mi = 0; mi < 2; mi++) {
                af[mi][0] = p01[mi][2 * kf];
                af[mi][1] = p23[mi][2 * kf];
                af[mi][2] = p01[mi][2 * kf + 1];
                af[mi][3] = p23[mi][2 * kf + 1];
            }
#pragma unroll
            for (int nf = 0; nf < 8; nf++) {
                unsigned bfr[2];
                bfr[0] = VTs[(nf * 8 + g) * AT_W + kf * 8 + t];
                bfr[1] = VTs[(nf * 8 + g) * AT_W + kf * 8 + t + 4];
                mma_f16(o[0][nf], af[0], bfr);
                mma_f16(o[1][nf], af[1], bfr);
            }
        }
    }

    // ---- normalize; write ctx fp16 [token][c] ----
    __half* obase = ctx + ((size_t)b * SEQ + qt * QROWS + qrow0) * DM + h * HD;
#pragma unroll
    for (int mi = 0; mi < 2; mi++) {
        float inv0 = 1.0f / l[mi][0], inv1 = 1.0f / l[mi][1];
        __half* ob = obase + (size_t)(mi * 16) * DM;
#pragma unroll
        for (int nf = 0; nf < 8; nf++) {
            int col = nf * 8 + 2 * t;
            *(__half2*)&ob[(size_t)g * DM + col] =
                __floats2half2_rn(o[mi][nf][0] * inv0, o[mi][nf][1] * inv0);
            *(__half2*)&ob[(size_t)(g + 8) * DM + col] =
                __floats2half2_rn(o[mi][nf][2] * inv1, o[mi][nf][3] * inv1);
        }
    }
}

// ---------------------------------------------------------------------------
extern "C" void kernel_launch(void* const* d_in, const int* in_sizes, int n_in,
                              void* d_out, int out_size)
{
    const float* q    = (const float*)d_in[0];
    const float* k    = (const float*)d_in[1];
    const float* v    = (const float*)d_in[2];
    const int*   mask = (const int*)  d_in[3];
    const float* Wq   = (const float*)d_in[4];
    const float* bq   = (const float*)d_in[5];
    const float* Wk   = (const float*)d_in[6];
    const float* bk   = (const float*)d_in[7];
    const float* Wv   = (const float*)d_in[8];
    const float* bv   = (const float*)d_in[9];
    const float* Wo   = (const float*)d_in[10];
    const float* bo   = (const float*)d_in[11];
    float* out = (float*)d_out;

    void *pin, *pwT, *pqkv, *pvwT, *pctx;
    cudaGetSymbolAddress(&pin,  g_inh);
    cudaGetSymbolAddress(&pwT,  g_wT);
    cudaGetSymbolAddress(&pqkv, g_qkv);
    cudaGetSymbolAddress(&pvwT, g_vwT);
    cudaGetSymbolAddress(&pctx, g_ctx);

    __half* inh = (__half*)pin;
    __half* wT  = (__half*)pwT;
    __half* qkv = (__half*)pqkv;
    __half* vwT = (__half*)pvwT;
    __half* ctx = (__half*)pctx;

    cudaFuncSetAttribute(gemm_qkv,
                         cudaFuncAttributeMaxDynamicSharedMemorySize, GEMM_SMEM);
    cudaFuncSetAttribute(gemm_out,
                         cudaFuncAttributeMaxDynamicSharedMemorySize, GEMM_SMEM);
    cudaFuncSetAttribute(attn_mma,
                         cudaFuncAttributeMaxDynamicSharedMemorySize, ATTN_SMEM);

    // 1) fused prepass: fp16 converts (z=3) + weight transposes (z=4)
    const int nBig = MROWS * DM / 4;
    to_f16_3<<<dim3(nBig / 256, 1, 3), 256>>>(
        (const float4*)q, (const float4*)k, (const float4*)v,
        (__half2*)inh, nBig);
    transp_w4<<<dim3(DM / 32, DM / 32, 4), dim3(32, 8)>>>(Wq, Wk, Wv, Wo, wT);

    // 2) grouped QKV projection; z==2 writes V transposed straight to vwT
    gemm_qkv<<<dim3(DM / 128, MROWS / 128, 3), 256, GEMM_SMEM>>>(
        inh, wT, bq, bk, bv, qkv, vwT);

    // 3) fused attention -> ctx (fp16), 3 CTAs/SM
    attn_mma<<<dim3(SEQ / QROWS, NH, NB), 128, ATTN_SMEM>>>(
        qkv, vwT, mask, ctx);

    // 4) output projection (fp32 out)
    gemm_out<<<dim3(DM / 128, MROWS / 128), 256, GEMM_SMEM>>>(
        ctx, wT + 3 * (size_t)DM * DM, bo, out);
}

// round 14
// speedup vs baseline: 2.1679x; 1.0134x over previous
#include <cuda_runtime.h>
#include <cuda_fp16.h>
#include <math.h>
#include <cstdint>

#define SEQ 2048
#define DM 1024
#define NH 16
#define HD 64
#define NB 2
#define MROWS (NB * SEQ)   // 4096
#define N3 (3 * DM)        // 3072 (qkv buffer width)

// Q projection pre-scaled by 0.125*log2(e): softmax runs in exp2 domain.
#define QSCALE 0.18033688011112042f

// Scratch (__device__ globals; allocation-free rule). fp16 payloads.
__device__ __half g_inh[3 * MROWS * DM];  // fp16(q|k|v) inputs, tensor-major
__device__ __half g_wT[4 * DM * DM];      // fp16(Wq^T|Wk^T|Wv^T|Wo^T) [N][K]
__device__ __half g_qkv[MROWS * N3];      // fp16 proj: [token][Q|K|.] (V seg unused)
__device__ __half g_vwT[NB * DM * SEQ];   // fp16(proj V)^T  [b][c][token]
__device__ __half g_ctx[MROWS * DM];      // fp16(attn out)  [token][c]

__device__ __forceinline__ void mma_f16(float c[4], const unsigned a[4],
                                        const unsigned b[2]) {
    asm volatile(
        "mma.sync.aligned.m16n8k16.row.col.f32.f16.f16.f32 "
        "{%0,%1,%2,%3}, {%4,%5,%6,%7}, {%8,%9}, {%0,%1,%2,%3};\n"
        : "+f"(c[0]), "+f"(c[1]), "+f"(c[2]), "+f"(c[3])
        : "r"(a[0]), "r"(a[1]), "r"(a[2]), "r"(a[3]), "r"(b[0]), "r"(b[1]));
}

__device__ __forceinline__ unsigned h2ex2(float lo, float hi) {
    __half2 d = __floats2half2_rn(lo, hi);
    unsigned x = *(unsigned*)&d, r;
    asm("ex2.approx.f16x2 %0, %1;" : "=r"(r) : "r"(x));
    return r;
}
__device__ __forceinline__ float ex2f(float x) {
    float r;
    asm("ex2.approx.f32 %0, %1;" : "=f"(r) : "f"(x));
    return r;
}

__device__ __forceinline__ void cp_cg16(void* dst, const void* src) {
    unsigned u = (unsigned)__cvta_generic_to_shared(dst);
    asm volatile("cp.async.cg.shared.global [%0], [%1], 16;" :: "r"(u), "l"(src));
}

extern __shared__ float sm_dyn[];

// ---------------------------------------------------------------------------
// Fused prepass kernels.
// ---------------------------------------------------------------------------
__global__ __launch_bounds__(256) void to_f16_3(
    const float4* __restrict__ q, const float4* __restrict__ k,
    const float4* __restrict__ v, __half2* __restrict__ out, int n4)
{
    int i = blockIdx.x * 256 + threadIdx.x;
    const float4* in = (blockIdx.z == 0) ? q : (blockIdx.z == 1) ? k : v;
    __half2* o = out + (size_t)blockIdx.z * (2 * (size_t)n4);
    if (i < n4) {
        float4 x = in[i];
        o[2 * i]     = __floats2half2_rn(x.x, x.y);
        o[2 * i + 1] = __floats2half2_rn(x.z, x.w);
    }
}

__global__ __launch_bounds__(256) void transp_w4(
    const float* __restrict__ w0, const float* __restrict__ w1,
    const float* __restrict__ w2, const float* __restrict__ w3,
    __half* __restrict__ out)
{
    __shared__ float t[32][33];
    const float* in = (blockIdx.z == 0) ? w0 : (blockIdx.z == 1) ? w1
                    : (blockIdx.z == 2) ? w2 : w3;
    __half* o = out + (size_t)blockIdx.z * DM * DM;
    int tx = threadIdx.x, ty = threadIdx.y;           // 32 x 8
    int bx = blockIdx.x * 32, by = blockIdx.y * 32;
#pragma unroll
    for (int j = 0; j < 4; j++)
        t[ty + j * 8][tx] = in[(size_t)(by + ty + j * 8) * DM + bx + tx];
    __syncthreads();
#pragma unroll
    for (int j = 0; j < 4; j++)
        o[(size_t)(bx + ty + j * 8) * DM + by + tx] =
            __float2half_rn(t[tx][ty + j * 8]);
}

// ---------------------------------------------------------------------------
// GEMM tiles: 128x128 block, 256 threads, 8 warps x (64x32), m16n8k16,
// k-chunk 64 halves, 3-stage cp.async (wait_group 1), pitch 36 words.
// ---------------------------------------------------------------------------
#define GW 36
#define GEMM_STAGE (128 * GW)
#define GEMM_NSTG 3
#define GEMM_SMEM ((2 * GEMM_NSTG * GEMM_STAGE) * (int)sizeof(float))  // 110592

__device__ __forceinline__ void gemm_prefetch(
    unsigned* As, unsigned* Bs, const __half* A, const __half* WT,
    int K, int bm, int bn, int k0, int tid)
{
#pragma unroll
    for (int j = 0; j < 4; j++) {
        int idx = tid + j * 256;
        int row = idx >> 3;
        int c16 = idx & 7;
        cp_cg16(&As[row * GW + c16 * 4],
                A + (size_t)(bm + row) * K + k0 + c16 * 8);
        cp_cg16(&Bs[row * GW + c16 * 4],
                WT + (size_t)(bn + row) * K + k0 + c16 * 8);
    }
}

__device__ __forceinline__ void gemm_mainloop(
    float acc[4][4][4], const __half* A, const __half* WT,
    int K, int bm, int bn, int tid, int wm, int wn, int g, int t)
{
    unsigned* As0 = (unsigned*)sm_dyn;
    unsigned* Bs0 = As0 + GEMM_NSTG * GEMM_STAGE;

    gemm_prefetch(As0, Bs0, A, WT, K, bm, bn, 0, tid);
    asm volatile("cp.async.commit_group;" ::: "memory");
    gemm_prefetch(As0 + GEMM_STAGE, Bs0 + GEMM_STAGE, A, WT, K, bm, bn, 64, tid);
    asm volatile("cp.async.commit_group;" ::: "memory");

    const int NKI = K / 64;
    for (int i = 0; i < NKI; i++) {
        asm volatile("cp.async.wait_group 1;" ::: "memory");
        __syncthreads();
        int pf = i + 2;
        if (pf < NKI) {
            int j = pf % GEMM_NSTG;
            gemm_prefetch(As0 + j * GEMM_STAGE, Bs0 + j * GEMM_STAGE,
                          A, WT, K, bm, bn, pf * 64, tid);
        }
        asm volatile("cp.async.commit_group;" ::: "memory");
        const int st = i % GEMM_NSTG;
        const unsigned* As = As0 + st * GEMM_STAGE;
        const unsigned* Bs = Bs0 + st * GEMM_STAGE;

#pragma unroll
        for (int kf = 0; kf < 4; kf++) {
            unsigned af[4][4], bf[4][2];
#pragma unroll
            for (int mi = 0; mi < 4; mi++) {
                int r = wm + mi * 16;
                af[mi][0] = As[(r + g)     * GW + kf * 8 + t];
                af[mi][1] = As[(r + g + 8) * GW + kf * 8 + t];
                af[mi][2] = As[(r + g)     * GW + kf * 8 + t + 4];
                af[mi][3] = As[(r + g + 8) * GW + kf * 8 + t + 4];
            }
#pragma unroll
            for (int ni = 0; ni < 4; ni++) {
                int c = wn + ni * 8;
                bf[ni][0] = Bs[(c + g) * GW + kf * 8 + t];
                bf[ni][1] = Bs[(c + g) * GW + kf * 8 + t + 4];
            }
#pragma unroll
            for (int mi = 0; mi < 4; mi++)
#pragma unroll
                for (int ni = 0; ni < 4; ni++)
                    mma_f16(acc[mi][ni], af[mi], bf[ni]);
        }
    }
}

// Grouped QKV projection. z=0: Q (scaled) -> qkv seg 0; z=1: K -> qkv seg 1;
// z=2: V -> written TRANSPOSED directly to vwT[b][c][tok] via smem restage.
__global__ __launch_bounds__(256, 2) void gemm_qkv(
    const __half* __restrict__ inh, const __half* __restrict__ wT,
    const float* __restrict__ bq, const float* __restrict__ bk,
    const float* __restrict__ bv, __half* __restrict__ qkv,
    __half* __restrict__ vwT)
{
    const int tid  = threadIdx.x;
    const int lane = tid & 31;
    const int warp = tid >> 5;
    const int g = lane >> 2, t = lane & 3;
    const int wm = (warp >> 2) * 64;
    const int wn = (warp & 3) * 32;
    const int bm = blockIdx.y * 128;
    const int bn = blockIdx.x * 128;
    const int z  = blockIdx.z;

    const __half* A  = inh + (size_t)z * MROWS * DM;
    const __half* WT = wT  + (size_t)z * DM * DM;
    const float* bias = (z == 0) ? bq : (z == 1) ? bk : bv;
    const float sc = (z == 0) ? QSCALE : 1.0f;

    float acc[4][4][4];
#pragma unroll
    for (int mi = 0; mi < 4; mi++)
#pragma unroll
        for (int ni = 0; ni < 4; ni++)
#pragma unroll
            for (int e = 0; e < 4; e++) acc[mi][ni][e] = 0.0f;

    gemm_mainloop(acc, A, WT, DM, bm, bn, tid, wm, wn, g, t);

    if (z < 2) {
#pragma unroll
        for (int mi = 0; mi < 4; mi++) {
            int r0 = bm + wm + mi * 16 + g;
#pragma unroll
            for (int ni = 0; ni < 4; ni++) {
                int cb = bn + wn + ni * 8 + 2 * t;
                float b0 = bias[cb], b1 = bias[cb + 1];
                float x00 = (acc[mi][ni][0] + b0) * sc;
                float x01 = (acc[mi][ni][1] + b1) * sc;
                float x10 = (acc[mi][ni][2] + b0) * sc;
                float x11 = (acc[mi][ni][3] + b1) * sc;
                __half* c0p = qkv + (size_t)r0 * N3 + z * DM + cb;
                *(__half2*)c0p = __floats2half2_rn(x00, x01);
                *(__half2*)(c0p + (size_t)8 * N3) = __floats2half2_rn(x10, x11);
            }
        }
    } else {
        // V: restage transposed through smem, write vwT[b][c][tok].
        __syncthreads();           // all warps done reading mainloop smem
        __half* ts = (__half*)sm_dyn;   // [128 c][136 tok-pitch] halves
#pragma unroll
        for (int mi = 0; mi < 4; mi++) {
            int tokl = wm + mi * 16 + g;
#pragma unroll
            for (int ni = 0; ni < 4; ni++) {
                int cl = wn + ni * 8 + 2 * t;
                float b0 = bias[bn + cl], b1 = bias[bn + cl + 1];
                ts[cl * 136 + tokl]           = __float2half_rn(acc[mi][ni][0] + b0);
                ts[(cl + 1) * 136 + tokl]     = __float2half_rn(acc[mi][ni][1] + b1);
                ts[cl * 136 + tokl + 8]       = __float2half_rn(acc[mi][ni][2] + b0);
                ts[(cl + 1) * 136 + tokl + 8] = __float2half_rn(acc[mi][ni][3] + b1);
            }
        }
        __syncthreads();
        const int b = bm >> 11;
        const int tok0 = bm & 2047;
#pragma unroll
        for (int it = 0; it < 8; it++) {
            int idx = tid + it * 256;
            int cl = idx >> 4;
            int tk = (idx & 15) * 8;
            uint4 y = *(const uint4*)&ts[cl * 136 + tk];
            *(uint4*)&vwT[((size_t)b * DM + bn + cl) * SEQ + tok0 + tk] = y;
        }
    }
}

// Output projection: C(fp32) = ctx(fp16) @ Wo + bo.
__global__ __launch_bounds__(256, 2) void gemm_out(
    const __half* __restrict__ A, const __half* __restrict__ WT,
    const float* __restrict__ bias, float* __restrict__ C)
{
    const int tid  = threadIdx.x;
    const int lane = tid & 31;
    const int warp = tid >> 5;
    const int g = lane >> 2, t = lane & 3;
    const int wm = (warp >> 2) * 64;
    const int wn = (warp & 3) * 32;
    const int bm = blockIdx.y * 128;
    const int bn = blockIdx.x * 128;

    float acc[4][4][4];
#pragma unroll
    for (int mi = 0; mi < 4; mi++)
#pragma unroll
        for (int ni = 0; ni < 4; ni++)
#pragma unroll
            for (int e = 0; e < 4; e++) acc[mi][ni][e] = 0.0f;

    gemm_mainloop(acc, A, WT, DM, bm, bn, tid, wm, wn, g, t);

#pragma unroll
    for (int mi = 0; mi < 4; mi++) {
        int r0 = bm + wm + mi * 16 + g;
#pragma unroll
        for (int ni = 0; ni < 4; ni++) {
            int cb = bn + wn + ni * 8 + 2 * t;
            float b0 = bias[cb], b1 = bias[cb + 1];
            *(float2*)&C[(size_t)r0 * DM + cb] =
                make_float2(acc[mi][ni][0] + b0, acc[mi][ni][1] + b1);
            *(float2*)&C[(size_t)(r0 + 8) * DM + cb] =
                make_float2(acc[mi][ni][2] + b0, acc[mi][ni][3] + b1);
        }
    }
}

// ---------------------------------------------------------------------------
// Flash-attention, fp16 mma, exp2-domain softmax with ex2.approx.f16x2.
// 128 threads / 4 warps, QROWS=128 (32 rows/warp, mi=2 B-frag sharing).
// l computed via ONES-COLUMN mma (O' = P.[V|1]): no scalar row-sum chain.
// 3 CTAs/SM (launch_bounds(128,3)).
// ---------------------------------------------------------------------------
#define QROWS 128
#define KTILE 64
#define NT (SEQ / KTILE)
#define NSTG 3
#define AT_W 36
#define STAGE_W (KTILE * AT_W * 2 + 64)
#define QS_W (QROWS * AT_W)
#define ATTN_SMEM ((NSTG * STAGE_W + QS_W) * (int)sizeof(float))  // 74496
#define ONES_H2 0x3C003C00u   // half2(1.0, 1.0)

__device__ __forceinline__ void attn_prefetch(
    unsigned* stage, const __half* kb, const __half* vtb, const int* mb,
    int kt, int tid)
{
    unsigned* Ks  = stage;
    unsigned* VTs = stage + KTILE * AT_W;
    unsigned* Mk  = VTs + KTILE * AT_W;
#pragma unroll
    for (int j = 0; j < 4; j++) {
        int idx = tid + j * 128;
        int row = idx >> 3;
        int c16 = idx & 7;
        cp_cg16(&Ks[row * AT_W + c16 * 4],
                kb + (size_t)(kt * KTILE + row) * N3 + c16 * 8);
        cp_cg16(&VTs[row * AT_W + c16 * 4],
                vtb + (size_t)row * SEQ + kt * KTILE + c16 * 8);
    }
    if (tid < 16) cp_cg16(&Mk[tid * 4], mb + kt * KTILE + tid * 4);
}

__global__ __launch_bounds__(128, 3) void attn_mma(
    const __half* __restrict__ qkv, const __half* __restrict__ vwT,
    const int* __restrict__ vmask, __half* __restrict__ ctx)
{
    const int tid  = threadIdx.x;
    const int lane = tid & 31;
    const int warp = tid >> 5;
    const int g = lane >> 2, t = lane & 3;
    const int qrow0 = warp * 32;
    const int qt = blockIdx.x, h = blockIdx.y, b = blockIdx.z;

    unsigned* Qs = (unsigned*)(sm_dyn + NSTG * STAGE_W);

    const __half* qb = qkv + ((size_t)b * SEQ + qt * QROWS) * N3 + h * HD;
#pragma unroll
    for (int j = 0; j < 8; j++) {
        int idx = tid + j * 128;
        int row = idx >> 3, c16 = idx & 7;
        cp_cg16(&Qs[row * AT_W + c16 * 4], qb + (size_t)row * N3 + c16 * 8);
    }

    const __half* kbase  = qkv + ((size_t)b * SEQ) * N3 + DM + h * HD;
    const __half* vtbase = vwT + ((size_t)b * DM + h * HD) * SEQ;
    const int*    mbase  = vmask + b * SEQ;

    attn_prefetch((unsigned*)sm_dyn, kbase, vtbase, mbase, 0, tid);
    asm volatile("cp.async.commit_group;" ::: "memory");
    attn_prefetch((unsigned*)sm_dyn + STAGE_W, kbase, vtbase, mbase, 1, tid);
    asm volatile("cp.async.commit_group;" ::: "memory");

    float m[2][2];
#pragma unroll
    for (int mi = 0; mi < 2; mi++) { m[mi][0] = -1e30f; m[mi][1] = -1e30f; }
    float o[2][8][4];
    float ol[2][4];   // ones-column accumulator: ol[mi][0]=l(row g), [2]=l(row g+8)
#pragma unroll
    for (int mi = 0; mi < 2; mi++) {
#pragma unroll
        for (int nf = 0; nf < 8; nf++)
#pragma unroll
            for (int e = 0; e < 4; e++) o[mi][nf][e] = 0.0f;
#pragma unroll
        for (int e = 0; e < 4; e++) ol[mi][e] = 0.0f;
    }

    const unsigned bones[2] = { ONES_H2, ONES_H2 };

    int st = 0;
    for (int kt = 0; kt < NT; kt++) {
        asm volatile("cp.async.wait_group 1;" ::: "memory");
        __syncthreads();
        if (kt + 2 < NT) {
            int j = st - 1; if (j < 0) j += NSTG;
            attn_prefetch((unsigned*)sm_dyn + j * STAGE_W,
                          kbase, vtbase, mbase, kt + 2, tid);
            asm volatile("cp.async.commit_group;" ::: "memory");
        } else {
            asm volatile("cp.async.commit_group;" ::: "memory");
        }
        const unsigned* Ks  = (const unsigned*)sm_dyn + st * STAGE_W;
        const unsigned* VTs = Ks + KTILE * AT_W;
        const int*      Mk  = (const int*)(VTs + KTILE * AT_W);
        if (++st == NSTG) st = 0;

        // ---- S = Q . K^T  (exp2-domain scores) ----
        float s[2][8][4];
#pragma unroll
        for (int mi = 0; mi < 2; mi++)
#pragma unroll
            for (int nf = 0; nf < 8; nf++)
#pragma unroll
                for (int e = 0; e < 4; e++) s[mi][nf][e] = 0.0f;

#pragma unroll
        for (int kf = 0; kf < 4; kf++) {
            unsigned a0[4], a1[4];
            a0[0] = Qs[(qrow0 + g)      * AT_W + kf * 8 + t];
            a0[1] = Qs[(qrow0 + g + 8)  * AT_W + kf * 8 + t];
            a0[2] = Qs[(qrow0 + g)      * AT_W + kf * 8 + t + 4];
            a0[3] = Qs[(qrow0 + g + 8)  * AT_W + kf * 8 + t + 4];
            a1[0] = Qs[(qrow0 + g + 16) * AT_W + kf * 8 + t];
            a1[1] = Qs[(qrow0 + g + 24) * AT_W + kf * 8 + t];
            a1[2] = Qs[(qrow0 + g + 16) * AT_W + kf * 8 + t + 4];
            a1[3] = Qs[(qrow0 + g + 24) * AT_W + kf * 8 + t + 4];
#pragma unroll
            for (int nf = 0; nf < 8; nf++) {
                unsigned bfr[2];
                bfr[0] = Ks[(nf * 8 + g) * AT_W + kf * 8 + t];
                bfr[1] = Ks[(nf * 8 + g) * AT_W + kf * 8 + t + 4];
                mma_f16(s[0][nf], a0, bfr);
                mma_f16(s[1][nf], a1, bfr);
            }
        }

        // ---- mask + online softmax (exp2, f16x2; l lives in ol column) ----
        unsigned p01[2][8], p23[2][8];
#pragma unroll
        for (int mi = 0; mi < 2; mi++) {
            float mx0 = -1e30f, mx1 = -1e30f;
#pragma unroll
            for (int nf = 0; nf < 8; nf++) {
                float pen0 = Mk[nf * 8 + 2 * t]     ? 0.0f : 1e12f;
                float pen1 = Mk[nf * 8 + 2 * t + 1] ? 0.0f : 1e12f;
                s[mi][nf][0] -= pen0; s[mi][nf][1] -= pen1;
                s[mi][nf][2] -= pen0; s[mi][nf][3] -= pen1;
                mx0 = fmaxf(mx0, fmaxf(s[mi][nf][0], s[mi][nf][1]));
                mx1 = fmaxf(mx1, fmaxf(s[mi][nf][2], s[mi][nf][3]));
            }
            mx0 = fmaxf(mx0, __shfl_xor_sync(0xffffffffu, mx0, 1));
            mx0 = fmaxf(mx0, __shfl_xor_sync(0xffffffffu, mx0, 2));
            mx1 = fmaxf(mx1, __shfl_xor_sync(0xffffffffu, mx1, 1));
            mx1 = fmaxf(mx1, __shfl_xor_sync(0xffffffffu, mx1, 2));
            float mn0 = fmaxf(m[mi][0], mx0), mn1 = fmaxf(m[mi][1], mx1);
            float al0 = ex2f(m[mi][0] - mn0), al1 = ex2f(m[mi][1] - mn1);
            m[mi][0] = mn0; m[mi][1] = mn1;
#pragma unroll
            for (int nf = 0; nf < 8; nf++) {
                p01[mi][nf] = h2ex2(s[mi][nf][0] - mn0, s[mi][nf][1] - mn0);
                p23[mi][nf] = h2ex2(s[mi][nf][2] - mn1, s[mi][nf][3] - mn1);
            }
#pragma unroll
            for (int nf = 0; nf < 8; nf++) {
                o[mi][nf][0] *= al0; o[mi][nf][1] *= al0;
                o[mi][nf][2] *= al1; o[mi][nf][3] *= al1;
            }
            ol[mi][0] *= al0; ol[mi][1] *= al0;
            ol[mi][2] *= al1; ol[mi][3] *= al1;
        }

        // ---- O' += P . [V | 1] : A-frag = fp16 exp output; l via ones col ----
#pragma unroll
        for (int kf = 0; kf < 4; kf++) {
            unsigned af[2][4];
#pragma unroll
            for (int mi = 0; mi < 2; mi++) {
                af[mi][0] = p01[mi][2 * kf];
                af[mi][1] = p23[mi][2 * kf];
                af[mi][2] = p01[mi][2 * kf + 1];
                af[mi][3] = p23[mi][2 * kf + 1];
            }
#pragma unroll
            for (int nf = 0; nf < 8; nf++) {
                unsigned bfr[2];
                bfr[0] = VTs[(nf * 8 + g) * AT_W + kf * 8 + t];
                bfr[1] = VTs[(nf * 8 + g) * AT_W + kf * 8 + t + 4];
                mma_f16(o[0][nf], af[0], bfr);
                mma_f16(o[1][nf], af[1], bfr);
            }
            mma_f16(ol[0], af[0], bones);
            mma_f16(ol[1], af[1], bones);
        }
    }

    // ---- normalize; write ctx fp16 [token][c] ----
    __half* obase = ctx + ((size_t)b * SEQ + qt * QROWS + qrow0) * DM + h * HD;
#pragma unroll
    for (int mi = 0; mi < 2; mi++) {
        float inv0 = 1.0f / ol[mi][0], inv1 = 1.0f / ol[mi][2];
        __half* ob = obase + (size_t)(mi * 16) * DM;
#pragma unroll
        for (int nf = 0; nf < 8; nf++) {
            int col = nf * 8 + 2 * t;
            *(__half2*)&ob[(size_t)g * DM + col] =
                __floats2half2_rn(o[mi][nf][0] * inv0, o[mi][nf][1] * inv0);
            *(__half2*)&ob[(size_t)(g + 8) * DM + col] =
                __floats2half2_rn(o[mi][nf][2] * inv1, o[mi][nf][3] * inv1);
        }
    }
}

// ---------------------------------------------------------------------------
extern "C" void kernel_launch(void* const* d_in, const int* in_sizes, int n_in,
                              void* d_out, int out_size)
{
    const float* q    = (const float*)d_in[0];
    const float* k    = (const float*)d_in[1];
    const float* v    = (const float*)d_in[2];
    const int*   mask = (const int*)  d_in[3];
    const float* Wq   = (const float*)d_in[4];
    const float* bq   = (const float*)d_in[5];
    const float* Wk   = (const float*)d_in[6];
    const float* bk   = (const float*)d_in[7];
    const float* Wv   = (const float*)d_in[8];
    const float* bv   = (const float*)d_in[9];
    const float* Wo   = (const float*)d_in[10];
    const float* bo   = (const float*)d_in[11];
    float* out = (float*)d_out;

    void *pin, *pwT, *pqkv, *pvwT, *pctx;
    cudaGetSymbolAddress(&pin,  g_inh);
    cudaGetSymbolAddress(&pwT,  g_wT);
    cudaGetSymbolAddress(&pqkv, g_qkv);
    cudaGetSymbolAddress(&pvwT, g_vwT);
    cudaGetSymbolAddress(&pctx, g_ctx);

    __half* inh = (__half*)pin;
    __half* wT  = (__half*)pwT;
    __half* qkv = (__half*)pqkv;
    __half* vwT = (__half*)pvwT;
    __half* ctx = (__half*)pctx;

    cudaFuncSetAttribute(gemm_qkv,
                         cudaFuncAttributeMaxDynamicSharedMemorySize, GEMM_SMEM);
    cudaFuncSetAttribute(gemm_out,
                         cudaFuncAttributeMaxDynamicSharedMemorySize, GEMM_SMEM);
    cudaFuncSetAttribute(attn_mma,
                         cudaFuncAttributeMaxDynamicSharedMemorySize, ATTN_SMEM);

    // 1) fused prepass: fp16 converts (z=3) + weight transposes (z=4)
    const int nBig = MROWS * DM / 4;
    to_f16_3<<<dim3(nBig / 256, 1, 3), 256>>>(
        (const float4*)q, (const float4*)k, (const float4*)v,
        (__half2*)inh, nBig);
    transp_w4<<<dim3(DM / 32, DM / 32, 4), dim3(32, 8)>>>(Wq, Wk, Wv, Wo, wT);

    // 2) grouped QKV projection; z==2 writes V transposed straight to vwT
    gemm_qkv<<<dim3(DM / 128, MROWS / 128, 3), 256, GEMM_SMEM>>>(
        inh, wT, bq, bk, bv, qkv, vwT);

    // 3) fused attention -> ctx (fp16), 3 CTAs/SM
    attn_mma<<<dim3(SEQ / QROWS, NH, NB), 128, ATTN_SMEM>>>(
        qkv, vwT, mask, ctx);

    // 4) output projection (fp32 out)
    gemm_out<<<dim3(DM / 128, MROWS / 128), 256, GEMM_SMEM>>>(
        ctx, wT + 3 * (size_t)DM * DM, bo, out);
}

// round 15
// speedup vs baseline: 3.1304x; 1.4440x over previous
#include <cuda_runtime.h>
#include <cuda_fp16.h>
#include <math.h>
#include <cstdint>

#define SEQ 2048
#define DM 1024
#define NH 16
#define HD 64
#define NB 2
#define MROWS (NB * SEQ)   // 4096
#define N3 (3 * DM)        // 3072 (qkv buffer width)

// Q projection pre-scaled by 0.125*log2(e): softmax runs in exp2 domain.
#define QSCALE 0.18033688011112042f

// Scratch (__device__ globals; allocation-free rule).
__device__ __half g_inh[3 * MROWS * DM];  // fp16(q|k|v) inputs, tensor-major
__device__ __half g_wT[4 * DM * DM];      // fp16(Wq^T|Wk^T|Wv^T|Wo^T) [N][K]
__device__ __half g_qkv[MROWS * N3];      // fp16 proj: [token][Q|Kc|.]
__device__ __half g_vwT[NB * DM * SEQ];   // fp16(proj V)^T compacted [b][c][j]
__device__ __half g_ctx[MROWS * DM];      // fp16(attn out)  [token][c]
__device__ int    g_idx[NB * SEQ];        // compacted key token index (local)
__device__ int    g_mkc[NB * SEQ];        // compacted mask (1 valid, 0 pad)
__device__ int    g_ntc[NB];              // #64-key tiles per batch

__device__ __forceinline__ void mma_f16(float c[4], const unsigned a[4],
                                        const unsigned b[2]) {
    asm volatile(
        "mma.sync.aligned.m16n8k16.row.col.f32.f16.f16.f32 "
        "{%0,%1,%2,%3}, {%4,%5,%6,%7}, {%8,%9}, {%0,%1,%2,%3};\n"
        : "+f"(c[0]), "+f"(c[1]), "+f"(c[2]), "+f"(c[3])
        : "r"(a[0]), "r"(a[1]), "r"(a[2]), "r"(a[3]), "r"(b[0]), "r"(b[1]));
}

__device__ __forceinline__ unsigned h2ex2(float lo, float hi) {
    __half2 d = __floats2half2_rn(lo, hi);
    unsigned x = *(unsigned*)&d, r;
    asm("ex2.approx.f16x2 %0, %1;" : "=r"(r) : "r"(x));
    return r;
}
__device__ __forceinline__ float ex2f(float x) {
    float r;
    asm("ex2.approx.f32 %0, %1;" : "=f"(r) : "f"(x));
    return r;
}

__device__ __forceinline__ void cp_cg16(void* dst, const void* src) {
    unsigned u = (unsigned)__cvta_generic_to_shared(dst);
    asm volatile("cp.async.cg.shared.global [%0], [%1], 16;" :: "r"(u), "l"(src));
}

extern __shared__ float sm_dyn[];

// ---------------------------------------------------------------------------
// Prepass kernels.
// ---------------------------------------------------------------------------
__global__ __launch_bounds__(256) void to_f16_3(
    const float4* __restrict__ q, const float4* __restrict__ k,
    const float4* __restrict__ v, __half2* __restrict__ out, int n4)
{
    int i = blockIdx.x * 256 + threadIdx.x;
    const float4* in = (blockIdx.z == 0) ? q : (blockIdx.z == 1) ? k : v;
    __half2* o = out + (size_t)blockIdx.z * (2 * (size_t)n4);
    if (i < n4) {
        float4 x = in[i];
        o[2 * i]     = __floats2half2_rn(x.x, x.y);
        o[2 * i + 1] = __floats2half2_rn(x.z, x.w);
    }
}

__global__ __launch_bounds__(256) void transp_w4(
    const float* __restrict__ w0, const float* __restrict__ w1,
    const float* __restrict__ w2, const float* __restrict__ w3,
    __half* __restrict__ out)
{
    __shared__ float t[32][33];
    const float* in = (blockIdx.z == 0) ? w0 : (blockIdx.z == 1) ? w1
                    : (blockIdx.z == 2) ? w2 : w3;
    __half* o = out + (size_t)blockIdx.z * DM * DM;
    int tx = threadIdx.x, ty = threadIdx.y;           // 32 x 8
    int bx = blockIdx.x * 32, by = blockIdx.y * 32;
#pragma unroll
    for (int j = 0; j < 4; j++)
        t[ty + j * 8][tx] = in[(size_t)(by + ty + j * 8) * DM + bx + tx];
    __syncthreads();
#pragma unroll
    for (int j = 0; j < 4; j++)
        o[(size_t)(bx + ty + j * 8) * DM + by + tx] =
            __float2half_rn(t[tx][ty + j * 8]);
}

// Order-preserving key compaction: one block per batch, deterministic scan.
// Masked keys have exactly 0 softmax weight in the fp32 reference
// (exp(-1e12) underflows), so dropping them is exact.
__global__ __launch_bounds__(1024) void compact_mask(
    const int* __restrict__ vmask, int* __restrict__ idx,
    int* __restrict__ mkc, int* __restrict__ ntc)
{
    __shared__ int s[1024];
    __shared__ int cnt_s;
    const int b = blockIdx.x, t = threadIdx.x;
    const int* mb = vmask + b * SEQ;
    const int m0 = mb[2 * t] ? 1 : 0;
    const int m1 = mb[2 * t + 1] ? 1 : 0;
    const int p = m0 + m1;
    s[t] = p;
    __syncthreads();
    for (int off = 1; off < 1024; off <<= 1) {
        int v = s[t];
        if (t >= off) v += s[t - off];
        __syncthreads();
        s[t] = v;
        __syncthreads();
    }
    const int incl = s[t];
    if (t == 1023) cnt_s = incl;
    __syncthreads();
    const int cnt = cnt_s;
    // zero-init idx (padding gathers token 0 -> finite values, masked out)
    idx[b * SEQ + t] = 0;
    idx[b * SEQ + t + 1024] = 0;
    mkc[b * SEQ + t] = (t < cnt) ? 1 : 0;
    mkc[b * SEQ + t + 1024] = (t + 1024 < cnt) ? 1 : 0;
    __syncthreads();
    const int e = incl - p;
    if (m0) idx[b * SEQ + e] = 2 * t;
    if (m1) idx[b * SEQ + e + m0] = 2 * t + 1;
    if (t == 0) ntc[b] = (cnt + 63) >> 6;
}

// ---------------------------------------------------------------------------
// GEMM tiles: 128x128 block, 256 threads, 8 warps x (64x32), m16n8k16,
// k-chunk 64 halves, 3-stage cp.async (wait_group 1), pitch 36 words.
// A-rows addressed through an smem token table (gather support).
// ---------------------------------------------------------------------------
#define GW 36
#define GEMM_STAGE (128 * GW)
#define GEMM_NSTG 3
#define GEMM_SMEM ((2 * GEMM_NSTG * GEMM_STAGE) * (int)sizeof(float))  // 110592

__device__ __forceinline__ void gemm_prefetch(
    unsigned* As, unsigned* Bs, const __half* A, const __half* WT,
    const int* __restrict__ stok,
    int K, int bn, int k0, int tid)
{
#pragma unroll
    for (int j = 0; j < 4; j++) {
        int idx = tid + j * 256;
        int row = idx >> 3;
        int c16 = idx & 7;
        cp_cg16(&As[row * GW + c16 * 4],
                A + (size_t)stok[row] * K + k0 + c16 * 8);
        cp_cg16(&Bs[row * GW + c16 * 4],
                WT + (size_t)(bn + row) * K + k0 + c16 * 8);
    }
}

__device__ __forceinline__ void gemm_mainloop(
    float acc[4][4][4], const __half* A, const __half* WT,
    const int* __restrict__ stok,
    int K, int bn, int tid, int wm, int wn, int g, int t)
{
    unsigned* As0 = (unsigned*)sm_dyn;
    unsigned* Bs0 = As0 + GEMM_NSTG * GEMM_STAGE;

    gemm_prefetch(As0, Bs0, A, WT, stok, K, bn, 0, tid);
    asm volatile("cp.async.commit_group;" ::: "memory");
    gemm_prefetch(As0 + GEMM_STAGE, Bs0 + GEMM_STAGE, A, WT, stok, K, bn, 64, tid);
    asm volatile("cp.async.commit_group;" ::: "memory");

    const int NKI = K / 64;
    for (int i = 0; i < NKI; i++) {
        asm volatile("cp.async.wait_group 1;" ::: "memory");
        __syncthreads();
        int pf = i + 2;
        if (pf < NKI) {
            int j = pf % GEMM_NSTG;
            gemm_prefetch(As0 + j * GEMM_STAGE, Bs0 + j * GEMM_STAGE,
                          A, WT, stok, K, bn, pf * 64, tid);
        }
        asm volatile("cp.async.commit_group;" ::: "memory");
        const int st = i % GEMM_NSTG;
        const unsigned* As = As0 + st * GEMM_STAGE;
        const unsigned* Bs = Bs0 + st * GEMM_STAGE;

#pragma unroll
        for (int kf = 0; kf < 4; kf++) {
            unsigned af[4][4], bf[4][2];
#pragma unroll
            for (int mi = 0; mi < 4; mi++) {
                int r = wm + mi * 16;
                af[mi][0] = As[(r + g)     * GW + kf * 8 + t];
                af[mi][1] = As[(r + g + 8) * GW + kf * 8 + t];
                af[mi][2] = As[(r + g)     * GW + kf * 8 + t + 4];
                af[mi][3] = As[(r + g + 8) * GW + kf * 8 + t + 4];
            }
#pragma unroll
            for (int ni = 0; ni < 4; ni++) {
                int c = wn + ni * 8;
                bf[ni][0] = Bs[(c + g) * GW + kf * 8 + t];
                bf[ni][1] = Bs[(c + g) * GW + kf * 8 + t + 4];
            }
#pragma unroll
            for (int mi = 0; mi < 4; mi++)
#pragma unroll
                for (int ni = 0; ni < 4; ni++)
                    mma_f16(acc[mi][ni], af[mi], bf[ni]);
        }
    }
}

// Grouped QKV projection. z=0: Q (scaled), all tokens -> qkv seg 0.
// z=1: K on COMPACTED tokens -> qkv seg 1 (dense compacted rows).
// z=2: V on COMPACTED tokens -> vwT[b][c][j] (transposed, dense compacted).
__global__ __launch_bounds__(256, 2) void gemm_qkv(
    const __half* __restrict__ inh, const __half* __restrict__ wT,
    const float* __restrict__ bq, const float* __restrict__ bk,
    const float* __restrict__ bv, __half* __restrict__ qkv,
    __half* __restrict__ vwT,
    const int* __restrict__ idx, const int* __restrict__ ntc)
{
    __shared__ int stok[128];

    const int tid  = threadIdx.x;
    const int lane = tid & 31;
    const int warp = tid >> 5;
    const int g = lane >> 2, t = lane & 3;
    const int wm = (warp >> 2) * 64;
    const int wn = (warp & 3) * 32;
    const int bm = blockIdx.y * 128;
    const int bn = blockIdx.x * 128;
    const int z  = blockIdx.z;
    const int b  = bm >> 11;
    const int lm = bm & 2047;

    if (z > 0 && lm >= ntc[b] * 64) return;   // uniform per CTA

    if (tid < 128)
        stok[tid] = (z == 0) ? (bm + tid)
                             : (b * SEQ + idx[b * SEQ + lm + tid]);
    __syncthreads();

    const __half* A  = inh + (size_t)z * MROWS * DM;
    const __half* WT = wT  + (size_t)z * DM * DM;
    const float* bias = (z == 0) ? bq : (z == 1) ? bk : bv;
    const float sc = (z == 0) ? QSCALE : 1.0f;

    float acc[4][4][4];
#pragma unroll
    for (int mi = 0; mi < 4; mi++)
#pragma unroll
        for (int ni = 0; ni < 4; ni++)
#pragma unroll
            for (int e = 0; e < 4; e++) acc[mi][ni][e] = 0.0f;

    gemm_mainloop(acc, A, WT, stok, DM, bn, tid, wm, wn, g, t);

    if (z < 2) {
#pragma unroll
        for (int mi = 0; mi < 4; mi++) {
            int r0 = bm + wm + mi * 16 + g;
#pragma unroll
            for (int ni = 0; ni < 4; ni++) {
                int cb = bn + wn + ni * 8 + 2 * t;
                float b0 = bias[cb], b1 = bias[cb + 1];
                float x00 = (acc[mi][ni][0] + b0) * sc;
                float x01 = (acc[mi][ni][1] + b1) * sc;
                float x10 = (acc[mi][ni][2] + b0) * sc;
                float x11 = (acc[mi][ni][3] + b1) * sc;
                __half* c0p = qkv + (size_t)r0 * N3 + z * DM + cb;
                *(__half2*)c0p = __floats2half2_rn(x00, x01);
                *(__half2*)(c0p + (size_t)8 * N3) = __floats2half2_rn(x10, x11);
            }
        }
    } else {
        // V: restage transposed through smem, write vwT[b][c][j] (compacted j).
        __syncthreads();           // all warps done reading mainloop smem
        __half* ts = (__half*)sm_dyn;   // [128 c][136 tok-pitch] halves
#pragma unroll
        for (int mi = 0; mi < 4; mi++) {
            int tokl = wm + mi * 16 + g;
#pragma unroll
            for (int ni = 0; ni < 4; ni++) {
                int cl = wn + ni * 8 + 2 * t;
                float b0 = bias[bn + cl], b1 = bias[bn + cl + 1];
                ts[cl * 136 + tokl]           = __float2half_rn(acc[mi][ni][0] + b0);
                ts[(cl + 1) * 136 + tokl]     = __float2half_rn(acc[mi][ni][1] + b1);
                ts[cl * 136 + tokl + 8]       = __float2half_rn(acc[mi][ni][2] + b0);
                ts[(cl + 1) * 136 + tokl + 8] = __float2half_rn(acc[mi][ni][3] + b1);
            }
        }
        __syncthreads();
#pragma unroll
        for (int it = 0; it < 8; it++) {
            int idx2 = tid + it * 256;
            int cl = idx2 >> 4;
            int tk = (idx2 & 15) * 8;
            uint4 y = *(const uint4*)&ts[cl * 136 + tk];
            *(uint4*)&vwT[((size_t)b * DM + bn + cl) * SEQ + lm + tk] = y;
        }
    }
}

// Output projection: C(fp32) = ctx(fp16) @ Wo + bo.
__global__ __launch_bounds__(256, 2) void gemm_out(
    const __half* __restrict__ A, const __half* __restrict__ WT,
    const float* __restrict__ bias, float* __restrict__ C)
{
    __shared__ int stok[128];

    const int tid  = threadIdx.x;
    const int lane = tid & 31;
    const int warp = tid >> 5;
    const int g = lane >> 2, t = lane & 3;
    const int wm = (warp >> 2) * 64;
    const int wn = (warp & 3) * 32;
    const int bm = blockIdx.y * 128;
    const int bn = blockIdx.x * 128;

    if (tid < 128) stok[tid] = bm + tid;
    __syncthreads();

    float acc[4][4][4];
#pragma unroll
    for (int mi = 0; mi < 4; mi++)
#pragma unroll
        for (int ni = 0; ni < 4; ni++)
#pragma unroll
            for (int e = 0; e < 4; e++) acc[mi][ni][e] = 0.0f;

    gemm_mainloop(acc, A, WT, stok, DM, bn, tid, wm, wn, g, t);

#pragma unroll
    for (int mi = 0; mi < 4; mi++) {
        int r0 = bm + wm + mi * 16 + g;
#pragma unroll
        for (int ni = 0; ni < 4; ni++) {
            int cb = bn + wn + ni * 8 + 2 * t;
            float b0 = bias[cb], b1 = bias[cb + 1];
            *(float2*)&C[(size_t)r0 * DM + cb] =
                make_float2(acc[mi][ni][0] + b0, acc[mi][ni][1] + b1);
            *(float2*)&C[(size_t)(r0 + 8) * DM + cb] =
                make_float2(acc[mi][ni][2] + b0, acc[mi][ni][3] + b1);
        }
    }
}

// ---------------------------------------------------------------------------
// Flash-attention over COMPACTED keys (nt = ntc[b] tiles of 64).
// fp16 mma, exp2-domain softmax, ones-column l. 128 thr / 4 warps,
// QROWS=128 (32 rows/warp), 3 CTAs/SM.
// ---------------------------------------------------------------------------
#define QROWS 128
#define KTILE 64
#define NSTG 3
#define AT_W 36
#define STAGE_W (KTILE * AT_W * 2 + 64)
#define QS_W (QROWS * AT_W)
#define ATTN_SMEM ((NSTG * STAGE_W + QS_W) * (int)sizeof(float))  // 74496
#define ONES_H2 0x3C003C00u

__device__ __forceinline__ void attn_prefetch(
    unsigned* stage, const __half* kb, const __half* vtb, const int* mb,
    int kt, int tid)
{
    unsigned* Ks  = stage;
    unsigned* VTs = stage + KTILE * AT_W;
    unsigned* Mk  = VTs + KTILE * AT_W;
#pragma unroll
    for (int j = 0; j < 4; j++) {
        int idx = tid + j * 128;
        int row = idx >> 3;
        int c16 = idx & 7;
        cp_cg16(&Ks[row * AT_W + c16 * 4],
                kb + (size_t)(kt * KTILE + row) * N3 + c16 * 8);
        cp_cg16(&VTs[row * AT_W + c16 * 4],
                vtb + (size_t)row * SEQ + kt * KTILE + c16 * 8);
    }
    if (tid < 16) cp_cg16(&Mk[tid * 4], mb + kt * KTILE + tid * 4);
}

__global__ __launch_bounds__(128, 3) void attn_mma(
    const __half* __restrict__ qkv, const __half* __restrict__ vwT,
    const int* __restrict__ mkc, const int* __restrict__ ntc,
    __half* __restrict__ ctx)
{
    const int tid  = threadIdx.x;
    const int lane = tid & 31;
    const int warp = tid >> 5;
    const int g = lane >> 2, t = lane & 3;
    const int qrow0 = warp * 32;
    const int qt = blockIdx.x, h = blockIdx.y, b = blockIdx.z;
    const int nt = ntc[b];

    unsigned* Qs = (unsigned*)(sm_dyn + NSTG * STAGE_W);

    const __half* qb = qkv + ((size_t)b * SEQ + qt * QROWS) * N3 + h * HD;
#pragma unroll
    for (int j = 0; j < 8; j++) {
        int idx = tid + j * 128;
        int row = idx >> 3, c16 = idx & 7;
        cp_cg16(&Qs[row * AT_W + c16 * 4], qb + (size_t)row * N3 + c16 * 8);
    }

    const __half* kbase  = qkv + ((size_t)b * SEQ) * N3 + DM + h * HD;
    const __half* vtbase = vwT + ((size_t)b * DM + h * HD) * SEQ;
    const int*    mbase  = mkc + b * SEQ;

    attn_prefetch((unsigned*)sm_dyn, kbase, vtbase, mbase, 0, tid);
    asm volatile("cp.async.commit_group;" ::: "memory");
    attn_prefetch((unsigned*)sm_dyn + STAGE_W, kbase, vtbase, mbase, 1, tid);
    asm volatile("cp.async.commit_group;" ::: "memory");

    float m[2][2];
#pragma unroll
    for (int mi = 0; mi < 2; mi++) { m[mi][0] = -1e30f; m[mi][1] = -1e30f; }
    float o[2][8][4];
    float ol[2][4];
#pragma unroll
    for (int mi = 0; mi < 2; mi++) {
#pragma unroll
        for (int nf = 0; nf < 8; nf++)
#pragma unroll
            for (int e = 0; e < 4; e++) o[mi][nf][e] = 0.0f;
#pragma unroll
        for (int e = 0; e < 4; e++) ol[mi][e] = 0.0f;
    }

    const unsigned bones[2] = { ONES_H2, ONES_H2 };

    int st = 0;
    for (int kt = 0; kt < nt; kt++) {
        asm volatile("cp.async.wait_group 1;" ::: "memory");
        __syncthreads();
        if (kt + 2 < nt) {
            int j = st - 1; if (j < 0) j += NSTG;
            attn_prefetch((unsigned*)sm_dyn + j * STAGE_W,
                          kbase, vtbase, mbase, kt + 2, tid);
            asm volatile("cp.async.commit_group;" ::: "memory");
        } else {
            asm volatile("cp.async.commit_group;" ::: "memory");
        }
        const unsigned* Ks  = (const unsigned*)sm_dyn + st * STAGE_W;
        const unsigned* VTs = Ks + KTILE * AT_W;
        const int*      Mk  = (const int*)(VTs + KTILE * AT_W);
        if (++st == NSTG) st = 0;

        // ---- S = Q . K^T  (exp2-domain scores) ----
        float s[2][8][4];
#pragma unroll
        for (int mi = 0; mi < 2; mi++)
#pragma unroll
            for (int nf = 0; nf < 8; nf++)
#pragma unroll
                for (int e = 0; e < 4; e++) s[mi][nf][e] = 0.0f;

#pragma unroll
        for (int kf = 0; kf < 4; kf++) {
            unsigned a0[4], a1[4];
            a0[0] = Qs[(qrow0 + g)      * AT_W + kf * 8 + t];
            a0[1] = Qs[(qrow0 + g + 8)  * AT_W + kf * 8 + t];
            a0[2] = Qs[(qrow0 + g)      * AT_W + kf * 8 + t + 4];
            a0[3] = Qs[(qrow0 + g + 8)  * AT_W + kf * 8 + t + 4];
            a1[0] = Qs[(qrow0 + g + 16) * AT_W + kf * 8 + t];
            a1[1] = Qs[(qrow0 + g + 24) * AT_W + kf * 8 + t];
            a1[2] = Qs[(qrow0 + g + 16) * AT_W + kf * 8 + t + 4];
            a1[3] = Qs[(qrow0 + g + 24) * AT_W + kf * 8 + t + 4];
#pragma unroll
            for (int nf = 0; nf < 8; nf++) {
                unsigned bfr[2];
                bfr[0] = Ks[(nf * 8 + g) * AT_W + kf * 8 + t];
                bfr[1] = Ks[(nf * 8 + g) * AT_W + kf * 8 + t + 4];
                mma_f16(s[0][nf], a0, bfr);
                mma_f16(s[1][nf], a1, bfr);
            }
        }

        // ---- mask + online softmax (exp2, f16x2; l via ones column) ----
        unsigned p01[2][8], p23[2][8];
#pragma unroll
        for (int mi = 0; mi < 2; mi++) {
            float mx0 = -1e30f, mx1 = -1e30f;
#pragma unroll
            for (int nf = 0; nf < 8; nf++) {
                float pen0 = Mk[nf * 8 + 2 * t]     ? 0.0f : 1e12f;
                float pen1 = Mk[nf * 8 + 2 * t + 1] ? 0.0f : 1e12f;
                s[mi][nf][0] -= pen0; s[mi][nf][1] -= pen1;
                s[mi][nf][2] -= pen0; s[mi][nf][3] -= pen1;
                mx0 = fmaxf(mx0, fmaxf(s[mi][nf][0], s[mi][nf][1]));
                mx1 = fmaxf(mx1, fmaxf(s[mi][nf][2], s[mi][nf][3]));
            }
            mx0 = fmaxf(mx0, __shfl_xor_sync(0xffffffffu, mx0, 1));
            mx0 = fmaxf(mx0, __shfl_xor_sync(0xffffffffu, mx0, 2));
            mx1 = fmaxf(mx1, __shfl_xor_sync(0xffffffffu, mx1, 1));
            mx1 = fmaxf(mx1, __shfl_xor_sync(0xffffffffu, mx1, 2));
            float mn0 = fmaxf(m[mi][0], mx0), mn1 = fmaxf(m[mi][1], mx1);
            float al0 = ex2f(m[mi][0] - mn0), al1 = ex2f(m[mi][1] - mn1);
            m[mi][0] = mn0; m[mi][1] = mn1;
#pragma unroll
            for (int nf = 0; nf < 8; nf++) {
                p01[mi][nf] = h2ex2(s[mi][nf][0] - mn0, s[mi][nf][1] - mn0);
                p23[mi][nf] = h2ex2(s[mi][nf][2] - mn1, s[mi][nf][3] - mn1);
            }
#pragma unroll
            for (int nf = 0; nf < 8; nf++) {
                o[mi][nf][0] *= al0; o[mi][nf][1] *= al0;
                o[mi][nf][2] *= al1; o[mi][nf][3] *= al1;
            }
            ol[mi][0] *= al0; ol[mi][1] *= al0;
            ol[mi][2] *= al1; ol[mi][3] *= al1;
        }

        // ---- O' += P . [V | 1] ----
#pragma unroll
        for (int kf = 0; kf < 4; kf++) {
            unsigned af[2][4];
#pragma unroll
            for (int mi = 0; mi < 2; mi++) {
                af[mi][0] = p01[mi][2 * kf];
                af[mi][1] = p23[mi][2 * kf];
                af[mi][2] = p01[mi][2 * kf + 1];
                af[mi][3] = p23[mi][2 * kf + 1];
            }
#pragma unroll
            for (int nf = 0; nf < 8; nf++) {
                unsigned bfr[2];
                bfr[0] = VTs[(nf * 8 + g) * AT_W + kf * 8 + t];
                bfr[1] = VTs[(nf * 8 + g) * AT_W + kf * 8 + t + 4];
                mma_f16(o[0][nf], af[0], bfr);
                mma_f16(o[1][nf], af[1], bfr);
            }
            mma_f16(ol[0], af[0], bones);
            mma_f16(ol[1], af[1], bones);
        }
    }

    // ---- normalize; write ctx fp16 [token][c] ----
    __half* obase = ctx + ((size_t)b * SEQ + qt * QROWS + qrow0) * DM + h * HD;
#pragma unroll
    for (int mi = 0; mi < 2; mi++) {
        float inv0 = 1.0f / ol[mi][0], inv1 = 1.0f / ol[mi][2];
        __half* ob = obase + (size_t)(mi * 16) * DM;
#pragma unroll
        for (int nf = 0; nf < 8; nf++) {
            int col = nf * 8 + 2 * t;
            *(__half2*)&ob[(size_t)g * DM + col] =
                __floats2half2_rn(o[mi][nf][0] * inv0, o[mi][nf][1] * inv0);
            *(__half2*)&ob[(size_t)(g + 8) * DM + col] =
                __floats2half2_rn(o[mi][nf][2] * inv1, o[mi][nf][3] * inv1);
        }
    }
}

// ---------------------------------------------------------------------------
extern "C" void kernel_launch(void* const* d_in, const int* in_sizes, int n_in,
                              void* d_out, int out_size)
{
    const float* q    = (const float*)d_in[0];
    const float* k    = (const float*)d_in[1];
    const float* v    = (const float*)d_in[2];
    const int*   mask = (const int*)  d_in[3];
    const float* Wq   = (const float*)d_in[4];
    const float* bq   = (const float*)d_in[5];
    const float* Wk   = (const float*)d_in[6];
    const float* bk   = (const float*)d_in[7];
    const float* Wv   = (const float*)d_in[8];
    const float* bv   = (const float*)d_in[9];
    const float* Wo   = (const float*)d_in[10];
    const float* bo   = (const float*)d_in[11];
    float* out = (float*)d_out;

    void *pin, *pwT, *pqkv, *pvwT, *pctx, *pidx, *pmkc, *pntc;
    cudaGetSymbolAddress(&pin,  g_inh);
    cudaGetSymbolAddress(&pwT,  g_wT);
    cudaGetSymbolAddress(&pqkv, g_qkv);
    cudaGetSymbolAddress(&pvwT, g_vwT);
    cudaGetSymbolAddress(&pctx, g_ctx);
    cudaGetSymbolAddress(&pidx, g_idx);
    cudaGetSymbolAddress(&pmkc, g_mkc);
    cudaGetSymbolAddress(&pntc, g_ntc);

    __half* inh = (__half*)pin;
    __half* wT  = (__half*)pwT;
    __half* qkv = (__half*)pqkv;
    __half* vwT = (__half*)pvwT;
    __half* ctx = (__half*)pctx;
    int* idx = (int*)pidx;
    int* mkc = (int*)pmkc;
    int* ntc = (int*)pntc;

    cudaFuncSetAttribute(gemm_qkv,
                         cudaFuncAttributeMaxDynamicSharedMemorySize, GEMM_SMEM);
    cudaFuncSetAttribute(gemm_out,
                         cudaFuncAttributeMaxDynamicSharedMemorySize, GEMM_SMEM);
    cudaFuncSetAttribute(attn_mma,
                         cudaFuncAttributeMaxDynamicSharedMemorySize, ATTN_SMEM);

    // 1) prepass: converts, weight transposes, key compaction
    const int nBig = MROWS * DM / 4;
    to_f16_3<<<dim3(nBig / 256, 1, 3), 256>>>(
        (const float4*)q, (const float4*)k, (const float4*)v,
        (__half2*)inh, nBig);
    transp_w4<<<dim3(DM / 32, DM / 32, 4), dim3(32, 8)>>>(Wq, Wk, Wv, Wo, wT);
    compact_mask<<<NB, 1024>>>(mask, idx, mkc, ntc);

    // 2) grouped QKV projection; K/V gathered over compacted tokens;
    //    z==2 writes V transposed straight to vwT (compacted columns)
    gemm_qkv<<<dim3(DM / 128, MROWS / 128, 3), 256, GEMM_SMEM>>>(
        inh, wT, bq, bk, bv, qkv, vwT, idx, ntc);

    // 3) fused attention over compacted keys -> ctx (fp16), 3 CTAs/SM
    attn_mma<<<dim3(SEQ / QROWS, NH, NB), 128, ATTN_SMEM>>>(
        qkv, vwT, mkc, ntc, ctx);

    // 4) output projection (fp32 out)
    gemm_out<<<dim3(DM / 128, MROWS / 128), 256, GEMM_SMEM>>>(
        ctx, wT + 3 * (size_t)DM * DM, bo, out);
}